// round 2
// baseline (speedup 1.0000x reference)
#include <cuda_runtime.h>
#include <math.h>

// Problem constants
#define NNODES 50000
#define NEDGES 800000

// ---------------------------------------------------------------------------
// Scratch (static __device__ arrays — the sanctioned no-alloc workaround)
// ---------------------------------------------------------------------------
__device__ float g_P[(size_t)NNODES * 192];     // propagation output (max C = 192 never needed; 163 max, keep slack)
__device__ float g_bufA[(size_t)NNODES * 163];  // e1 / e2 / e / nn
__device__ float g_bufB[(size_t)NNODES * 96];   // n1 (long-lived)
__device__ float g_bufC[(size_t)NNODES * 163];  // mu_e / mu_n
__device__ float g_deg[NNODES];
__device__ float g_dinv[NNODES];
__device__ int   g_row[NEDGES];
__device__ int   g_col[NEDGES];
__device__ float g_coef[NEDGES];
__device__ unsigned g_flag32;   // nonzero => edge_index is int32

// ---------------------------------------------------------------------------
// Prep kernels
// ---------------------------------------------------------------------------
__global__ void k_zero_prep() {
    int i = blockIdx.x * blockDim.x + threadIdx.x;
    if (i < NNODES) g_deg[i] = 0.0f;
    if (i == 0) g_flag32 = 0u;
}

// Detect int64 vs int32 layout of edge_index: read first 2*NEDGES 32-bit words
// (safe under both layouts). If the buffer is int64 (values < 2^31), every odd
// word is a zero high-half. If int32, odd words are random node ids -> OR != 0.
__global__ void k_detect(const unsigned* __restrict__ w) {
    unsigned v = 0;
    for (int i = blockIdx.x * blockDim.x + threadIdx.x; i < NEDGES;
         i += gridDim.x * blockDim.x)
        v |= w[2 * i + 1];
    #pragma unroll
    for (int o = 16; o; o >>= 1) v |= __shfl_xor_sync(0xFFFFFFFFu, v, o);
    if ((threadIdx.x & 31) == 0 && v) atomicOr(&g_flag32, 1u);
}

__global__ void k_convert(const void* __restrict__ ei) {
    int e = blockIdx.x * blockDim.x + threadIdx.x;
    if (e >= NEDGES) return;
    if (g_flag32 == 0u) {  // int64 layout
        const long long* ll = (const long long*)ei;
        g_row[e] = (int)ll[e];
        g_col[e] = (int)ll[NEDGES + e];
    } else {               // int32 layout
        const int* q = (const int*)ei;
        g_row[e] = q[e];
        g_col[e] = q[NEDGES + e];
    }
}

__global__ void k_deg() {
    int e = blockIdx.x * blockDim.x + threadIdx.x;
    if (e < NEDGES) atomicAdd(&g_deg[g_col[e]], 1.0f);
}

__global__ void k_dinv() {
    int i = blockIdx.x * blockDim.x + threadIdx.x;
    if (i < NNODES) g_dinv[i] = rsqrtf(g_deg[i] + 1.0f);
}

__global__ void k_coef() {
    int e = blockIdx.x * blockDim.x + threadIdx.x;
    if (e < NEDGES) g_coef[e] = g_dinv[g_row[e]] * g_dinv[g_col[e]];
}

// ---------------------------------------------------------------------------
// Propagation: P = Â h  =  scatter(h[row]*coef -> col) + h * dinv^2
// ---------------------------------------------------------------------------
template <int C>
__global__ void k_prop_init(const float* __restrict__ in, float* __restrict__ out) {
    int i = blockIdx.x * blockDim.x + threadIdx.x;
    if (i >= NNODES * C) return;
    int n = i / C;
    float d = g_dinv[n];
    out[i] = in[i] * d * d;
}

template <int C>
__global__ void k_scatter(const float* __restrict__ in, float* __restrict__ out) {
    int i = blockIdx.x * blockDim.x + threadIdx.x;
    if (i >= NEDGES * C) return;
    int e = i / C;
    int c = i - e * C;
    atomicAdd(&out[g_col[e] * C + c], in[g_row[e] * C + c] * g_coef[e]);
}

// ---------------------------------------------------------------------------
// GEMM: out[N,M] = A[N,K] @ W[K,M] + bias, with fused epilogue.
// mode: 0 none, 1 relu, 2 sigmoid, 3 reparam out = mu + eps*exp(v)/10
// BM=128, BN=64, BK=16, 256 threads, 8x4 microtile.
// ---------------------------------------------------------------------------
#define BM 128
#define BN 64
#define BK 16

__global__ __launch_bounds__(256) void k_gemm(
    const float* __restrict__ A, const float* __restrict__ W,
    const float* __restrict__ bias, float* __restrict__ out,
    int K, int M, int mode,
    const float* __restrict__ mu, const float* __restrict__ eps)
{
    __shared__ float As[BM * BK];  // [m][kk]
    __shared__ float Bs[BK * BN];  // [kk][n]
    int tid = threadIdx.x;
    int r0 = blockIdx.y * BM;
    int c0 = blockIdx.x * BN;
    int tx = tid & 15;   // 16 -> N dir (x4)
    int ty = tid >> 4;   // 16 -> M dir (x8)

    float acc[8][4];
    #pragma unroll
    for (int i = 0; i < 8; i++)
        #pragma unroll
        for (int j = 0; j < 4; j++) acc[i][j] = 0.0f;

    for (int k0 = 0; k0 < K; k0 += BK) {
        // load A tile (128x16), [m][kk] layout, conflict-free stores
        #pragma unroll
        for (int i = 0; i < 8; i++) {
            int li = tid + i * 256;
            int m = li >> 4, kk = li & 15;
            int r = r0 + m, k = k0 + kk;
            As[li] = (r < NNODES && k < K) ? A[(size_t)r * K + k] : 0.0f;
        }
        // load B tile (16x64)
        #pragma unroll
        for (int i = 0; i < 4; i++) {
            int li = tid + i * 256;
            int kk = li >> 6, n = li & 63;
            int k = k0 + kk, c = c0 + n;
            Bs[li] = (k < K && c < M) ? W[(size_t)k * M + c] : 0.0f;
        }
        __syncthreads();
        #pragma unroll
        for (int kk = 0; kk < BK; kk++) {
            float4 b4 = ((const float4*)Bs)[kk * 16 + tx];  // conflict-free
            float bb0 = b4.x, bb1 = b4.y, bb2 = b4.z, bb3 = b4.w;
            #pragma unroll
            for (int i = 0; i < 8; i++) {
                float a = As[(ty * 8 + i) * BK + kk];       // broadcast
                acc[i][0] += a * bb0;
                acc[i][1] += a * bb1;
                acc[i][2] += a * bb2;
                acc[i][3] += a * bb3;
            }
        }
        __syncthreads();
    }

    #pragma unroll
    for (int i = 0; i < 8; i++) {
        int r = r0 + ty * 8 + i;
        if (r >= NNODES) continue;
        #pragma unroll
        for (int j = 0; j < 4; j++) {
            int c = c0 + tx * 4 + j;
            if (c >= M) continue;
            float v = acc[i][j] + bias[c];
            if (mode == 1) {
                v = fmaxf(v, 0.0f);
            } else if (mode == 2) {
                v = 1.0f / (1.0f + expf(-v));
            } else if (mode == 3) {
                size_t idx = (size_t)r * M + c;
                v = mu[idx] + eps[idx] * expf(v) / 10.0f;
            }
            out[(size_t)r * M + c] = v;
        }
    }
}

// ---------------------------------------------------------------------------
// Host side
// ---------------------------------------------------------------------------
static void launch_prop(const float* in, float* P, int C) {
    int tn = NNODES * C;
    int te = NEDGES * C;
    int bn = (tn + 255) / 256;
    int be = (te + 255) / 256;
    switch (C) {
        case 96:
            k_prop_init<96><<<bn, 256>>>(in, P);
            k_scatter<96><<<be, 256>>>(in, P);
            break;
        case 125:
            k_prop_init<125><<<bn, 256>>>(in, P);
            k_scatter<125><<<be, 256>>>(in, P);
            break;
        case 144:
            k_prop_init<144><<<bn, 256>>>(in, P);
            k_scatter<144><<<be, 256>>>(in, P);
            break;
        case 163:
            k_prop_init<163><<<bn, 256>>>(in, P);
            k_scatter<163><<<be, 256>>>(in, P);
            break;
    }
}

static void launch_gemm(const float* A, int K, const float* W, const float* b,
                        int M, int mode, const float* mu, const float* eps,
                        float* out) {
    dim3 grid((M + BN - 1) / BN, (NNODES + BM - 1) / BM);
    k_gemm<<<grid, 256>>>(A, W, b, out, K, M, mode, mu, eps);
}

extern "C" void kernel_launch(void* const* d_in, const int* in_sizes, int n_in,
                              void* d_out, int out_size) {
    const float* x     = (const float*)d_in[0];
    const void*  ei    = d_in[1];
    const float* eps_e = (const float*)d_in[2];
    const float* eps_n = (const float*)d_in[3];
    const float* w1e = (const float*)d_in[4];  const float* b1e = (const float*)d_in[5];
    const float* w2e = (const float*)d_in[6];  const float* b2e = (const float*)d_in[7];
    const float* wme = (const float*)d_in[8];  const float* bme = (const float*)d_in[9];
    const float* wle = (const float*)d_in[10]; const float* ble = (const float*)d_in[11];
    const float* w4e = (const float*)d_in[12]; const float* b4e = (const float*)d_in[13];
    const float* w1n = (const float*)d_in[14]; const float* b1n = (const float*)d_in[15];
    const float* wmn = (const float*)d_in[16]; const float* bmn = (const float*)d_in[17];
    const float* wln = (const float*)d_in[18]; const float* bln = (const float*)d_in[19];
    const float* w5n = (const float*)d_in[20]; const float* b5n = (const float*)d_in[21];

    float* out   = (float*)d_out;
    float* edges = out;                              // [N,192]
    float* nodes = out + (size_t)NNODES * 192;       // [N,96]

    float *P, *bufA, *bufB, *bufC;
    cudaGetSymbolAddress((void**)&P,    g_P);
    cudaGetSymbolAddress((void**)&bufA, g_bufA);
    cudaGetSymbolAddress((void**)&bufB, g_bufB);
    cudaGetSymbolAddress((void**)&bufC, g_bufC);

    // ---- prep: degrees, dinv, coefficients ----
    k_zero_prep<<<(NNODES + 255) / 256, 256>>>();
    k_detect<<<512, 256>>>((const unsigned*)ei);
    k_convert<<<(NEDGES + 255) / 256, 256>>>(ei);
    k_deg<<<(NEDGES + 255) / 256, 256>>>();
    k_dinv<<<(NNODES + 255) / 256, 256>>>();
    k_coef<<<(NEDGES + 255) / 256, 256>>>();

    // ---- shared first propagation: P = Â x ----
    launch_prop(x, P, 96);
    launch_gemm(P, 96, w1e, b1e, 125, 1, 0, 0, bufA);   // e1 = relu(conv)
    launch_gemm(P, 96, w1n, b1n, 96,  1, 0, 0, bufB);   // n1 = relu(conv)

    // ---- edge branch ----
    launch_prop(bufA, P, 125);
    launch_gemm(P, 125, w2e, b2e, 144, 1, 0, 0, bufA);  // e2
    launch_prop(bufA, P, 144);
    launch_gemm(P, 144, wme, bme, 163, 0, 0, 0, bufC);        // mu_e
    launch_gemm(P, 144, wle, ble, 163, 3, bufC, eps_e, bufA); // e = mu + eps*exp(ls)/10
    launch_prop(bufA, P, 163);
    launch_gemm(P, 163, w4e, b4e, 192, 2, 0, 0, edges); // sigmoid

    // ---- node branch ----
    launch_prop(bufB, P, 96);
    launch_gemm(P, 96, wmn, bmn, 96, 0, 0, 0, bufC);          // mu_n
    launch_gemm(P, 96, wln, bln, 96, 3, bufC, eps_n, bufA);   // nn
    launch_prop(bufA, P, 96);
    launch_gemm(P, 96, w5n, b5n, 96, 1, 0, 0, nodes);   // relu
}

// round 3
// speedup vs baseline: 1.3146x; 1.3146x over previous
#include <cuda_runtime.h>
#include <math.h>

// Problem constants
#define NNODES 50000
#define NEDGES 800000

// ---------------------------------------------------------------------------
// Scratch (static __device__ arrays)
// ---------------------------------------------------------------------------
__device__ float g_P[(size_t)NNODES * 192];
__device__ float g_bufA[(size_t)NNODES * 163];
__device__ float g_bufB[(size_t)NNODES * 96];
__device__ float g_bufC[(size_t)NNODES * 163];
__device__ float g_dinv[NNODES];
__device__ int   g_row[NEDGES];
__device__ int   g_col[NEDGES];
__device__ float g_coef[NEDGES];
__device__ int   g_ideg[NNODES];
__device__ int   g_off[NNODES + 1];
__device__ int   g_cursor[NNODES];
__device__ int2  g_ecsr[NEDGES];     // {src row, coef as float bits} sorted by dest
__device__ unsigned g_flag32;

// ---------------------------------------------------------------------------
// Prep kernels
// ---------------------------------------------------------------------------
__global__ void k_zero_prep() {
    int i = blockIdx.x * blockDim.x + threadIdx.x;
    if (i < NNODES) g_ideg[i] = 0;
    if (i == 0) g_flag32 = 0u;
}

// Detect int64 vs int32 layout of edge_index buffer.
__global__ void k_detect(const unsigned* __restrict__ w) {
    unsigned v = 0;
    for (int i = blockIdx.x * blockDim.x + threadIdx.x; i < NEDGES;
         i += gridDim.x * blockDim.x)
        v |= w[2 * i + 1];
    #pragma unroll
    for (int o = 16; o; o >>= 1) v |= __shfl_xor_sync(0xFFFFFFFFu, v, o);
    if ((threadIdx.x & 31) == 0 && v) atomicOr(&g_flag32, 1u);
}

__global__ void k_convert(const void* __restrict__ ei) {
    int e = blockIdx.x * blockDim.x + threadIdx.x;
    if (e >= NEDGES) return;
    int r, c;
    if (g_flag32 == 0u) {
        const long long* ll = (const long long*)ei;
        r = (int)ll[e];
        c = (int)ll[NEDGES + e];
    } else {
        const int* q = (const int*)ei;
        r = q[e];
        c = q[NEDGES + e];
    }
    g_row[e] = r;
    g_col[e] = c;
    atomicAdd(&g_ideg[c], 1);
}

__global__ void k_dinv() {
    int i = blockIdx.x * blockDim.x + threadIdx.x;
    if (i < NNODES) g_dinv[i] = rsqrtf((float)g_ideg[i] + 1.0f);
}

// Single-block exclusive prefix scan over g_ideg -> g_off, also inits cursor.
#define SCAN_T 1024
__global__ __launch_bounds__(SCAN_T) void k_scan() {
    __shared__ float dummy;  (void)dummy;
    __shared__ int sh[SCAN_T];
    __shared__ int carry;
    int tid = threadIdx.x;
    if (tid == 0) carry = 0;
    __syncthreads();
    for (int base = 0; base < NNODES; base += SCAN_T) {
        int i = base + tid;
        int v = (i < NNODES) ? g_ideg[i] : 0;
        sh[tid] = v;
        __syncthreads();
        // Hillis-Steele inclusive scan
        #pragma unroll
        for (int o = 1; o < SCAN_T; o <<= 1) {
            int t = (tid >= o) ? sh[tid - o] : 0;
            __syncthreads();
            sh[tid] += t;
            __syncthreads();
        }
        int incl = sh[tid];
        int excl = incl - v + carry;
        if (i < NNODES) {
            g_off[i] = excl;
            g_cursor[i] = excl;
        }
        __syncthreads();
        if (tid == SCAN_T - 1) carry += incl;
        __syncthreads();
    }
    if (tid == 0) g_off[NNODES] = NEDGES;
}

__global__ void k_coef_fill() {
    int e = blockIdx.x * blockDim.x + threadIdx.x;
    if (e >= NEDGES) return;
    int r = g_row[e], c = g_col[e];
    float cf = g_dinv[r] * g_dinv[c];
    int pos = atomicAdd(&g_cursor[c], 1);
    g_ecsr[pos] = make_int2(r, __float_as_int(cf));
}

// ---------------------------------------------------------------------------
// Gather propagation: out[n,:] = sum_{e: col=n} in[row_e,:]*coef_e + in[n,:]*dinv[n]^2
// One warp handles one (node, 32-channel chunk).
// ---------------------------------------------------------------------------
template <int C>
__global__ __launch_bounds__(256) void k_gather(const float* __restrict__ in,
                                                float* __restrict__ out) {
    const int WPN = (C + 31) / 32;  // warps per node
    int w = blockIdx.x * 8 + (threadIdx.x >> 5);
    int lane = threadIdx.x & 31;
    int node = w / WPN;
    int chunk = w - node * WPN;
    if (node >= NNODES) return;
    int c = chunk * 32 + lane;
    bool act = (c < C);
    size_t cc = c;

    float d = g_dinv[node];
    float acc = act ? in[(size_t)node * C + cc] * d * d : 0.0f;

    int s = g_off[node];
    int e = g_off[node + 1];
    int i = s;
    for (; i + 1 < e; i += 2) {
        int2 p0 = g_ecsr[i];
        int2 p1 = g_ecsr[i + 1];
        float v0 = act ? in[(size_t)p0.x * C + cc] : 0.0f;
        float v1 = act ? in[(size_t)p1.x * C + cc] : 0.0f;
        acc += v0 * __int_as_float(p0.y);
        acc += v1 * __int_as_float(p1.y);
    }
    if (i < e) {
        int2 p = g_ecsr[i];
        if (act) acc += in[(size_t)p.x * C + cc] * __int_as_float(p.y);
    }
    if (act) out[(size_t)node * C + cc] = acc;
}

// ---------------------------------------------------------------------------
// GEMM: out[N,M] = A[N,K] @ W[K,M] + bias, fused epilogue.
// mode: 0 none, 1 relu, 2 sigmoid, 3 reparam out = mu + eps*exp(v)/10
// ---------------------------------------------------------------------------
#define BM 128
#define BN 64
#define BK 16

__global__ __launch_bounds__(256) void k_gemm(
    const float* __restrict__ A, const float* __restrict__ W,
    const float* __restrict__ bias, float* __restrict__ out,
    int K, int M, int mode,
    const float* __restrict__ mu, const float* __restrict__ eps)
{
    __shared__ float As[BM * BK];
    __shared__ float Bs[BK * BN];
    int tid = threadIdx.x;
    int r0 = blockIdx.y * BM;
    int c0 = blockIdx.x * BN;
    int tx = tid & 15;
    int ty = tid >> 4;

    float acc[8][4];
    #pragma unroll
    for (int i = 0; i < 8; i++)
        #pragma unroll
        for (int j = 0; j < 4; j++) acc[i][j] = 0.0f;

    for (int k0 = 0; k0 < K; k0 += BK) {
        #pragma unroll
        for (int i = 0; i < 8; i++) {
            int li = tid + i * 256;
            int m = li >> 4, kk = li & 15;
            int r = r0 + m, k = k0 + kk;
            As[li] = (r < NNODES && k < K) ? A[(size_t)r * K + k] : 0.0f;
        }
        #pragma unroll
        for (int i = 0; i < 4; i++) {
            int li = tid + i * 256;
            int kk = li >> 6, n = li & 63;
            int k = k0 + kk, c = c0 + n;
            Bs[li] = (k < K && c < M) ? W[(size_t)k * M + c] : 0.0f;
        }
        __syncthreads();
        #pragma unroll
        for (int kk = 0; kk < BK; kk++) {
            float4 b4 = ((const float4*)Bs)[kk * 16 + tx];
            float bb0 = b4.x, bb1 = b4.y, bb2 = b4.z, bb3 = b4.w;
            #pragma unroll
            for (int i = 0; i < 8; i++) {
                float a = As[(ty * 8 + i) * BK + kk];
                acc[i][0] += a * bb0;
                acc[i][1] += a * bb1;
                acc[i][2] += a * bb2;
                acc[i][3] += a * bb3;
            }
        }
        __syncthreads();
    }

    #pragma unroll
    for (int i = 0; i < 8; i++) {
        int r = r0 + ty * 8 + i;
        if (r >= NNODES) continue;
        #pragma unroll
        for (int j = 0; j < 4; j++) {
            int c = c0 + tx * 4 + j;
            if (c >= M) continue;
            float v = acc[i][j] + bias[c];
            if (mode == 1) {
                v = fmaxf(v, 0.0f);
            } else if (mode == 2) {
                v = 1.0f / (1.0f + expf(-v));
            } else if (mode == 3) {
                size_t idx = (size_t)r * M + c;
                v = mu[idx] + eps[idx] * expf(v) / 10.0f;
            }
            out[(size_t)r * M + c] = v;
        }
    }
}

// ---------------------------------------------------------------------------
// Host side
// ---------------------------------------------------------------------------
static void launch_prop(const float* in, float* P, int C) {
    int wpn = (C + 31) / 32;
    long long warps = (long long)NNODES * wpn;
    int blocks = (int)((warps + 7) / 8);
    switch (C) {
        case 96:  k_gather<96><<<blocks, 256>>>(in, P); break;
        case 125: k_gather<125><<<blocks, 256>>>(in, P); break;
        case 144: k_gather<144><<<blocks, 256>>>(in, P); break;
        case 163: k_gather<163><<<blocks, 256>>>(in, P); break;
    }
}

static void launch_gemm(const float* A, int K, const float* W, const float* b,
                        int M, int mode, const float* mu, const float* eps,
                        float* out) {
    dim3 grid((M + BN - 1) / BN, (NNODES + BM - 1) / BM);
    k_gemm<<<grid, 256>>>(A, W, b, out, K, M, mode, mu, eps);
}

extern "C" void kernel_launch(void* const* d_in, const int* in_sizes, int n_in,
                              void* d_out, int out_size) {
    const float* x     = (const float*)d_in[0];
    const void*  ei    = d_in[1];
    const float* eps_e = (const float*)d_in[2];
    const float* eps_n = (const float*)d_in[3];
    const float* w1e = (const float*)d_in[4];  const float* b1e = (const float*)d_in[5];
    const float* w2e = (const float*)d_in[6];  const float* b2e = (const float*)d_in[7];
    const float* wme = (const float*)d_in[8];  const float* bme = (const float*)d_in[9];
    const float* wle = (const float*)d_in[10]; const float* ble = (const float*)d_in[11];
    const float* w4e = (const float*)d_in[12]; const float* b4e = (const float*)d_in[13];
    const float* w1n = (const float*)d_in[14]; const float* b1n = (const float*)d_in[15];
    const float* wmn = (const float*)d_in[16]; const float* bmn = (const float*)d_in[17];
    const float* wln = (const float*)d_in[18]; const float* bln = (const float*)d_in[19];
    const float* w5n = (const float*)d_in[20]; const float* b5n = (const float*)d_in[21];

    float* out   = (float*)d_out;
    float* edges = out;
    float* nodes = out + (size_t)NNODES * 192;

    float *P, *bufA, *bufB, *bufC;
    cudaGetSymbolAddress((void**)&P,    g_P);
    cudaGetSymbolAddress((void**)&bufA, g_bufA);
    cudaGetSymbolAddress((void**)&bufB, g_bufB);
    cudaGetSymbolAddress((void**)&bufC, g_bufC);

    // ---- prep: int degrees, dinv, CSR build ----
    k_zero_prep<<<(NNODES + 255) / 256, 256>>>();
    k_detect<<<512, 256>>>((const unsigned*)ei);
    k_convert<<<(NEDGES + 255) / 256, 256>>>(ei);
    k_dinv<<<(NNODES + 255) / 256, 256>>>();
    k_scan<<<1, SCAN_T>>>();
    k_coef_fill<<<(NEDGES + 255) / 256, 256>>>();

    // ---- shared first propagation: P = Â x ----
    launch_prop(x, P, 96);
    launch_gemm(P, 96, w1e, b1e, 125, 1, 0, 0, bufA);
    launch_gemm(P, 96, w1n, b1n, 96,  1, 0, 0, bufB);

    // ---- edge branch ----
    launch_prop(bufA, P, 125);
    launch_gemm(P, 125, w2e, b2e, 144, 1, 0, 0, bufA);
    launch_prop(bufA, P, 144);
    launch_gemm(P, 144, wme, bme, 163, 0, 0, 0, bufC);
    launch_gemm(P, 144, wle, ble, 163, 3, bufC, eps_e, bufA);
    launch_prop(bufA, P, 163);
    launch_gemm(P, 163, w4e, b4e, 192, 2, 0, 0, edges);

    // ---- node branch ----
    launch_prop(bufB, P, 96);
    launch_gemm(P, 96, wmn, bmn, 96, 0, 0, 0, bufC);
    launch_gemm(P, 96, wln, bln, 96, 3, bufC, eps_n, bufA);
    launch_prop(bufA, P, 96);
    launch_gemm(P, 96, w5n, b5n, 96, 1, 0, 0, nodes);
}

// round 4
// speedup vs baseline: 1.4987x; 1.1401x over previous
#include <cuda_runtime.h>
#include <math.h>

#define NNODES 50000
#define NEDGES 800000

// ---------------------------------------------------------------------------
// Scratch
// ---------------------------------------------------------------------------
__device__ float g_P[(size_t)NNODES * 192];
__device__ float g_bufA[(size_t)NNODES * 164];
__device__ float g_bufB[(size_t)NNODES * 96];
__device__ float g_bufC[(size_t)NNODES * 164];
__device__ float g_dinv[NNODES];
__device__ int   g_row[NEDGES];
__device__ int   g_col[NEDGES];
__device__ int   g_ideg[NNODES];
__device__ int   g_off[NNODES + 1];
__device__ int   g_cursor[NNODES];
__device__ int2  g_ecsr[NEDGES];     // {src row, coef bits} sorted by dest
__device__ unsigned g_flag32;

// ---------------------------------------------------------------------------
// f32x2 helpers
// ---------------------------------------------------------------------------
__device__ __forceinline__ unsigned long long pk2(float lo, float hi) {
    unsigned long long r;
    asm("mov.b64 %0,{%1,%2};" : "=l"(r) : "f"(lo), "f"(hi));
    return r;
}
__device__ __forceinline__ void upk2(unsigned long long v, float& lo, float& hi) {
    asm("mov.b64 {%0,%1},%2;" : "=f"(lo), "=f"(hi) : "l"(v));
}
__device__ __forceinline__ void fma2(unsigned long long& d, unsigned long long a,
                                     unsigned long long b) {
    asm("fma.rn.f32x2 %0,%1,%2,%0;" : "+l"(d) : "l"(a), "l"(b));
}

// ---------------------------------------------------------------------------
// Prep kernels
// ---------------------------------------------------------------------------
__global__ void k_zero_prep() {
    int i = blockIdx.x * blockDim.x + threadIdx.x;
    if (i < NNODES) g_ideg[i] = 0;
    if (i == 0) g_flag32 = 0u;
}

__global__ void k_detect(const unsigned* __restrict__ w) {
    unsigned v = 0;
    for (int i = blockIdx.x * blockDim.x + threadIdx.x; i < NEDGES;
         i += gridDim.x * blockDim.x)
        v |= w[2 * i + 1];
    #pragma unroll
    for (int o = 16; o; o >>= 1) v |= __shfl_xor_sync(0xFFFFFFFFu, v, o);
    if ((threadIdx.x & 31) == 0 && v) atomicOr(&g_flag32, 1u);
}

__global__ void k_convert(const void* __restrict__ ei) {
    int e = blockIdx.x * blockDim.x + threadIdx.x;
    if (e >= NEDGES) return;
    int r, c;
    if (g_flag32 == 0u) {
        const long long* ll = (const long long*)ei;
        r = (int)ll[e];
        c = (int)ll[NEDGES + e];
    } else {
        const int* q = (const int*)ei;
        r = q[e];
        c = q[NEDGES + e];
    }
    g_row[e] = r;
    g_col[e] = c;
    atomicAdd(&g_ideg[c], 1);
}

__global__ void k_dinv() {
    int i = blockIdx.x * blockDim.x + threadIdx.x;
    if (i < NNODES) g_dinv[i] = rsqrtf((float)g_ideg[i] + 1.0f);
}

#define SCAN_T 1024
__global__ __launch_bounds__(SCAN_T) void k_scan() {
    __shared__ int sh[SCAN_T];
    __shared__ int carry;
    int tid = threadIdx.x;
    if (tid == 0) carry = 0;
    __syncthreads();
    for (int base = 0; base < NNODES; base += SCAN_T) {
        int i = base + tid;
        int v = (i < NNODES) ? g_ideg[i] : 0;
        sh[tid] = v;
        __syncthreads();
        #pragma unroll
        for (int o = 1; o < SCAN_T; o <<= 1) {
            int t = (tid >= o) ? sh[tid - o] : 0;
            __syncthreads();
            sh[tid] += t;
            __syncthreads();
        }
        int incl = sh[tid];
        int excl = incl - v + carry;
        if (i < NNODES) {
            g_off[i] = excl;
            g_cursor[i] = excl;
        }
        __syncthreads();
        if (tid == SCAN_T - 1) carry += incl;
        __syncthreads();
    }
    if (tid == 0) g_off[NNODES] = NEDGES;
}

__global__ void k_coef_fill() {
    int e = blockIdx.x * blockDim.x + threadIdx.x;
    if (e >= NEDGES) return;
    int r = g_row[e], c = g_col[e];
    float cf = g_dinv[r] * g_dinv[c];
    int pos = atomicAdd(&g_cursor[c], 1);
    g_ecsr[pos] = make_int2(r, __float_as_int(cf));
}

// ---------------------------------------------------------------------------
// Gather propagation (float4, one warp per node, whole row)
// Strides are PAD(C) = ((C+3)/4)*4 floats, both input and output.
// ---------------------------------------------------------------------------
template <int C>
__global__ __launch_bounds__(256) void k_gather(const float4* __restrict__ in4,
                                                float4* __restrict__ out4) {
    constexpr int NV4 = (C + 3) / 4;          // float4 per row
    constexpr int NIT = (NV4 + 31) / 32;      // 1 or 2
    int node = blockIdx.x * 8 + (threadIdx.x >> 5);
    if (node >= NNODES) return;
    int lane = threadIdx.x & 31;

    float d = g_dinv[node];
    float dd = d * d;

    float4 acc[NIT];
    #pragma unroll
    for (int v = 0; v < NIT; v++) {
        int id = lane + 32 * v;
        if (id < NV4) {
            float4 t = in4[(size_t)node * NV4 + id];
            acc[v] = make_float4(t.x * dd, t.y * dd, t.z * dd, t.w * dd);
        } else {
            acc[v] = make_float4(0.f, 0.f, 0.f, 0.f);
        }
    }

    int s = g_off[node];
    int e = g_off[node + 1];
    int i = s;
    for (; i + 1 < e; i += 2) {
        int2 p0 = g_ecsr[i];
        int2 p1 = g_ecsr[i + 1];
        float c0 = __int_as_float(p0.y);
        float c1 = __int_as_float(p1.y);
        #pragma unroll
        for (int v = 0; v < NIT; v++) {
            int id = lane + 32 * v;
            if (id < NV4) {
                float4 a = in4[(size_t)p0.x * NV4 + id];
                float4 b = in4[(size_t)p1.x * NV4 + id];
                acc[v].x += a.x * c0; acc[v].y += a.y * c0;
                acc[v].z += a.z * c0; acc[v].w += a.w * c0;
                acc[v].x += b.x * c1; acc[v].y += b.y * c1;
                acc[v].z += b.z * c1; acc[v].w += b.w * c1;
            }
        }
    }
    if (i < e) {
        int2 p = g_ecsr[i];
        float c0 = __int_as_float(p.y);
        #pragma unroll
        for (int v = 0; v < NIT; v++) {
            int id = lane + 32 * v;
            if (id < NV4) {
                float4 a = in4[(size_t)p.x * NV4 + id];
                acc[v].x += a.x * c0; acc[v].y += a.y * c0;
                acc[v].z += a.z * c0; acc[v].w += a.w * c0;
            }
        }
    }
    #pragma unroll
    for (int v = 0; v < NIT; v++) {
        int id = lane + 32 * v;
        if (id < NV4) out4[(size_t)node * NV4 + id] = acc[v];
    }
}

// ---------------------------------------------------------------------------
// GEMM with f32x2 FMAs: out[N,M] = A[N,K] @ W[K,M] + bias (+epilogue)
// A stride lda, out stride ldc (floats). mode: 0 none, 1 relu, 2 sigmoid,
// 3 reparam: out = mu[r*ldc+c] + eps[r*lde+c]*exp(v)/10
// BM=128, BN=64, BK=16, 128 threads, 8x8 microtile.
// ---------------------------------------------------------------------------
#define BM 128
#define BN 64
#define BK 16
#define AS_LD (BM + 4)

__global__ __launch_bounds__(128) void k_gemm(
    const float* __restrict__ A, int lda,
    const float* __restrict__ W,
    const float* __restrict__ bias, float* __restrict__ out, int ldc,
    int K, int M, int mode,
    const float* __restrict__ mu, const float* __restrict__ eps, int lde)
{
    __shared__ float As[BK][AS_LD];   // [kk][m]
    __shared__ float Bs[BK][BN];      // [kk][n]
    int tid = threadIdx.x;
    int r0 = blockIdx.y * BM;
    int c0 = blockIdx.x * BN;
    int tx = tid & 7;    // 8 -> N dir (x8 cols)
    int ty = tid >> 3;   // 16 -> M dir (x8 rows)

    unsigned long long acc[8][4];
    #pragma unroll
    for (int i = 0; i < 8; i++)
        #pragma unroll
        for (int j = 0; j < 4; j++) acc[i][j] = 0ULL;

    for (int k0 = 0; k0 < K; k0 += BK) {
        // A tile: 128x16, coalesced over k
        #pragma unroll
        for (int t = 0; t < 16; t++) {
            int li = tid + t * 128;
            int m = li >> 4, kk = li & 15;
            int r = r0 + m, k = k0 + kk;
            As[kk][m] = (r < NNODES && k < K) ? A[(size_t)r * lda + k] : 0.0f;
        }
        // B tile: 16x64
        #pragma unroll
        for (int t = 0; t < 8; t++) {
            int li = tid + t * 128;
            int kk = li >> 6, n = li & 63;
            int k = k0 + kk, c = c0 + n;
            Bs[kk][n] = (k < K && c < M) ? W[(size_t)k * M + c] : 0.0f;
        }
        __syncthreads();
        #pragma unroll
        for (int kk = 0; kk < BK; kk++) {
            float4 b0 = *(const float4*)&Bs[kk][tx * 8];
            float4 b1 = *(const float4*)&Bs[kk][tx * 8 + 4];
            unsigned long long bp0 = pk2(b0.x, b0.y);
            unsigned long long bp1 = pk2(b0.z, b0.w);
            unsigned long long bp2 = pk2(b1.x, b1.y);
            unsigned long long bp3 = pk2(b1.z, b1.w);
            #pragma unroll
            for (int i = 0; i < 8; i++) {
                float a = As[kk][ty * 8 + i];
                unsigned long long ap = pk2(a, a);
                fma2(acc[i][0], ap, bp0);
                fma2(acc[i][1], ap, bp1);
                fma2(acc[i][2], ap, bp2);
                fma2(acc[i][3], ap, bp3);
            }
        }
        __syncthreads();
    }

    #pragma unroll
    for (int i = 0; i < 8; i++) {
        int r = r0 + ty * 8 + i;
        if (r >= NNODES) continue;
        #pragma unroll
        for (int j = 0; j < 4; j++) {
            float lo, hi;
            upk2(acc[i][j], lo, hi);
            #pragma unroll
            for (int h = 0; h < 2; h++) {
                int c = c0 + tx * 8 + j * 2 + h;
                if (c >= M) continue;
                float v = (h ? hi : lo) + bias[c];
                if (mode == 1) {
                    v = fmaxf(v, 0.0f);
                } else if (mode == 2) {
                    v = 1.0f / (1.0f + expf(-v));
                } else if (mode == 3) {
                    v = mu[(size_t)r * ldc + c] +
                        eps[(size_t)r * lde + c] * expf(v) / 10.0f;
                }
                out[(size_t)r * ldc + c] = v;
            }
        }
    }
}

// ---------------------------------------------------------------------------
// Host side
// ---------------------------------------------------------------------------
static inline int padc(int C) { return ((C + 3) / 4) * 4; }

static void launch_prop(const float* in, float* P, int C) {
    int blocks = (NNODES + 7) / 8;
    switch (C) {
        case 96:  k_gather<96><<<blocks, 256>>>((const float4*)in, (float4*)P); break;
        case 125: k_gather<125><<<blocks, 256>>>((const float4*)in, (float4*)P); break;
        case 144: k_gather<144><<<blocks, 256>>>((const float4*)in, (float4*)P); break;
        case 163: k_gather<163><<<blocks, 256>>>((const float4*)in, (float4*)P); break;
    }
}

static void launch_gemm(const float* A, int K, const float* W, const float* b,
                        int M, int ldc, int mode, const float* mu,
                        const float* eps, int lde, float* out) {
    dim3 grid((M + BN - 1) / BN, (NNODES + BM - 1) / BM);
    k_gemm<<<grid, 128>>>(A, padc(K), W, b, out, ldc, K, M, mode, mu, eps, lde);
}

extern "C" void kernel_launch(void* const* d_in, const int* in_sizes, int n_in,
                              void* d_out, int out_size) {
    const float* x     = (const float*)d_in[0];
    const void*  ei    = d_in[1];
    const float* eps_e = (const float*)d_in[2];
    const float* eps_n = (const float*)d_in[3];
    const float* w1e = (const float*)d_in[4];  const float* b1e = (const float*)d_in[5];
    const float* w2e = (const float*)d_in[6];  const float* b2e = (const float*)d_in[7];
    const float* wme = (const float*)d_in[8];  const float* bme = (const float*)d_in[9];
    const float* wle = (const float*)d_in[10]; const float* ble = (const float*)d_in[11];
    const float* w4e = (const float*)d_in[12]; const float* b4e = (const float*)d_in[13];
    const float* w1n = (const float*)d_in[14]; const float* b1n = (const float*)d_in[15];
    const float* wmn = (const float*)d_in[16]; const float* bmn = (const float*)d_in[17];
    const float* wln = (const float*)d_in[18]; const float* bln = (const float*)d_in[19];
    const float* w5n = (const float*)d_in[20]; const float* b5n = (const float*)d_in[21];

    float* out   = (float*)d_out;
    float* edges = out;                         // [N,192] stride 192
    float* nodes = out + (size_t)NNODES * 192;  // [N,96]  stride 96

    float *P, *bufA, *bufB, *bufC;
    cudaGetSymbolAddress((void**)&P,    g_P);
    cudaGetSymbolAddress((void**)&bufA, g_bufA);
    cudaGetSymbolAddress((void**)&bufB, g_bufB);
    cudaGetSymbolAddress((void**)&bufC, g_bufC);

    // ---- prep ----
    k_zero_prep<<<(NNODES + 255) / 256, 256>>>();
    k_detect<<<512, 256>>>((const unsigned*)ei);
    k_convert<<<(NEDGES + 255) / 256, 256>>>(ei);
    k_dinv<<<(NNODES + 255) / 256, 256>>>();
    k_scan<<<1, SCAN_T>>>();
    k_coef_fill<<<(NEDGES + 255) / 256, 256>>>();

    // ---- shared first propagation: P = Â x ----
    launch_prop(x, P, 96);                                              // stride 96
    launch_gemm(P, 96, w1e, b1e, 125, 128, 1, 0, 0, 0, bufA);  // e1 (pad 128)
    launch_gemm(P, 96, w1n, b1n, 96,  96,  1, 0, 0, 0, bufB);  // n1

    // ---- edge branch ----
    launch_prop(bufA, P, 125);                                          // stride 128
    launch_gemm(P, 125, w2e, b2e, 144, 144, 1, 0, 0, 0, bufA);          // e2
    launch_prop(bufA, P, 144);
    launch_gemm(P, 144, wme, bme, 163, 164, 0, 0, 0, 0, bufC);          // mu_e
    launch_gemm(P, 144, wle, ble, 163, 164, 3, bufC, eps_e, 163, bufA); // e
    launch_prop(bufA, P, 163);                                          // stride 164
    launch_gemm(P, 163, w4e, b4e, 192, 192, 2, 0, 0, 0, edges);         // sigmoid

    // ---- node branch ----
    launch_prop(bufB, P, 96);
    launch_gemm(P, 96, wmn, bmn, 96, 96, 0, 0, 0, 0, bufC);             // mu_n
    launch_gemm(P, 96, wln, bln, 96, 96, 3, bufC, eps_n, 96, bufA);     // nn
    launch_prop(bufA, P, 96);
    launch_gemm(P, 96, w5n, b5n, 96, 96, 1, 0, 0, 0, nodes);            // relu
}

// round 5
// speedup vs baseline: 2.1366x; 1.4256x over previous
#include <cuda_runtime.h>
#include <math.h>

#define NNODES 50000
#define NEDGES 800000
#define NBLK 13          // ceil(50000/4096) scan blocks

// ---------------------------------------------------------------------------
// Scratch
// ---------------------------------------------------------------------------
__device__ float g_P[(size_t)NNODES * 192];
__device__ float g_bufA[(size_t)NNODES * 192];
__device__ float g_bufB[(size_t)NNODES * 96];
__device__ float g_dinv[NNODES];
__device__ int   g_row[NEDGES];
__device__ int   g_col[NEDGES];
__device__ int   g_ideg[NNODES];
__device__ int   g_off[NNODES + 1];
__device__ int   g_cursor[NNODES];
__device__ int2  g_ecsr[NEDGES];
__device__ int   g_bsum[32];
__device__ int   g_bpre[32];
__device__ unsigned g_flag32;

// ---------------------------------------------------------------------------
// f32x2 helpers
// ---------------------------------------------------------------------------
__device__ __forceinline__ unsigned long long pk2(float lo, float hi) {
    unsigned long long r;
    asm("mov.b64 %0,{%1,%2};" : "=l"(r) : "f"(lo), "f"(hi));
    return r;
}
__device__ __forceinline__ void upk2(unsigned long long v, float& lo, float& hi) {
    asm("mov.b64 {%0,%1},%2;" : "=f"(lo), "=f"(hi) : "l"(v));
}
__device__ __forceinline__ void fma2(unsigned long long& d, unsigned long long a,
                                     unsigned long long b) {
    asm("fma.rn.f32x2 %0,%1,%2,%0;" : "+l"(d) : "l"(a), "l"(b));
}

// ---------------------------------------------------------------------------
// Prep kernels
// ---------------------------------------------------------------------------
__global__ void k_prep1() {
    int i = blockIdx.x * blockDim.x + threadIdx.x;
    if (i < NNODES) g_ideg[i] = 0;
    if (i == 0) g_flag32 = 0u;
}

__global__ void k_detect(const unsigned* __restrict__ w) {
    unsigned v = 0;
    for (int i = blockIdx.x * blockDim.x + threadIdx.x; i < NEDGES;
         i += gridDim.x * blockDim.x)
        v |= w[2 * i + 1];
    #pragma unroll
    for (int o = 16; o; o >>= 1) v |= __shfl_xor_sync(0xFFFFFFFFu, v, o);
    if ((threadIdx.x & 31) == 0 && v) atomicOr(&g_flag32, 1u);
}

__global__ void k_convert(const void* __restrict__ ei) {
    int e = blockIdx.x * blockDim.x + threadIdx.x;
    if (e >= NEDGES) return;
    int r, c;
    if (g_flag32 == 0u) {
        const long long* ll = (const long long*)ei;
        r = (int)ll[e];
        c = (int)ll[NEDGES + e];
    } else {
        const int* q = (const int*)ei;
        r = q[e];
        c = q[NEDGES + e];
    }
    g_row[e] = r;
    g_col[e] = c;
    atomicAdd(&g_ideg[c], 1);
}

__global__ void k_dinv() {
    int i = blockIdx.x * blockDim.x + threadIdx.x;
    if (i < NNODES) g_dinv[i] = rsqrtf((float)g_ideg[i] + 1.0f);
}

// Scan stage A: per-block (4096 elems) sums
__global__ __launch_bounds__(1024) void k_scanA() {
    __shared__ int sh[32];
    int b = blockIdx.x, t = threadIdx.x;
    int base = b * 4096 + t * 4;
    int s = 0;
    #pragma unroll
    for (int j = 0; j < 4; j++) {
        int i = base + j;
        if (i < NNODES) s += g_ideg[i];
    }
    #pragma unroll
    for (int o = 16; o; o >>= 1) s += __shfl_xor_sync(0xFFFFFFFFu, s, o);
    if ((t & 31) == 0) sh[t >> 5] = s;
    __syncthreads();
    if (t < 32) {
        int x = sh[t];
        #pragma unroll
        for (int o = 16; o; o >>= 1) x += __shfl_xor_sync(0xFFFFFFFFu, x, o);
        if (t == 0) g_bsum[b] = x;
    }
}

// Scan stage B: exclusive scan of NBLK block sums (one warp)
__global__ void k_scanB() {
    int t = threadIdx.x;
    int v = (t < NBLK) ? g_bsum[t] : 0;
    int own = v;
    #pragma unroll
    for (int o = 1; o < 32; o <<= 1) {
        int u = __shfl_up_sync(0xFFFFFFFFu, v, o);
        if (t >= o) v += u;
    }
    if (t < NBLK) g_bpre[t] = v - own;
}

// Scan stage C: full exclusive scan, writes off + cursor
__global__ __launch_bounds__(1024) void k_scanC() {
    __shared__ int sh[1024];
    int b = blockIdx.x, t = threadIdx.x;
    int base = b * 4096 + t * 4;
    int v[4];
    int s = 0;
    #pragma unroll
    for (int j = 0; j < 4; j++) {
        int i = base + j;
        v[j] = (i < NNODES) ? g_ideg[i] : 0;
        s += v[j];
    }
    sh[t] = s;
    __syncthreads();
    #pragma unroll
    for (int o = 1; o < 1024; o <<= 1) {
        int tmp = (t >= o) ? sh[t - o] : 0;
        __syncthreads();
        sh[t] += tmp;
        __syncthreads();
    }
    int excl = sh[t] - s + g_bpre[b];
    #pragma unroll
    for (int j = 0; j < 4; j++) {
        int i = base + j;
        if (i < NNODES) { g_off[i] = excl; g_cursor[i] = excl; }
        excl += v[j];
    }
    if (b == 0 && t == 0) g_off[NNODES] = NEDGES;
}

__global__ void k_fill() {
    int e = blockIdx.x * blockDim.x + threadIdx.x;
    if (e >= NEDGES) return;
    int r = g_row[e], c = g_col[e];
    float cf = g_dinv[r] * g_dinv[c];
    int pos = atomicAdd(&g_cursor[c], 1);
    g_ecsr[pos] = make_int2(r, __float_as_int(cf));
}

// ---------------------------------------------------------------------------
// Gather: out[n] = sum_{e:col=n} in[row]*coef + in[n]*dinv^2, row stride S
// One warp per node. S multiple of 32 floats (128B-aligned rows).
// ---------------------------------------------------------------------------
template <int S>
__global__ __launch_bounds__(256) void k_gather(const float4* __restrict__ in4,
                                                float4* __restrict__ out4) {
    constexpr int NV4 = S / 4;
    constexpr int NIT = (NV4 + 31) / 32;
    int node = blockIdx.x * 8 + (threadIdx.x >> 5);
    if (node >= NNODES) return;
    int lane = threadIdx.x & 31;

    float d = g_dinv[node];
    float dd = d * d;

    float4 acc[NIT];
    #pragma unroll
    for (int v = 0; v < NIT; v++) {
        int id = lane + 32 * v;
        if (id < NV4) {
            float4 t = in4[(size_t)node * NV4 + id];
            acc[v] = make_float4(t.x * dd, t.y * dd, t.z * dd, t.w * dd);
        } else acc[v] = make_float4(0.f, 0.f, 0.f, 0.f);
    }

    int s = g_off[node];
    int e = g_off[node + 1];
    int i = s;
    for (; i + 3 < e; i += 4) {
        int2 p0 = g_ecsr[i];
        int2 p1 = g_ecsr[i + 1];
        int2 p2 = g_ecsr[i + 2];
        int2 p3 = g_ecsr[i + 3];
        float c0 = __int_as_float(p0.y), c1 = __int_as_float(p1.y);
        float c2 = __int_as_float(p2.y), c3 = __int_as_float(p3.y);
        #pragma unroll
        for (int v = 0; v < NIT; v++) {
            int id = lane + 32 * v;
            if (id < NV4) {
                float4 a0 = in4[(size_t)p0.x * NV4 + id];
                float4 a1 = in4[(size_t)p1.x * NV4 + id];
                float4 a2 = in4[(size_t)p2.x * NV4 + id];
                float4 a3 = in4[(size_t)p3.x * NV4 + id];
                acc[v].x += a0.x * c0; acc[v].y += a0.y * c0;
                acc[v].z += a0.z * c0; acc[v].w += a0.w * c0;
                acc[v].x += a1.x * c1; acc[v].y += a1.y * c1;
                acc[v].z += a1.z * c1; acc[v].w += a1.w * c1;
                acc[v].x += a2.x * c2; acc[v].y += a2.y * c2;
                acc[v].z += a2.z * c2; acc[v].w += a2.w * c2;
                acc[v].x += a3.x * c3; acc[v].y += a3.y * c3;
                acc[v].z += a3.z * c3; acc[v].w += a3.w * c3;
            }
        }
    }
    for (; i < e; i++) {
        int2 p = g_ecsr[i];
        float c0 = __int_as_float(p.y);
        #pragma unroll
        for (int v = 0; v < NIT; v++) {
            int id = lane + 32 * v;
            if (id < NV4) {
                float4 a = in4[(size_t)p.x * NV4 + id];
                acc[v].x += a.x * c0; acc[v].y += a.y * c0;
                acc[v].z += a.z * c0; acc[v].w += a.w * c0;
            }
        }
    }
    #pragma unroll
    for (int v = 0; v < NIT; v++) {
        int id = lane + 32 * v;
        if (id < NV4) out4[(size_t)node * NV4 + id] = acc[v];
    }
}

// ---------------------------------------------------------------------------
// Single GEMM: out = A@W + bias (+relu/sigmoid). BM=128,BN=64,BK=16,128thr.
// ---------------------------------------------------------------------------
#define BM 128
#define BN 64
#define BK 16
#define AS_LD (BM + 4)

__global__ __launch_bounds__(128) void k_gemm(
    const float* __restrict__ A, int lda,
    const float* __restrict__ W,
    const float* __restrict__ bias, float* __restrict__ out, int ldc,
    int K, int M, int mode)
{
    __shared__ float As[BK][AS_LD];
    __shared__ float Bs[BK][BN];
    int tid = threadIdx.x;
    int r0 = blockIdx.y * BM;
    int c0 = blockIdx.x * BN;
    int tx = tid & 7;
    int ty = tid >> 3;

    unsigned long long acc[8][4];
    #pragma unroll
    for (int i = 0; i < 8; i++)
        #pragma unroll
        for (int j = 0; j < 4; j++) acc[i][j] = 0ULL;

    for (int k0 = 0; k0 < K; k0 += BK) {
        #pragma unroll
        for (int t = 0; t < 16; t++) {
            int li = tid + t * 128;
            int m = li >> 4, kk = li & 15;
            int r = r0 + m, k = k0 + kk;
            As[kk][m] = (r < NNODES && k < K) ? A[(size_t)r * lda + k] : 0.0f;
        }
        #pragma unroll
        for (int t = 0; t < 8; t++) {
            int li = tid + t * 128;
            int kk = li >> 6, n = li & 63;
            int k = k0 + kk, c = c0 + n;
            Bs[kk][n] = (k < K && c < M) ? W[(size_t)k * M + c] : 0.0f;
        }
        __syncthreads();
        #pragma unroll
        for (int kk = 0; kk < BK; kk++) {
            float4 b0 = *(const float4*)&Bs[kk][tx * 8];
            float4 b1 = *(const float4*)&Bs[kk][tx * 8 + 4];
            unsigned long long bp0 = pk2(b0.x, b0.y);
            unsigned long long bp1 = pk2(b0.z, b0.w);
            unsigned long long bp2 = pk2(b1.x, b1.y);
            unsigned long long bp3 = pk2(b1.z, b1.w);
            #pragma unroll
            for (int i = 0; i < 8; i++) {
                float a = As[kk][ty * 8 + i];
                unsigned long long ap = pk2(a, a);
                fma2(acc[i][0], ap, bp0);
                fma2(acc[i][1], ap, bp1);
                fma2(acc[i][2], ap, bp2);
                fma2(acc[i][3], ap, bp3);
            }
        }
        __syncthreads();
    }

    #pragma unroll
    for (int i = 0; i < 8; i++) {
        int r = r0 + ty * 8 + i;
        if (r >= NNODES) continue;
        #pragma unroll
        for (int j = 0; j < 4; j++) {
            float lo, hi;
            upk2(acc[i][j], lo, hi);
            #pragma unroll
            for (int h = 0; h < 2; h++) {
                int c = c0 + tx * 8 + j * 2 + h;
                if (c >= M) continue;
                float v = (h ? hi : lo) + bias[c];
                if (mode == 1) v = fmaxf(v, 0.0f);
                else if (mode == 2) v = 1.0f / (1.0f + expf(-v));
                out[(size_t)r * ldc + c] = v;
            }
        }
    }
}

// ---------------------------------------------------------------------------
// Dual GEMM: mu = A@W1+b1, ls = A@W2+b2, out = mu + eps*exp(ls)/10
// BM=64, BN=64, BK=16, 128 threads, 4x8 per-thread per matrix.
// ---------------------------------------------------------------------------
#define DBM 64

__global__ __launch_bounds__(128) void k_gemm_dual(
    const float* __restrict__ A, int lda,
    const float* __restrict__ W1, const float* __restrict__ W2,
    const float* __restrict__ b1, const float* __restrict__ b2,
    const float* __restrict__ eps, int lde,
    float* __restrict__ out, int ldc, int K, int M)
{
    __shared__ float As[BK][DBM + 4];
    __shared__ float B1s[BK][BN];
    __shared__ float B2s[BK][BN];
    int tid = threadIdx.x;
    int r0 = blockIdx.y * DBM;
    int c0 = blockIdx.x * BN;
    int tx = tid & 7;
    int ty = tid >> 3;   // 16, x4 rows

    unsigned long long ac1[4][4], ac2[4][4];
    #pragma unroll
    for (int i = 0; i < 4; i++)
        #pragma unroll
        for (int j = 0; j < 4; j++) { ac1[i][j] = 0ULL; ac2[i][j] = 0ULL; }

    for (int k0 = 0; k0 < K; k0 += BK) {
        #pragma unroll
        for (int t = 0; t < 8; t++) {
            int li = tid + t * 128;
            int m = li >> 4, kk = li & 15;
            int r = r0 + m, k = k0 + kk;
            As[kk][m] = (r < NNODES && k < K) ? A[(size_t)r * lda + k] : 0.0f;
        }
        #pragma unroll
        for (int t = 0; t < 8; t++) {
            int li = tid + t * 128;
            int kk = li >> 6, n = li & 63;
            int k = k0 + kk, c = c0 + n;
            bool ok = (k < K && c < M);
            B1s[kk][n] = ok ? W1[(size_t)k * M + c] : 0.0f;
            B2s[kk][n] = ok ? W2[(size_t)k * M + c] : 0.0f;
        }
        __syncthreads();
        #pragma unroll
        for (int kk = 0; kk < BK; kk++) {
            float4 a0 = *(const float4*)&B1s[kk][tx * 8];
            float4 a1 = *(const float4*)&B1s[kk][tx * 8 + 4];
            float4 c0v = *(const float4*)&B2s[kk][tx * 8];
            float4 c1v = *(const float4*)&B2s[kk][tx * 8 + 4];
            unsigned long long bp1[4] = {pk2(a0.x, a0.y), pk2(a0.z, a0.w),
                                         pk2(a1.x, a1.y), pk2(a1.z, a1.w)};
            unsigned long long bp2[4] = {pk2(c0v.x, c0v.y), pk2(c0v.z, c0v.w),
                                         pk2(c1v.x, c1v.y), pk2(c1v.z, c1v.w)};
            #pragma unroll
            for (int i = 0; i < 4; i++) {
                float a = As[kk][ty * 4 + i];
                unsigned long long ap = pk2(a, a);
                #pragma unroll
                for (int j = 0; j < 4; j++) {
                    fma2(ac1[i][j], ap, bp1[j]);
                    fma2(ac2[i][j], ap, bp2[j]);
                }
            }
        }
        __syncthreads();
    }

    #pragma unroll
    for (int i = 0; i < 4; i++) {
        int r = r0 + ty * 4 + i;
        if (r >= NNODES) continue;
        #pragma unroll
        for (int j = 0; j < 4; j++) {
            float mlo, mhi, llo, lhi;
            upk2(ac1[i][j], mlo, mhi);
            upk2(ac2[i][j], llo, lhi);
            #pragma unroll
            for (int h = 0; h < 2; h++) {
                int c = c0 + tx * 8 + j * 2 + h;
                if (c >= M) continue;
                float mu = (h ? mhi : mlo) + b1[c];
                float ls = (h ? lhi : llo) + b2[c];
                out[(size_t)r * ldc + c] =
                    mu + eps[(size_t)r * lde + c] * expf(ls) / 10.0f;
            }
        }
    }
}

// ---------------------------------------------------------------------------
// Host side
// ---------------------------------------------------------------------------
static void launch_prop(const float* in, float* P, int S) {
    int blocks = (NNODES + 7) / 8;
    switch (S) {
        case 96:  k_gather<96><<<blocks, 256>>>((const float4*)in, (float4*)P); break;
        case 128: k_gather<128><<<blocks, 256>>>((const float4*)in, (float4*)P); break;
        case 160: k_gather<160><<<blocks, 256>>>((const float4*)in, (float4*)P); break;
        case 192: k_gather<192><<<blocks, 256>>>((const float4*)in, (float4*)P); break;
    }
}

static void launch_gemm(const float* A, int lda, int K, const float* W,
                        const float* b, int M, int ldc, int mode, float* out) {
    dim3 grid((M + BN - 1) / BN, (NNODES + BM - 1) / BM);
    k_gemm<<<grid, 128>>>(A, lda, W, b, out, ldc, K, M, mode);
}

static void launch_dual(const float* A, int lda, int K,
                        const float* W1, const float* W2,
                        const float* b1, const float* b2,
                        const float* eps, int lde, int M, int ldc, float* out) {
    dim3 grid((M + BN - 1) / BN, (NNODES + DBM - 1) / DBM);
    k_gemm_dual<<<grid, 128>>>(A, lda, W1, W2, b1, b2, eps, lde, out, ldc, K, M);
}

extern "C" void kernel_launch(void* const* d_in, const int* in_sizes, int n_in,
                              void* d_out, int out_size) {
    const float* x     = (const float*)d_in[0];
    const void*  ei    = d_in[1];
    const float* eps_e = (const float*)d_in[2];
    const float* eps_n = (const float*)d_in[3];
    const float* w1e = (const float*)d_in[4];  const float* b1e = (const float*)d_in[5];
    const float* w2e = (const float*)d_in[6];  const float* b2e = (const float*)d_in[7];
    const float* wme = (const float*)d_in[8];  const float* bme = (const float*)d_in[9];
    const float* wle = (const float*)d_in[10]; const float* ble = (const float*)d_in[11];
    const float* w4e = (const float*)d_in[12]; const float* b4e = (const float*)d_in[13];
    const float* w1n = (const float*)d_in[14]; const float* b1n = (const float*)d_in[15];
    const float* wmn = (const float*)d_in[16]; const float* bmn = (const float*)d_in[17];
    const float* wln = (const float*)d_in[18]; const float* bln = (const float*)d_in[19];
    const float* w5n = (const float*)d_in[20]; const float* b5n = (const float*)d_in[21];

    float* out   = (float*)d_out;
    float* edges = out;                         // [N,192]
    float* nodes = out + (size_t)NNODES * 192;  // [N,96]

    float *P, *bufA, *bufB;
    cudaGetSymbolAddress((void**)&P,    g_P);
    cudaGetSymbolAddress((void**)&bufA, g_bufA);
    cudaGetSymbolAddress((void**)&bufB, g_bufB);

    // ---- prep (probe deliberately placed as 4th launch for ncu -s 5 -c 1) --
    k_prep1<<<(NNODES + 255) / 256, 256>>>();                 // #1
    k_detect<<<512, 256>>>((const unsigned*)ei);              // #2
    k_convert<<<(NEDGES + 255) / 256, 256>>>(ei);             // #3
    launch_gemm(x, 96, 96, w1e, b1e, 125, 128, 1, P);         // #4 PROBE (P overwritten later)
    k_dinv<<<(NNODES + 255) / 256, 256>>>();                  // #5
    k_scanA<<<NBLK, 1024>>>();                                // #6
    k_scanB<<<1, 32>>>();                                     // #7
    k_scanC<<<NBLK, 1024>>>();                                // #8
    k_fill<<<(NEDGES + 255) / 256, 256>>>();                  // #9

    // ---- shared first propagation: P = Â x (stride 96) ----
    launch_prop(x, P, 96);
    launch_gemm(P, 96, 96, w1e, b1e, 125, 128, 1, bufA);      // e1 relu
    launch_gemm(P, 96, 96, w1n, b1n, 96,  96,  1, bufB);      // n1 relu

    // ---- edge branch ----
    launch_prop(bufA, P, 128);                                // C=125 in stride 128
    launch_gemm(P, 128, 125, w2e, b2e, 144, 160, 1, bufA);    // e2 relu
    launch_prop(bufA, P, 160);                                // C=144 in stride 160
    launch_dual(P, 160, 144, wme, wle, bme, ble, eps_e, 163, 163, 192, bufA);
    launch_prop(bufA, P, 192);                                // C=163 in stride 192
    launch_gemm(P, 192, 163, w4e, b4e, 192, 192, 2, edges);   // sigmoid

    // ---- node branch ----
    launch_prop(bufB, P, 96);
    launch_dual(P, 96, 96, wmn, wln, bmn, bln, eps_n, 96, 96, 96, bufA);
    launch_prop(bufA, P, 96);
    launch_gemm(P, 96, 96, w5n, b5n, 96, 96, 1, nodes);       // relu
}

// round 6
// speedup vs baseline: 2.4329x; 1.1387x over previous
#include <cuda_runtime.h>
#include <math.h>

#define NNODES 50000
#define NEDGES 800000
#define NBLK 13

// ---------------------------------------------------------------------------
// Scratch
// ---------------------------------------------------------------------------
__device__ float g_P[(size_t)NNODES * 192];
__device__ float g_bufA[(size_t)NNODES * 192];
__device__ float g_bufB[(size_t)NNODES * 96];
__device__ float g_dinv[NNODES];
__device__ int   g_row[NEDGES];
__device__ int   g_col[NEDGES];
__device__ int   g_ideg[NNODES];
__device__ int   g_off[NNODES + 1];
__device__ int   g_cursor[NNODES];
__device__ int2  g_ecsr[NEDGES];
__device__ int   g_bsum[32];
__device__ int   g_bpre[32];
__device__ unsigned g_flag32;

// ---------------------------------------------------------------------------
// f32x2 helpers
// ---------------------------------------------------------------------------
__device__ __forceinline__ unsigned long long pk2(float lo, float hi) {
    unsigned long long r;
    asm("mov.b64 %0,{%1,%2};" : "=l"(r) : "f"(lo), "f"(hi));
    return r;
}
__device__ __forceinline__ void upk2(unsigned long long v, float& lo, float& hi) {
    asm("mov.b64 {%0,%1},%2;" : "=f"(lo), "=f"(hi) : "l"(v));
}
__device__ __forceinline__ void fma2(unsigned long long& d, unsigned long long a,
                                     unsigned long long b) {
    asm("fma.rn.f32x2 %0,%1,%2,%0;" : "+l"(d) : "l"(a), "l"(b));
}

// ---------------------------------------------------------------------------
// Prep kernels
// ---------------------------------------------------------------------------
__global__ void k_prep1() {
    int i = blockIdx.x * blockDim.x + threadIdx.x;
    if (i < NNODES) g_ideg[i] = 0;
    if (i == 0) g_flag32 = 0u;
}

__global__ void k_detect(const unsigned* __restrict__ w) {
    unsigned v = 0;
    for (int i = blockIdx.x * blockDim.x + threadIdx.x; i < NEDGES;
         i += gridDim.x * blockDim.x)
        v |= w[2 * i + 1];
    #pragma unroll
    for (int o = 16; o; o >>= 1) v |= __shfl_xor_sync(0xFFFFFFFFu, v, o);
    if ((threadIdx.x & 31) == 0 && v) atomicOr(&g_flag32, 1u);
}

__global__ void k_convert(const void* __restrict__ ei) {
    int e = blockIdx.x * blockDim.x + threadIdx.x;
    if (e >= NEDGES) return;
    int r, c;
    if (g_flag32 == 0u) {
        const long long* ll = (const long long*)ei;
        r = (int)ll[e];
        c = (int)ll[NEDGES + e];
    } else {
        const int* q = (const int*)ei;
        r = q[e];
        c = q[NEDGES + e];
    }
    g_row[e] = r;
    g_col[e] = c;
    atomicAdd(&g_ideg[c], 1);
}

__global__ void k_dinv() {
    int i = blockIdx.x * blockDim.x + threadIdx.x;
    if (i < NNODES) g_dinv[i] = rsqrtf((float)g_ideg[i] + 1.0f);
}

__global__ __launch_bounds__(1024) void k_scanA() {
    __shared__ int sh[32];
    int b = blockIdx.x, t = threadIdx.x;
    int base = b * 4096 + t * 4;
    int s = 0;
    #pragma unroll
    for (int j = 0; j < 4; j++) {
        int i = base + j;
        if (i < NNODES) s += g_ideg[i];
    }
    #pragma unroll
    for (int o = 16; o; o >>= 1) s += __shfl_xor_sync(0xFFFFFFFFu, s, o);
    if ((t & 31) == 0) sh[t >> 5] = s;
    __syncthreads();
    if (t < 32) {
        int x = sh[t];
        #pragma unroll
        for (int o = 16; o; o >>= 1) x += __shfl_xor_sync(0xFFFFFFFFu, x, o);
        if (t == 0) g_bsum[b] = x;
    }
}

__global__ void k_scanB() {
    int t = threadIdx.x;
    int v = (t < NBLK) ? g_bsum[t] : 0;
    int own = v;
    #pragma unroll
    for (int o = 1; o < 32; o <<= 1) {
        int u = __shfl_up_sync(0xFFFFFFFFu, v, o);
        if (t >= o) v += u;
    }
    if (t < NBLK) g_bpre[t] = v - own;
}

__global__ __launch_bounds__(1024) void k_scanC() {
    __shared__ int sh[1024];
    int b = blockIdx.x, t = threadIdx.x;
    int base = b * 4096 + t * 4;
    int v[4];
    int s = 0;
    #pragma unroll
    for (int j = 0; j < 4; j++) {
        int i = base + j;
        v[j] = (i < NNODES) ? g_ideg[i] : 0;
        s += v[j];
    }
    sh[t] = s;
    __syncthreads();
    #pragma unroll
    for (int o = 1; o < 1024; o <<= 1) {
        int tmp = (t >= o) ? sh[t - o] : 0;
        __syncthreads();
        sh[t] += tmp;
        __syncthreads();
    }
    int excl = sh[t] - s + g_bpre[b];
    #pragma unroll
    for (int j = 0; j < 4; j++) {
        int i = base + j;
        if (i < NNODES) { g_off[i] = excl; g_cursor[i] = excl; }
        excl += v[j];
    }
    if (b == 0 && t == 0) g_off[NNODES] = NEDGES;
}

__global__ void k_fill() {
    int e = blockIdx.x * blockDim.x + threadIdx.x;
    if (e >= NEDGES) return;
    int r = g_row[e], c = g_col[e];
    float cf = g_dinv[r] * g_dinv[c];
    int pos = atomicAdd(&g_cursor[c], 1);
    g_ecsr[pos] = make_int2(r, __float_as_int(cf));
}

// ---------------------------------------------------------------------------
// Gather: one warp per node, row stride S floats (128B multiple)
// ---------------------------------------------------------------------------
template <int S>
__global__ __launch_bounds__(256) void k_gather(const float4* __restrict__ in4,
                                                float4* __restrict__ out4) {
    constexpr int NV4 = S / 4;
    constexpr int NIT = (NV4 + 31) / 32;
    int node = blockIdx.x * 8 + (threadIdx.x >> 5);
    if (node >= NNODES) return;
    int lane = threadIdx.x & 31;

    float d = g_dinv[node];
    float dd = d * d;

    float4 acc[NIT];
    #pragma unroll
    for (int v = 0; v < NIT; v++) {
        int id = lane + 32 * v;
        if (id < NV4) {
            float4 t = in4[(size_t)node * NV4 + id];
            acc[v] = make_float4(t.x * dd, t.y * dd, t.z * dd, t.w * dd);
        } else acc[v] = make_float4(0.f, 0.f, 0.f, 0.f);
    }

    int s = g_off[node];
    int e = g_off[node + 1];
    int i = s;
    for (; i + 3 < e; i += 4) {
        int2 p0 = g_ecsr[i];
        int2 p1 = g_ecsr[i + 1];
        int2 p2 = g_ecsr[i + 2];
        int2 p3 = g_ecsr[i + 3];
        float c0 = __int_as_float(p0.y), c1 = __int_as_float(p1.y);
        float c2 = __int_as_float(p2.y), c3 = __int_as_float(p3.y);
        #pragma unroll
        for (int v = 0; v < NIT; v++) {
            int id = lane + 32 * v;
            if (id < NV4) {
                float4 a0 = in4[(size_t)p0.x * NV4 + id];
                float4 a1 = in4[(size_t)p1.x * NV4 + id];
                float4 a2 = in4[(size_t)p2.x * NV4 + id];
                float4 a3 = in4[(size_t)p3.x * NV4 + id];
                acc[v].x += a0.x * c0; acc[v].y += a0.y * c0;
                acc[v].z += a0.z * c0; acc[v].w += a0.w * c0;
                acc[v].x += a1.x * c1; acc[v].y += a1.y * c1;
                acc[v].z += a1.z * c1; acc[v].w += a1.w * c1;
                acc[v].x += a2.x * c2; acc[v].y += a2.y * c2;
                acc[v].z += a2.z * c2; acc[v].w += a2.w * c2;
                acc[v].x += a3.x * c3; acc[v].y += a3.y * c3;
                acc[v].z += a3.z * c3; acc[v].w += a3.w * c3;
            }
        }
    }
    for (; i < e; i++) {
        int2 p = g_ecsr[i];
        float c0 = __int_as_float(p.y);
        #pragma unroll
        for (int v = 0; v < NIT; v++) {
            int id = lane + 32 * v;
            if (id < NV4) {
                float4 a = in4[(size_t)p.x * NV4 + id];
                acc[v].x += a.x * c0; acc[v].y += a.y * c0;
                acc[v].z += a.z * c0; acc[v].w += a.w * c0;
            }
        }
    }
    #pragma unroll
    for (int v = 0; v < NIT; v++) {
        int id = lane + 32 * v;
        if (id < NV4) out4[(size_t)node * NV4 + id] = acc[v];
    }
}

// ---------------------------------------------------------------------------
// Single GEMM, double-buffered, vectorized LDS. BM=128,BN=64,BK=16,128 thr.
// ---------------------------------------------------------------------------
#define BM 128
#define BN 64
#define BK 16
#define AS_LD 132   // multiple of 4 -> float4-aligned rows

__global__ __launch_bounds__(128) void k_gemm(
    const float* __restrict__ A, int lda,
    const float* __restrict__ W,
    const float* __restrict__ bias, float* __restrict__ out, int ldc,
    int K, int M, int mode, int rows)
{
    __shared__ float As[2][BK][AS_LD];
    __shared__ float Bs[2][BK][BN];
    int tid = threadIdx.x;
    int r0 = blockIdx.y * BM;
    int c0 = blockIdx.x * BN;
    int tx = tid & 7;
    int ty = tid >> 3;

    // tile 0 -> buffer 0
    #pragma unroll
    for (int t = 0; t < 16; t++) {
        int li = tid + t * 128;
        int m = li >> 4, kk = li & 15;
        int r = r0 + m;
        As[0][kk][m] = (r < rows && kk < K) ? A[(size_t)r * lda + kk] : 0.0f;
    }
    #pragma unroll
    for (int t = 0; t < 8; t++) {
        int li = tid + t * 128;
        int kk = li >> 6, n = li & 63;
        int c = c0 + n;
        Bs[0][kk][n] = (kk < K && c < M) ? W[(size_t)kk * M + c] : 0.0f;
    }
    __syncthreads();

    unsigned long long acc[8][4];
    #pragma unroll
    for (int i = 0; i < 8; i++)
        #pragma unroll
        for (int j = 0; j < 4; j++) acc[i][j] = 0ULL;

    int nk = (K + BK - 1) / BK;
    for (int it = 0; it < nk; it++) {
        int buf = it & 1;
        float pa[16], pb[8];
        bool nx = (it + 1 < nk);
        if (nx) {
            int k0 = (it + 1) * BK;
            #pragma unroll
            for (int t = 0; t < 16; t++) {
                int li = tid + t * 128;
                int m = li >> 4, kk = li & 15;
                int r = r0 + m, k = k0 + kk;
                pa[t] = (r < rows && k < K) ? A[(size_t)r * lda + k] : 0.0f;
            }
            #pragma unroll
            for (int t = 0; t < 8; t++) {
                int li = tid + t * 128;
                int kk = li >> 6, n = li & 63;
                int k = k0 + kk, c = c0 + n;
                pb[t] = (k < K && c < M) ? W[(size_t)k * M + c] : 0.0f;
            }
        }
        #pragma unroll
        for (int kk = 0; kk < BK; kk++) {
            float4 b0 = *(const float4*)&Bs[buf][kk][tx * 8];
            float4 b1 = *(const float4*)&Bs[buf][kk][tx * 8 + 4];
            float4 a0 = *(const float4*)&As[buf][kk][ty * 8];
            float4 a1 = *(const float4*)&As[buf][kk][ty * 8 + 4];
            unsigned long long bp0 = pk2(b0.x, b0.y);
            unsigned long long bp1 = pk2(b0.z, b0.w);
            unsigned long long bp2 = pk2(b1.x, b1.y);
            unsigned long long bp3 = pk2(b1.z, b1.w);
            float av[8] = {a0.x, a0.y, a0.z, a0.w, a1.x, a1.y, a1.z, a1.w};
            #pragma unroll
            for (int i = 0; i < 8; i++) {
                unsigned long long ap = pk2(av[i], av[i]);
                fma2(acc[i][0], ap, bp0);
                fma2(acc[i][1], ap, bp1);
                fma2(acc[i][2], ap, bp2);
                fma2(acc[i][3], ap, bp3);
            }
        }
        if (nx) {
            int nb = buf ^ 1;
            #pragma unroll
            for (int t = 0; t < 16; t++) {
                int li = tid + t * 128;
                As[nb][li & 15][li >> 4] = pa[t];
            }
            #pragma unroll
            for (int t = 0; t < 8; t++) {
                int li = tid + t * 128;
                Bs[nb][li >> 6][li & 63] = pb[t];
            }
            __syncthreads();
        }
    }

    #pragma unroll
    for (int i = 0; i < 8; i++) {
        int r = r0 + ty * 8 + i;
        if (r >= rows) continue;
        #pragma unroll
        for (int j = 0; j < 4; j++) {
            float lo, hi;
            upk2(acc[i][j], lo, hi);
            #pragma unroll
            for (int h = 0; h < 2; h++) {
                int c = c0 + tx * 8 + j * 2 + h;
                if (c >= M) continue;
                float v = (h ? hi : lo) + bias[c];
                if (mode == 1) v = fmaxf(v, 0.0f);
                else if (mode == 2) v = 1.0f / (1.0f + expf(-v));
                out[(size_t)r * ldc + c] = v;
            }
        }
    }
}

// ---------------------------------------------------------------------------
// Dual GEMM (mu/ls fused reparam), double-buffered. BM=64.
// ---------------------------------------------------------------------------
#define DBM 64
#define DAS_LD 68

__global__ __launch_bounds__(128) void k_gemm_dual(
    const float* __restrict__ A, int lda,
    const float* __restrict__ W1, const float* __restrict__ W2,
    const float* __restrict__ b1, const float* __restrict__ b2,
    const float* __restrict__ eps, int lde,
    float* __restrict__ out, int ldc, int K, int M)
{
    __shared__ float As[2][BK][DAS_LD];
    __shared__ float B1s[2][BK][BN];
    __shared__ float B2s[2][BK][BN];
    int tid = threadIdx.x;
    int r0 = blockIdx.y * DBM;
    int c0 = blockIdx.x * BN;
    int tx = tid & 7;
    int ty = tid >> 3;

    #pragma unroll
    for (int t = 0; t < 8; t++) {
        int li = tid + t * 128;
        int m = li >> 4, kk = li & 15;
        int r = r0 + m;
        As[0][kk][m] = (r < NNODES && kk < K) ? A[(size_t)r * lda + kk] : 0.0f;
    }
    #pragma unroll
    for (int t = 0; t < 8; t++) {
        int li = tid + t * 128;
        int kk = li >> 6, n = li & 63;
        int c = c0 + n;
        bool ok = (kk < K && c < M);
        B1s[0][kk][n] = ok ? W1[(size_t)kk * M + c] : 0.0f;
        B2s[0][kk][n] = ok ? W2[(size_t)kk * M + c] : 0.0f;
    }
    __syncthreads();

    unsigned long long ac1[4][4], ac2[4][4];
    #pragma unroll
    for (int i = 0; i < 4; i++)
        #pragma unroll
        for (int j = 0; j < 4; j++) { ac1[i][j] = 0ULL; ac2[i][j] = 0ULL; }

    int nk = (K + BK - 1) / BK;
    for (int it = 0; it < nk; it++) {
        int buf = it & 1;
        float pa[8], pb1[8], pb2[8];
        bool nx = (it + 1 < nk);
        if (nx) {
            int k0 = (it + 1) * BK;
            #pragma unroll
            for (int t = 0; t < 8; t++) {
                int li = tid + t * 128;
                int m = li >> 4, kk = li & 15;
                int r = r0 + m, k = k0 + kk;
                pa[t] = (r < NNODES && k < K) ? A[(size_t)r * lda + k] : 0.0f;
            }
            #pragma unroll
            for (int t = 0; t < 8; t++) {
                int li = tid + t * 128;
                int kk = li >> 6, n = li & 63;
                int k = k0 + kk, c = c0 + n;
                bool ok = (k < K && c < M);
                pb1[t] = ok ? W1[(size_t)k * M + c] : 0.0f;
                pb2[t] = ok ? W2[(size_t)k * M + c] : 0.0f;
            }
        }
        #pragma unroll
        for (int kk = 0; kk < BK; kk++) {
            float4 x0 = *(const float4*)&B1s[buf][kk][tx * 8];
            float4 x1 = *(const float4*)&B1s[buf][kk][tx * 8 + 4];
            float4 y0 = *(const float4*)&B2s[buf][kk][tx * 8];
            float4 y1 = *(const float4*)&B2s[buf][kk][tx * 8 + 4];
            float4 a0 = *(const float4*)&As[buf][kk][ty * 4];  // wait: ty*4 not 16B-aligned for odd ty? ty*4 floats = 16B multiple ✓
            unsigned long long bp1[4] = {pk2(x0.x, x0.y), pk2(x0.z, x0.w),
                                         pk2(x1.x, x1.y), pk2(x1.z, x1.w)};
            unsigned long long bp2[4] = {pk2(y0.x, y0.y), pk2(y0.z, y0.w),
                                         pk2(y1.x, y1.y), pk2(y1.z, y1.w)};
            float av[4] = {a0.x, a0.y, a0.z, a0.w};
            #pragma unroll
            for (int i = 0; i < 4; i++) {
                unsigned long long ap = pk2(av[i], av[i]);
                #pragma unroll
                for (int j = 0; j < 4; j++) {
                    fma2(ac1[i][j], ap, bp1[j]);
                    fma2(ac2[i][j], ap, bp2[j]);
                }
            }
        }
        if (nx) {
            int nb = buf ^ 1;
            #pragma unroll
            for (int t = 0; t < 8; t++) {
                int li = tid + t * 128;
                As[nb][li & 15][li >> 4] = pa[t];
            }
            #pragma unroll
            for (int t = 0; t < 8; t++) {
                int li = tid + t * 128;
                B1s[nb][li >> 6][li & 63] = pb1[t];
                B2s[nb][li >> 6][li & 63] = pb2[t];
            }
            __syncthreads();
        }
    }

    #pragma unroll
    for (int i = 0; i < 4; i++) {
        int r = r0 + ty * 4 + i;
        if (r >= NNODES) continue;
        #pragma unroll
        for (int j = 0; j < 4; j++) {
            float mlo, mhi, llo, lhi;
            upk2(ac1[i][j], mlo, mhi);
            upk2(ac2[i][j], llo, lhi);
            #pragma unroll
            for (int h = 0; h < 2; h++) {
                int c = c0 + tx * 8 + j * 2 + h;
                if (c >= M) continue;
                float mu = (h ? mhi : mlo) + b1[c];
                float ls = (h ? lhi : llo) + b2[c];
                out[(size_t)r * ldc + c] =
                    mu + eps[(size_t)r * lde + c] * expf(ls) / 10.0f;
            }
        }
    }
}

// ---------------------------------------------------------------------------
// Host side
// ---------------------------------------------------------------------------
static void launch_prop(const float* in, float* P, int S) {
    int blocks = (NNODES + 7) / 8;
    switch (S) {
        case 96:  k_gather<96><<<blocks, 256>>>((const float4*)in, (float4*)P); break;
        case 128: k_gather<128><<<blocks, 256>>>((const float4*)in, (float4*)P); break;
        case 160: k_gather<160><<<blocks, 256>>>((const float4*)in, (float4*)P); break;
        case 192: k_gather<192><<<blocks, 256>>>((const float4*)in, (float4*)P); break;
    }
}

static void launch_gemm(const float* A, int lda, int K, const float* W,
                        const float* b, int M, int ldc, int mode, float* out) {
    dim3 grid((M + BN - 1) / BN, (NNODES + BM - 1) / BM);
    k_gemm<<<grid, 128>>>(A, lda, W, b, out, ldc, K, M, mode, NNODES);
}

static void launch_dual(const float* A, int lda, int K,
                        const float* W1, const float* W2,
                        const float* b1, const float* b2,
                        const float* eps, int lde, int M, int ldc, float* out) {
    dim3 grid((M + BN - 1) / BN, (NNODES + DBM - 1) / DBM);
    k_gemm_dual<<<grid, 128>>>(A, lda, W1, W2, b1, b2, eps, lde, out, ldc, K, M);
}

extern "C" void kernel_launch(void* const* d_in, const int* in_sizes, int n_in,
                              void* d_out, int out_size) {
    const float* x     = (const float*)d_in[0];
    const void*  ei    = d_in[1];
    const float* eps_e = (const float*)d_in[2];
    const float* eps_n = (const float*)d_in[3];
    const float* w1e = (const float*)d_in[4];  const float* b1e = (const float*)d_in[5];
    const float* w2e = (const float*)d_in[6];  const float* b2e = (const float*)d_in[7];
    const float* wme = (const float*)d_in[8];  const float* bme = (const float*)d_in[9];
    const float* wle = (const float*)d_in[10]; const float* ble = (const float*)d_in[11];
    const float* w4e = (const float*)d_in[12]; const float* b4e = (const float*)d_in[13];
    const float* w1n = (const float*)d_in[14]; const float* b1n = (const float*)d_in[15];
    const float* wmn = (const float*)d_in[16]; const float* bmn = (const float*)d_in[17];
    const float* wln = (const float*)d_in[18]; const float* bln = (const float*)d_in[19];
    const float* w5n = (const float*)d_in[20]; const float* b5n = (const float*)d_in[21];

    float* out   = (float*)d_out;
    float* edges = out;                         // [N,192]
    float* nodes = out + (size_t)NNODES * 192;  // [N,96]

    float *P, *bufA, *bufB;
    cudaGetSymbolAddress((void**)&P,    g_P);
    cudaGetSymbolAddress((void**)&bufA, g_bufA);
    cudaGetSymbolAddress((void**)&bufB, g_bufB);

    // ---- prep (launch #4 = small GEMM probe for ncu -s 5 -c 1) ----
    k_prep1<<<(NNODES + 255) / 256, 256>>>();                 // #1
    k_detect<<<512, 256>>>((const unsigned*)ei);              // #2
    k_convert<<<(NEDGES + 255) / 256, 256>>>(ei);             // #3
    {   // #4 PROBE: 3200-row slice of the e1 GEMM shape (P overwritten later)
        dim3 grid((125 + BN - 1) / BN, (3200 + BM - 1) / BM);
        k_gemm<<<grid, 128>>>(x, 96, w1e, b1e, P, 128, 96, 125, 1, 3200);
    }
    k_dinv<<<(NNODES + 255) / 256, 256>>>();                  // #5
    k_scanA<<<NBLK, 1024>>>();                                // #6
    k_scanB<<<1, 32>>>();                                     // #7
    k_scanC<<<NBLK, 1024>>>();                                // #8
    k_fill<<<(NEDGES + 255) / 256, 256>>>();                  // #9

    // ---- shared first propagation: P = Â x (stride 96) ----
    launch_prop(x, P, 96);
    launch_gemm(P, 96, 96, w1e, b1e, 125, 128, 1, bufA);      // e1 relu
    launch_gemm(P, 96, 96, w1n, b1n, 96,  96,  1, bufB);      // n1 relu

    // ---- edge branch ----
    launch_prop(bufA, P, 128);                                // C=125, stride 128
    launch_gemm(P, 128, 125, w2e, b2e, 144, 160, 1, bufA);    // e2 relu
    launch_prop(bufA, P, 160);                                // C=144, stride 160
    launch_dual(P, 160, 144, wme, wle, bme, ble, eps_e, 163, 163, 192, bufA);
    launch_prop(bufA, P, 192);                                // C=163, stride 192
    launch_gemm(P, 192, 163, w4e, b4e, 192, 192, 2, edges);   // sigmoid

    // ---- node branch ----
    launch_prop(bufB, P, 96);
    launch_dual(P, 96, 96, wmn, wln, bmn, bln, eps_n, 96, 96, 96, bufA);
    launch_prop(bufA, P, 96);
    launch_gemm(P, 96, 96, w5n, b5n, 96, 96, 1, nodes);       // relu
}

// round 7
// speedup vs baseline: 2.5077x; 1.0307x over previous
#include <cuda_runtime.h>
#include <math.h>

#define NNODES 50000
#define NEDGES 800000
#define NBLK 13

// ---------------------------------------------------------------------------
// Scratch
// ---------------------------------------------------------------------------
__device__ float g_P[(size_t)NNODES * 192];
__device__ float g_bufA[(size_t)NNODES * 192];
__device__ float g_bufB[(size_t)NNODES * 96];
__device__ float g_dinv[NNODES];
__device__ int   g_row[NEDGES];
__device__ int   g_col[NEDGES];
__device__ int   g_ideg[NNODES];
__device__ int   g_off[NNODES + 1];
__device__ int   g_cursor[NNODES];
__device__ int2  g_ecsr[NEDGES];
__device__ int   g_bsum[32];
__device__ int   g_bpre[32];
__device__ unsigned g_flag32;

// ---------------------------------------------------------------------------
// helpers
// ---------------------------------------------------------------------------
__device__ __forceinline__ unsigned long long pk2(float lo, float hi) {
    unsigned long long r;
    asm("mov.b64 %0,{%1,%2};" : "=l"(r) : "f"(lo), "f"(hi));
    return r;
}
__device__ __forceinline__ void upk2(unsigned long long v, float& lo, float& hi) {
    asm("mov.b64 {%0,%1},%2;" : "=f"(lo), "=f"(hi) : "l"(v));
}
__device__ __forceinline__ void fma2(unsigned long long& d, unsigned long long a,
                                     unsigned long long b) {
    asm("fma.rn.f32x2 %0,%1,%2,%0;" : "+l"(d) : "l"(a), "l"(b));
}
__device__ __forceinline__ unsigned s2u(const void* p) {
    return (unsigned)__cvta_generic_to_shared(p);
}
// 4B async copy; pred=false -> zero-fill (src not read)
__device__ __forceinline__ void cpa4(unsigned dst, const float* src, bool p) {
    asm volatile("cp.async.ca.shared.global [%0], [%1], 4, %2;"
                 :: "r"(dst), "l"(src), "r"(p ? 4 : 0));
}
#define CP_COMMIT() asm volatile("cp.async.commit_group;")
template <int N>
__device__ __forceinline__ void cp_wait() {
    asm volatile("cp.async.wait_group %0;" :: "n"(N));
}

// ---------------------------------------------------------------------------
// Prep kernels
// ---------------------------------------------------------------------------
__global__ void k_prep1() {
    int i = blockIdx.x * blockDim.x + threadIdx.x;
    if (i < NNODES) g_ideg[i] = 0;
    if (i == 0) g_flag32 = 0u;
}

__global__ void k_detect(const unsigned* __restrict__ w) {
    unsigned v = 0;
    for (int i = blockIdx.x * blockDim.x + threadIdx.x; i < NEDGES;
         i += gridDim.x * blockDim.x)
        v |= w[2 * i + 1];
    #pragma unroll
    for (int o = 16; o; o >>= 1) v |= __shfl_xor_sync(0xFFFFFFFFu, v, o);
    if ((threadIdx.x & 31) == 0 && v) atomicOr(&g_flag32, 1u);
}

__global__ void k_convert(const void* __restrict__ ei) {
    int e = blockIdx.x * blockDim.x + threadIdx.x;
    if (e >= NEDGES) return;
    int r, c;
    if (g_flag32 == 0u) {
        const long long* ll = (const long long*)ei;
        r = (int)ll[e];
        c = (int)ll[NEDGES + e];
    } else {
        const int* q = (const int*)ei;
        r = q[e];
        c = q[NEDGES + e];
    }
    g_row[e] = r;
    g_col[e] = c;
    atomicAdd(&g_ideg[c], 1);
}

__global__ void k_dinv() {
    int i = blockIdx.x * blockDim.x + threadIdx.x;
    if (i < NNODES) g_dinv[i] = rsqrtf((float)g_ideg[i] + 1.0f);
}

__global__ __launch_bounds__(1024) void k_scanA() {
    __shared__ int sh[32];
    int b = blockIdx.x, t = threadIdx.x;
    int base = b * 4096 + t * 4;
    int s = 0;
    #pragma unroll
    for (int j = 0; j < 4; j++) {
        int i = base + j;
        if (i < NNODES) s += g_ideg[i];
    }
    #pragma unroll
    for (int o = 16; o; o >>= 1) s += __shfl_xor_sync(0xFFFFFFFFu, s, o);
    if ((t & 31) == 0) sh[t >> 5] = s;
    __syncthreads();
    if (t < 32) {
        int x = sh[t];
        #pragma unroll
        for (int o = 16; o; o >>= 1) x += __shfl_xor_sync(0xFFFFFFFFu, x, o);
        if (t == 0) g_bsum[b] = x;
    }
}

__global__ void k_scanB() {
    int t = threadIdx.x;
    int v = (t < NBLK) ? g_bsum[t] : 0;
    int own = v;
    #pragma unroll
    for (int o = 1; o < 32; o <<= 1) {
        int u = __shfl_up_sync(0xFFFFFFFFu, v, o);
        if (t >= o) v += u;
    }
    if (t < NBLK) g_bpre[t] = v - own;
}

__global__ __launch_bounds__(1024) void k_scanC() {
    __shared__ int sh[1024];
    int b = blockIdx.x, t = threadIdx.x;
    int base = b * 4096 + t * 4;
    int v[4];
    int s = 0;
    #pragma unroll
    for (int j = 0; j < 4; j++) {
        int i = base + j;
        v[j] = (i < NNODES) ? g_ideg[i] : 0;
        s += v[j];
    }
    sh[t] = s;
    __syncthreads();
    #pragma unroll
    for (int o = 1; o < 1024; o <<= 1) {
        int tmp = (t >= o) ? sh[t - o] : 0;
        __syncthreads();
        sh[t] += tmp;
        __syncthreads();
    }
    int excl = sh[t] - s + g_bpre[b];
    #pragma unroll
    for (int j = 0; j < 4; j++) {
        int i = base + j;
        if (i < NNODES) { g_off[i] = excl; g_cursor[i] = excl; }
        excl += v[j];
    }
    if (b == 0 && t == 0) g_off[NNODES] = NEDGES;
}

__global__ void k_fill() {
    int e = blockIdx.x * blockDim.x + threadIdx.x;
    if (e >= NEDGES) return;
    int r = g_row[e], c = g_col[e];
    float cf = g_dinv[r] * g_dinv[c];
    int pos = atomicAdd(&g_cursor[c], 1);
    g_ecsr[pos] = make_int2(r, __float_as_int(cf));
}

// ---------------------------------------------------------------------------
// Gather: one warp per node, row stride S floats (128B multiple)
// ---------------------------------------------------------------------------
template <int S>
__global__ __launch_bounds__(256) void k_gather(const float4* __restrict__ in4,
                                                float4* __restrict__ out4) {
    constexpr int NV4 = S / 4;
    constexpr int NIT = (NV4 + 31) / 32;
    int node = blockIdx.x * 8 + (threadIdx.x >> 5);
    if (node >= NNODES) return;
    int lane = threadIdx.x & 31;

    float d = g_dinv[node];
    float dd = d * d;

    float4 acc[NIT];
    #pragma unroll
    for (int v = 0; v < NIT; v++) {
        int id = lane + 32 * v;
        if (id < NV4) {
            float4 t = in4[(size_t)node * NV4 + id];
            acc[v] = make_float4(t.x * dd, t.y * dd, t.z * dd, t.w * dd);
        } else acc[v] = make_float4(0.f, 0.f, 0.f, 0.f);
    }

    int s = g_off[node];
    int e = g_off[node + 1];
    int i = s;
    for (; i + 3 < e; i += 4) {
        int2 p0 = g_ecsr[i];
        int2 p1 = g_ecsr[i + 1];
        int2 p2 = g_ecsr[i + 2];
        int2 p3 = g_ecsr[i + 3];
        float c0 = __int_as_float(p0.y), c1 = __int_as_float(p1.y);
        float c2 = __int_as_float(p2.y), c3 = __int_as_float(p3.y);
        #pragma unroll
        for (int v = 0; v < NIT; v++) {
            int id = lane + 32 * v;
            if (id < NV4) {
                float4 a0 = in4[(size_t)p0.x * NV4 + id];
                float4 a1 = in4[(size_t)p1.x * NV4 + id];
                float4 a2 = in4[(size_t)p2.x * NV4 + id];
                float4 a3 = in4[(size_t)p3.x * NV4 + id];
                acc[v].x += a0.x * c0; acc[v].y += a0.y * c0;
                acc[v].z += a0.z * c0; acc[v].w += a0.w * c0;
                acc[v].x += a1.x * c1; acc[v].y += a1.y * c1;
                acc[v].z += a1.z * c1; acc[v].w += a1.w * c1;
                acc[v].x += a2.x * c2; acc[v].y += a2.y * c2;
                acc[v].z += a2.z * c2; acc[v].w += a2.w * c2;
                acc[v].x += a3.x * c3; acc[v].y += a3.y * c3;
                acc[v].z += a3.z * c3; acc[v].w += a3.w * c3;
            }
        }
    }
    for (; i < e; i++) {
        int2 p = g_ecsr[i];
        float c0 = __int_as_float(p.y);
        #pragma unroll
        for (int v = 0; v < NIT; v++) {
            int id = lane + 32 * v;
            if (id < NV4) {
                float4 a = in4[(size_t)p.x * NV4 + id];
                acc[v].x += a.x * c0; acc[v].y += a.y * c0;
                acc[v].z += a.z * c0; acc[v].w += a.w * c0;
            }
        }
    }
    #pragma unroll
    for (int v = 0; v < NIT; v++) {
        int id = lane + 32 * v;
        if (id < NV4) out4[(size_t)node * NV4 + id] = acc[v];
    }
}

// ---------------------------------------------------------------------------
// Single GEMM, cp.async double-buffered. BM=128,BN=64,BK=16,128 threads.
// NOTE: requires lda >= ceil(K/16)*16 (padded A rows, guaranteed by caller).
// ---------------------------------------------------------------------------
#define BM 128
#define BN 64
#define BK 16
#define AS_LD 132

__global__ __launch_bounds__(128, 4) void k_gemm(
    const float* __restrict__ A, int lda,
    const float* __restrict__ W,
    const float* __restrict__ bias, float* __restrict__ out, int ldc,
    int K, int M, int mode, int rows)
{
    __shared__ float As[2][BK][AS_LD];
    __shared__ float Bs[2][BK][BN];
    int tid = threadIdx.x;
    int r0 = blockIdx.y * BM;
    int c0 = blockIdx.x * BN;
    int tx = tid & 7;
    int ty = tid >> 3;

    int nk = (K + BK - 1) / BK;

    // async loaders: tile k0 -> buffer b
    auto loadA = [&](int b, int k0) {
        #pragma unroll
        for (int t = 0; t < 16; t++) {
            int li = tid + t * 128;
            int m = li >> 4, kk = li & 15;
            int r = r0 + m;
            bool ok = (r < rows);                  // k within lda (padded)
            const float* src = A + (size_t)(ok ? r : 0) * lda + k0 + kk;
            cpa4(s2u(&As[b][kk][m]), src, ok);
        }
    };
    auto loadB = [&](int b, int k0) {
        #pragma unroll
        for (int t = 0; t < 8; t++) {
            int li = tid + t * 128;
            int kk = li >> 6, n = li & 63;
            int k = k0 + kk, c = c0 + n;
            bool ok = (k < K && c < M);
            const float* src = W + (size_t)(ok ? k : 0) * M + (ok ? c : 0);
            cpa4(s2u(&Bs[b][kk][n]), src, ok);
        }
    };

    loadA(0, 0); loadB(0, 0); CP_COMMIT();

    unsigned long long acc[8][4];
    #pragma unroll
    for (int i = 0; i < 8; i++)
        #pragma unroll
        for (int j = 0; j < 4; j++) acc[i][j] = 0ULL;

    for (int it = 0; it < nk; it++) {
        int buf = it & 1;
        bool nx = (it + 1 < nk);
        if (nx) {
            loadA(buf ^ 1, (it + 1) * BK);
            loadB(buf ^ 1, (it + 1) * BK);
            CP_COMMIT();
            cp_wait<1>();
        } else {
            cp_wait<0>();
        }
        __syncthreads();
        #pragma unroll
        for (int kk = 0; kk < BK; kk++) {
            float4 b0 = *(const float4*)&Bs[buf][kk][tx * 8];
            float4 b1 = *(const float4*)&Bs[buf][kk][tx * 8 + 4];
            float4 a0 = *(const float4*)&As[buf][kk][ty * 8];
            float4 a1 = *(const float4*)&As[buf][kk][ty * 8 + 4];
            unsigned long long bp0 = pk2(b0.x, b0.y);
            unsigned long long bp1 = pk2(b0.z, b0.w);
            unsigned long long bp2 = pk2(b1.x, b1.y);
            unsigned long long bp3 = pk2(b1.z, b1.w);
            float av[8] = {a0.x, a0.y, a0.z, a0.w, a1.x, a1.y, a1.z, a1.w};
            #pragma unroll
            for (int i = 0; i < 8; i++) {
                unsigned long long ap = pk2(av[i], av[i]);
                fma2(acc[i][0], ap, bp0);
                fma2(acc[i][1], ap, bp1);
                fma2(acc[i][2], ap, bp2);
                fma2(acc[i][3], ap, bp3);
            }
        }
        __syncthreads();
    }

    #pragma unroll
    for (int i = 0; i < 8; i++) {
        int r = r0 + ty * 8 + i;
        if (r >= rows) continue;
        #pragma unroll
        for (int j = 0; j < 4; j++) {
            float lo, hi;
            upk2(acc[i][j], lo, hi);
            #pragma unroll
            for (int h = 0; h < 2; h++) {
                int c = c0 + tx * 8 + j * 2 + h;
                if (c >= M) continue;
                float v = (h ? hi : lo) + bias[c];
                if (mode == 1) v = fmaxf(v, 0.0f);
                else if (mode == 2) v = 1.0f / (1.0f + expf(-v));
                out[(size_t)r * ldc + c] = v;
            }
        }
    }
}

// ---------------------------------------------------------------------------
// Dual GEMM (mu/ls fused reparam), cp.async double-buffered. BM=64.
// ---------------------------------------------------------------------------
#define DBM 64
#define DAS_LD 68

__global__ __launch_bounds__(128, 4) void k_gemm_dual(
    const float* __restrict__ A, int lda,
    const float* __restrict__ W1, const float* __restrict__ W2,
    const float* __restrict__ b1, const float* __restrict__ b2,
    const float* __restrict__ eps, int lde,
    float* __restrict__ out, int ldc, int K, int M)
{
    __shared__ float As[2][BK][DAS_LD];
    __shared__ float B1s[2][BK][BN];
    __shared__ float B2s[2][BK][BN];
    int tid = threadIdx.x;
    int r0 = blockIdx.y * DBM;
    int c0 = blockIdx.x * BN;
    int tx = tid & 7;
    int ty = tid >> 3;

    int nk = (K + BK - 1) / BK;

    auto loadA = [&](int b, int k0) {
        #pragma unroll
        for (int t = 0; t < 8; t++) {
            int li = tid + t * 128;
            int m = li >> 4, kk = li & 15;
            int r = r0 + m;
            bool ok = (r < NNODES);
            const float* src = A + (size_t)(ok ? r : 0) * lda + k0 + kk;
            cpa4(s2u(&As[b][kk][m]), src, ok);
        }
    };
    auto loadB = [&](int b, int k0) {
        #pragma unroll
        for (int t = 0; t < 8; t++) {
            int li = tid + t * 128;
            int kk = li >> 6, n = li & 63;
            int k = k0 + kk, c = c0 + n;
            bool ok = (k < K && c < M);
            size_t off = (size_t)(ok ? k : 0) * M + (ok ? c : 0);
            cpa4(s2u(&B1s[b][kk][n]), W1 + off, ok);
            cpa4(s2u(&B2s[b][kk][n]), W2 + off, ok);
        }
    };

    loadA(0, 0); loadB(0, 0); CP_COMMIT();

    unsigned long long ac1[4][4], ac2[4][4];
    #pragma unroll
    for (int i = 0; i < 4; i++)
        #pragma unroll
        for (int j = 0; j < 4; j++) { ac1[i][j] = 0ULL; ac2[i][j] = 0ULL; }

    for (int it = 0; it < nk; it++) {
        int buf = it & 1;
        bool nx = (it + 1 < nk);
        if (nx) {
            loadA(buf ^ 1, (it + 1) * BK);
            loadB(buf ^ 1, (it + 1) * BK);
            CP_COMMIT();
            cp_wait<1>();
        } else {
            cp_wait<0>();
        }
        __syncthreads();
        #pragma unroll
        for (int kk = 0; kk < BK; kk++) {
            float4 x0 = *(const float4*)&B1s[buf][kk][tx * 8];
            float4 x1 = *(const float4*)&B1s[buf][kk][tx * 8 + 4];
            float4 y0 = *(const float4*)&B2s[buf][kk][tx * 8];
            float4 y1 = *(const float4*)&B2s[buf][kk][tx * 8 + 4];
            float4 a0 = *(const float4*)&As[buf][kk][ty * 4];
            unsigned long long bp1[4] = {pk2(x0.x, x0.y), pk2(x0.z, x0.w),
                                         pk2(x1.x, x1.y), pk2(x1.z, x1.w)};
            unsigned long long bp2[4] = {pk2(y0.x, y0.y), pk2(y0.z, y0.w),
                                         pk2(y1.x, y1.y), pk2(y1.z, y1.w)};
            float av[4] = {a0.x, a0.y, a0.z, a0.w};
            #pragma unroll
            for (int i = 0; i < 4; i++) {
                unsigned long long ap = pk2(av[i], av[i]);
                #pragma unroll
                for (int j = 0; j < 4; j++) {
                    fma2(ac1[i][j], ap, bp1[j]);
                    fma2(ac2[i][j], ap, bp2[j]);
                }
            }
        }
        __syncthreads();
    }

    #pragma unroll
    for (int i = 0; i < 4; i++) {
        int r = r0 + ty * 4 + i;
        if (r >= NNODES) continue;
        #pragma unroll
        for (int j = 0; j < 4; j++) {
            float mlo, mhi, llo, lhi;
            upk2(ac1[i][j], mlo, mhi);
            upk2(ac2[i][j], llo, lhi);
            #pragma unroll
            for (int h = 0; h < 2; h++) {
                int c = c0 + tx * 8 + j * 2 + h;
                if (c >= M) continue;
                float mu = (h ? mhi : mlo) + b1[c];
                float ls = (h ? lhi : llo) + b2[c];
                out[(size_t)r * ldc + c] =
                    mu + eps[(size_t)r * lde + c] * expf(ls) / 10.0f;
            }
        }
    }
}

// ---------------------------------------------------------------------------
// Host side
// ---------------------------------------------------------------------------
static void launch_prop(const float* in, float* P, int S) {
    int blocks = (NNODES + 7) / 8;
    switch (S) {
        case 96:  k_gather<96><<<blocks, 256>>>((const float4*)in, (float4*)P); break;
        case 128: k_gather<128><<<blocks, 256>>>((const float4*)in, (float4*)P); break;
        case 160: k_gather<160><<<blocks, 256>>>((const float4*)in, (float4*)P); break;
        case 192: k_gather<192><<<blocks, 256>>>((const float4*)in, (float4*)P); break;
    }
}

static void launch_gemm(const float* A, int lda, int K, const float* W,
                        const float* b, int M, int ldc, int mode, float* out) {
    dim3 grid((M + BN - 1) / BN, (NNODES + BM - 1) / BM);
    k_gemm<<<grid, 128>>>(A, lda, W, b, out, ldc, K, M, mode, NNODES);
}

static void launch_dual(const float* A, int lda, int K,
                        const float* W1, const float* W2,
                        const float* b1, const float* b2,
                        const float* eps, int lde, int M, int ldc, float* out) {
    dim3 grid((M + BN - 1) / BN, (NNODES + DBM - 1) / DBM);
    k_gemm_dual<<<grid, 128>>>(A, lda, W1, W2, b1, b2, eps, lde, out, ldc, K, M);
}

extern "C" void kernel_launch(void* const* d_in, const int* in_sizes, int n_in,
                              void* d_out, int out_size) {
    const float* x     = (const float*)d_in[0];
    const void*  ei    = d_in[1];
    const float* eps_e = (const float*)d_in[2];
    const float* eps_n = (const float*)d_in[3];
    const float* w1e = (const float*)d_in[4];  const float* b1e = (const float*)d_in[5];
    const float* w2e = (const float*)d_in[6];  const float* b2e = (const float*)d_in[7];
    const float* wme = (const float*)d_in[8];  const float* bme = (const float*)d_in[9];
    const float* wle = (const float*)d_in[10]; const float* ble = (const float*)d_in[11];
    const float* w4e = (const float*)d_in[12]; const float* b4e = (const float*)d_in[13];
    const float* w1n = (const float*)d_in[14]; const float* b1n = (const float*)d_in[15];
    const float* wmn = (const float*)d_in[16]; const float* bmn = (const float*)d_in[17];
    const float* wln = (const float*)d_in[18]; const float* bln = (const float*)d_in[19];
    const float* w5n = (const float*)d_in[20]; const float* b5n = (const float*)d_in[21];

    float* out   = (float*)d_out;
    float* edges = out;                         // [N,192]
    float* nodes = out + (size_t)NNODES * 192;  // [N,96]

    float *P, *bufA, *bufB;
    cudaGetSymbolAddress((void**)&P,    g_P);
    cudaGetSymbolAddress((void**)&bufA, g_bufA);
    cudaGetSymbolAddress((void**)&bufB, g_bufB);

    // ---- prep (launch #4 = FULL-GRID probe, production shape for ncu) ----
    k_prep1<<<(NNODES + 255) / 256, 256>>>();                 // #1
    k_detect<<<512, 256>>>((const unsigned*)ei);              // #2
    k_convert<<<(NEDGES + 255) / 256, 256>>>(ei);             // #3
    launch_gemm(x, 96, 96, w1e, b1e, 125, 128, 1, P);         // #4 PROBE (full shape; P overwritten)
    k_dinv<<<(NNODES + 255) / 256, 256>>>();                  // #5
    k_scanA<<<NBLK, 1024>>>();                                // #6
    k_scanB<<<1, 32>>>();                                     // #7
    k_scanC<<<NBLK, 1024>>>();                                // #8
    k_fill<<<(NEDGES + 255) / 256, 256>>>();                  // #9

    // ---- shared first propagation: P = Â x (stride 96) ----
    launch_prop(x, P, 96);
    launch_gemm(P, 96, 96, w1e, b1e, 125, 128, 1, bufA);      // e1 relu
    launch_gemm(P, 96, 96, w1n, b1n, 96,  96,  1, bufB);      // n1 relu

    // ---- edge branch ----
    launch_prop(bufA, P, 128);                                // C=125, stride 128
    launch_gemm(P, 128, 125, w2e, b2e, 144, 160, 1, bufA);    // e2 relu
    launch_prop(bufA, P, 160);                                // C=144, stride 160
    launch_dual(P, 160, 144, wme, wle, bme, ble, eps_e, 163, 163, 192, bufA);
    launch_prop(bufA, P, 192);                                // C=163, stride 192
    launch_gemm(P, 192, 163, w4e, b4e, 192, 192, 2, edges);   // sigmoid

    // ---- node branch ----
    launch_prop(bufB, P, 96);
    launch_dual(P, 96, 96, wmn, wln, bmn, bln, eps_n, 96, 96, 96, bufA);
    launch_prop(bufA, P, 96);
    launch_gemm(P, 96, 96, w5n, b5n, 96, 96, 1, nodes);       // relu
}

// round 10
// speedup vs baseline: 3.9601x; 1.5791x over previous
#include <cuda_runtime.h>
#include <cuda_fp16.h>
#include <math.h>
#include <cstdint>

#define NNODES 50000
#define NEDGES 800000
#define NBLK 13

// ---------------------------------------------------------------------------
// Scratch
// ---------------------------------------------------------------------------
__device__ __align__(16) __half g_Ahi[(size_t)NNODES * 192];
__device__ __align__(16) __half g_Alo[(size_t)NNODES * 192];
__device__ __align__(16) __half g_Whi[9][192 * 192];
__device__ __align__(16) __half g_Wlo[9][192 * 192];
__device__ float g_bufA[(size_t)NNODES * 192];
__device__ float g_bufB[(size_t)NNODES * 96];
__device__ float g_dinv[NNODES];
__device__ int   g_row[NEDGES];
__device__ int   g_col[NEDGES];
__device__ int   g_ideg[NNODES];
__device__ int   g_off[NNODES + 1];
__device__ int   g_cursor[NNODES];
__device__ int2  g_ecsr[NEDGES];
__device__ int   g_bsum[32];
__device__ int   g_bpre[32];
__device__ unsigned g_flag32;

// ---------------------------------------------------------------------------
// PTX helpers (all sm_103-safe, no "a" features)
// ---------------------------------------------------------------------------
__device__ __forceinline__ unsigned s2u(const void* p) {
    return (unsigned)__cvta_generic_to_shared(p);
}
__device__ __forceinline__ void cpa16(unsigned dst, const void* src, bool p) {
    asm volatile("cp.async.cg.shared.global [%0], [%1], 16, %2;"
                 :: "r"(dst), "l"(src), "r"(p ? 16 : 0));
}
#define CP_COMMIT() asm volatile("cp.async.commit_group;")
template <int N>
__device__ __forceinline__ void cp_wait() {
    asm volatile("cp.async.wait_group %0;" :: "n"(N) : "memory");
}
__device__ __forceinline__ uint32_t lds32(uint32_t a) {
    uint32_t v;
    asm volatile("ld.shared.b32 %0,[%1];" : "=r"(v) : "r"(a));
    return v;
}
// m16n8k16 row.col f16xf16 -> f32
__device__ __forceinline__ void mma16816(float* c, const uint32_t* a,
                                         const uint32_t* b) {
    asm volatile(
        "mma.sync.aligned.m16n8k16.row.col.f32.f16.f16.f32 "
        "{%0,%1,%2,%3}, {%4,%5,%6,%7}, {%8,%9}, {%0,%1,%2,%3};"
        : "+f"(c[0]), "+f"(c[1]), "+f"(c[2]), "+f"(c[3])
        : "r"(a[0]), "r"(a[1]), "r"(a[2]), "r"(a[3]), "r"(b[0]), "r"(b[1]));
}

// ---------------------------------------------------------------------------
// Prep kernels
// ---------------------------------------------------------------------------
__global__ void k_prep1() {
    int i = blockIdx.x * blockDim.x + threadIdx.x;
    if (i < NNODES) g_ideg[i] = 0;
    if (i == 0) g_flag32 = 0u;
}

__global__ void k_detect(const unsigned* __restrict__ w) {
    unsigned v = 0;
    for (int i = blockIdx.x * blockDim.x + threadIdx.x; i < NEDGES;
         i += gridDim.x * blockDim.x)
        v |= w[2 * i + 1];
    #pragma unroll
    for (int o = 16; o; o >>= 1) v |= __shfl_xor_sync(0xFFFFFFFFu, v, o);
    if ((threadIdx.x & 31) == 0 && v) atomicOr(&g_flag32, 1u);
}

__global__ void k_convert(const void* __restrict__ ei) {
    int e = blockIdx.x * blockDim.x + threadIdx.x;
    if (e >= NEDGES) return;
    int r, c;
    if (g_flag32 == 0u) {
        const long long* ll = (const long long*)ei;
        r = (int)ll[e];
        c = (int)ll[NEDGES + e];
    } else {
        const int* q = (const int*)ei;
        r = q[e];
        c = q[NEDGES + e];
    }
    g_row[e] = r;
    g_col[e] = c;
    atomicAdd(&g_ideg[c], 1);
}

__global__ void k_dinv() {
    int i = blockIdx.x * blockDim.x + threadIdx.x;
    if (i < NNODES) g_dinv[i] = rsqrtf((float)g_ideg[i] + 1.0f);
}

__global__ __launch_bounds__(1024) void k_scanA() {
    __shared__ int sh[32];
    int b = blockIdx.x, t = threadIdx.x;
    int base = b * 4096 + t * 4;
    int s = 0;
    #pragma unroll
    for (int j = 0; j < 4; j++) {
        int i = base + j;
        if (i < NNODES) s += g_ideg[i];
    }
    #pragma unroll
    for (int o = 16; o; o >>= 1) s += __shfl_xor_sync(0xFFFFFFFFu, s, o);
    if ((t & 31) == 0) sh[t >> 5] = s;
    __syncthreads();
    if (t < 32) {
        int x = sh[t];
        #pragma unroll
        for (int o = 16; o; o >>= 1) x += __shfl_xor_sync(0xFFFFFFFFu, x, o);
        if (t == 0) g_bsum[b] = x;
    }
}

__global__ void k_scanB() {
    int t = threadIdx.x;
    int v = (t < NBLK) ? g_bsum[t] : 0;
    int own = v;
    #pragma unroll
    for (int o = 1; o < 32; o <<= 1) {
        int u = __shfl_up_sync(0xFFFFFFFFu, v, o);
        if (t >= o) v += u;
    }
    if (t < NBLK) g_bpre[t] = v - own;
}

__global__ __launch_bounds__(1024) void k_scanC() {
    __shared__ int sh[1024];
    int b = blockIdx.x, t = threadIdx.x;
    int base = b * 4096 + t * 4;
    int v[4];
    int s = 0;
    #pragma unroll
    for (int j = 0; j < 4; j++) {
        int i = base + j;
        v[j] = (i < NNODES) ? g_ideg[i] : 0;
        s += v[j];
    }
    sh[t] = s;
    __syncthreads();
    #pragma unroll
    for (int o = 1; o < 1024; o <<= 1) {
        int tmp = (t >= o) ? sh[t - o] : 0;
        __syncthreads();
        sh[t] += tmp;
        __syncthreads();
    }
    int excl = sh[t] - s + g_bpre[b];
    #pragma unroll
    for (int j = 0; j < 4; j++) {
        int i = base + j;
        if (i < NNODES) { g_off[i] = excl; g_cursor[i] = excl; }
        excl += v[j];
    }
    if (b == 0 && t == 0) g_off[NNODES] = NEDGES;
}

__global__ void k_fill() {
    int e = blockIdx.x * blockDim.x + threadIdx.x;
    if (e >= NEDGES) return;
    int r = g_row[e], c = g_col[e];
    float cf = g_dinv[r] * g_dinv[c];
    int pos = atomicAdd(&g_cursor[c], 1);
    g_ecsr[pos] = make_int2(r, __float_as_int(cf));
}

// Weight transpose [k][n] -> [n][k] + fp16 split, padded 192x192 slab
__global__ void k_wsplit(const float* __restrict__ W,
                         __half* __restrict__ hi, __half* __restrict__ lo,
                         int K, int M) {
    int idx = blockIdx.x * blockDim.x + threadIdx.x;
    if (idx >= 192 * 192) return;
    int n = idx / 192, k = idx % 192;
    float v = (k < K && n < M) ? W[(size_t)k * M + n] : 0.0f;
    __half h = __float2half_rn(v);
    hi[idx] = h;
    lo[idx] = __float2half_rn(v - __half2float(h));
}

// ---------------------------------------------------------------------------
// Gather + fp16 split: out hi/lo [node, KPAD] half (zero-padded cols >= SIN)
// ---------------------------------------------------------------------------
__device__ __forceinline__ uint32_t hfp(float a, float b) {
    __half2 t;
    t.x = __float2half_rn(a);
    t.y = __float2half_rn(b);
    return *reinterpret_cast<uint32_t*>(&t);
}

template <int SIN, int KPAD>
__global__ __launch_bounds__(256) void k_gather(const float4* __restrict__ in4,
                                                uint2* __restrict__ hi,
                                                uint2* __restrict__ lo) {
    constexpr int NV4 = SIN / 4;
    constexpr int OV4 = KPAD / 4;
    constexpr int NIT = (OV4 + 31) / 32;
    int node = blockIdx.x * 8 + (threadIdx.x >> 5);
    if (node >= NNODES) return;
    int lane = threadIdx.x & 31;

    float d = g_dinv[node];
    float dd = d * d;

    float4 acc[NIT];
    #pragma unroll
    for (int v = 0; v < NIT; v++) {
        int id = lane + 32 * v;
        if (id < NV4) {
            float4 t = in4[(size_t)node * NV4 + id];
            acc[v] = make_float4(t.x * dd, t.y * dd, t.z * dd, t.w * dd);
        } else acc[v] = make_float4(0.f, 0.f, 0.f, 0.f);
    }

    int s = g_off[node];
    int e = g_off[node + 1];
    int i = s;
    for (; i + 3 < e; i += 4) {
        int2 p0 = g_ecsr[i];
        int2 p1 = g_ecsr[i + 1];
        int2 p2 = g_ecsr[i + 2];
        int2 p3 = g_ecsr[i + 3];
        float c0 = __int_as_float(p0.y), c1 = __int_as_float(p1.y);
        float c2 = __int_as_float(p2.y), c3 = __int_as_float(p3.y);
        #pragma unroll
        for (int v = 0; v < NIT; v++) {
            int id = lane + 32 * v;
            if (id < NV4) {
                float4 a0 = in4[(size_t)p0.x * NV4 + id];
                float4 a1 = in4[(size_t)p1.x * NV4 + id];
                float4 a2 = in4[(size_t)p2.x * NV4 + id];
                float4 a3 = in4[(size_t)p3.x * NV4 + id];
                acc[v].x += a0.x * c0; acc[v].y += a0.y * c0;
                acc[v].z += a0.z * c0; acc[v].w += a0.w * c0;
                acc[v].x += a1.x * c1; acc[v].y += a1.y * c1;
                acc[v].z += a1.z * c1; acc[v].w += a1.w * c1;
                acc[v].x += a2.x * c2; acc[v].y += a2.y * c2;
                acc[v].z += a2.z * c2; acc[v].w += a2.w * c2;
                acc[v].x += a3.x * c3; acc[v].y += a3.y * c3;
                acc[v].z += a3.z * c3; acc[v].w += a3.w * c3;
            }
        }
    }
    for (; i < e; i++) {
        int2 p = g_ecsr[i];
        float c0 = __int_as_float(p.y);
        #pragma unroll
        for (int v = 0; v < NIT; v++) {
            int id = lane + 32 * v;
            if (id < NV4) {
                float4 a = in4[(size_t)p.x * NV4 + id];
                acc[v].x += a.x * c0; acc[v].y += a.y * c0;
                acc[v].z += a.z * c0; acc[v].w += a.w * c0;
            }
        }
    }
    #pragma unroll
    for (int v = 0; v < NIT; v++) {
        int id = lane + 32 * v;
        if (id < OV4) {
            float4 a = acc[v];
            float hx = __half2float(__float2half_rn(a.x));
            float hy = __half2float(__float2half_rn(a.y));
            float hz = __half2float(__float2half_rn(a.z));
            float hw = __half2float(__float2half_rn(a.w));
            uint2 ph, pl;
            ph.x = hfp(a.x, a.y);
            ph.y = hfp(a.z, a.w);
            pl.x = hfp(a.x - hx, a.y - hy);
            pl.y = hfp(a.z - hz, a.w - hw);
            hi[(size_t)node * OV4 + id] = ph;
            lo[(size_t)node * OV4 + id] = pl;
        }
    }
}

// ---------------------------------------------------------------------------
// mma.sync GEMM: out[rows,ldc] = A @ W + bias (+relu/sigmoid), zero-pad cols.
// A split hi/lo [rows,kpad] fp16; W slab [n=192][k=192] fp16 (pre-transposed).
// Block 256 thr (8 warps), tile 128x64, warp tile 32x32, BK=32 double-buffered.
// D = Ahi@Bhi + Ahi@Blo + Alo@Bhi (f32 acc).
// ---------------------------------------------------------------------------
#define RS 80                 // smem row stride bytes (bank-conflict-free)
#define ASZ (128 * RS)        // 10240
#define BSZ (64 * RS)         // 5120

__global__ __launch_bounds__(256, 3) void k_mgemm(
    const __half* __restrict__ Ahi, const __half* __restrict__ Alo, int kpad,
    const __half* __restrict__ Wh, const __half* __restrict__ Wl,
    const float* __restrict__ bias, float* __restrict__ out, int ldc,
    int M, int nk, int mode, int rows)
{
    extern __shared__ char sm[];
    uint32_t base = s2u(sm);
    const int STRIDE = 2 * ASZ + 2 * BSZ;   // per buffer
    int tid = threadIdx.x;
    int wid = tid >> 5, lane = tid & 31;
    int g = lane >> 2, t = lane & 3;
    int wm = wid & 3, wn = wid >> 2;
    int r0 = blockIdx.y * 128;
    int c0 = blockIdx.x * 64;

    auto loadT = [&](int b, int k0) {
        uint32_t ba = base + b * STRIDE;
        #pragma unroll
        for (int i = 0; i < 2; i++) {
            int it = tid + i * 256;
            int m = it >> 2, c = it & 3;
            int gr = r0 + m;
            bool ok = (gr < rows);
            size_t so = (size_t)(ok ? gr : 0) * kpad + k0 + c * 8;
            uint32_t dd = ba + m * RS + c * 16;
            cpa16(dd, Ahi + so, ok);
            cpa16(dd + ASZ, Alo + so, ok);
        }
        {
            int n = tid >> 2, c = tid & 3;
            size_t so = (size_t)(c0 + n) * 192 + k0 + c * 8;
            uint32_t dd = ba + 2 * ASZ + n * RS + c * 16;
            cpa16(dd, Wh + so, true);
            cpa16(dd + BSZ, Wl + so, true);
        }
        CP_COMMIT();
    };

    loadT(0, 0);

    float acc[2][4][4];
    #pragma unroll
    for (int i = 0; i < 2; i++)
        #pragma unroll
        for (int j = 0; j < 4; j++)
            #pragma unroll
            for (int q = 0; q < 4; q++) acc[i][j][q] = 0.0f;

    for (int it = 0; it < nk; it++) {
        int b = it & 1;
        if (it + 1 < nk) { loadT(b ^ 1, (it + 1) * 32); cp_wait<1>(); }
        else cp_wait<0>();
        __syncthreads();
        uint32_t ba = base + b * STRIDE;
        uint32_t aB = ba + (wm * 32 + g) * RS + t * 4;
        uint32_t bB = ba + 2 * ASZ + (wn * 32 + g) * RS + t * 4;
        #pragma unroll
        for (int kc = 0; kc < 2; kc++) {
            uint32_t ah[2][4], al[2][4];
            #pragma unroll
            for (int ms = 0; ms < 2; ms++) {
                uint32_t a0 = aB + ms * (16 * RS) + kc * 32;
                ah[ms][0] = lds32(a0);
                ah[ms][1] = lds32(a0 + 8 * RS);
                ah[ms][2] = lds32(a0 + 16);
                ah[ms][3] = lds32(a0 + 8 * RS + 16);
                al[ms][0] = lds32(a0 + ASZ);
                al[ms][1] = lds32(a0 + ASZ + 8 * RS);
                al[ms][2] = lds32(a0 + ASZ + 16);
                al[ms][3] = lds32(a0 + ASZ + 8 * RS + 16);
            }
            #pragma unroll
            for (int ns = 0; ns < 4; ns++) {
                uint32_t b0 = bB + ns * (8 * RS) + kc * 32;
                uint32_t bh[2], bl[2];
                bh[0] = lds32(b0);
                bh[1] = lds32(b0 + 16);
                bl[0] = lds32(b0 + BSZ);
                bl[1] = lds32(b0 + BSZ + 16);
                #pragma unroll
                for (int ms = 0; ms < 2; ms++) {
                    mma16816(acc[ms][ns], ah[ms], bh);
                    mma16816(acc[ms][ns], ah[ms], bl);
                    mma16816(acc[ms][ns], al[ms], bh);
                }
            }
        }
        __syncthreads();
    }

    #pragma unroll
    for (int ms = 0; ms < 2; ms++) {
        #pragma unroll
        for (int h = 0; h < 2; h++) {
            int r = r0 + wm * 32 + ms * 16 + h * 8 + g;
            if (r >= rows) continue;
            #pragma unroll
            for (int ns = 0; ns < 4; ns++) {
                int cc = c0 + wn * 32 + ns * 8 + 2 * t;
                if (cc >= ldc) continue;
                float v0 = acc[ms][ns][h * 2 + 0];
                float v1 = acc[ms][ns][h * 2 + 1];
                if (cc < M) {
                    v0 += bias[cc];
                    if (mode == 1) v0 = fmaxf(v0, 0.0f);
                    else if (mode == 2) v0 = 1.0f / (1.0f + expf(-v0));
                } else v0 = 0.0f;
                if (cc + 1 < M) {
                    v1 += bias[cc + 1];
                    if (mode == 1) v1 = fmaxf(v1, 0.0f);
                    else if (mode == 2) v1 = 1.0f / (1.0f + expf(-v1));
                } else v1 = 0.0f;
                float2 st; st.x = v0; st.y = v1;
                *(float2*)(&out[(size_t)r * ldc + cc]) = st;
            }
        }
    }
}

// ---------------------------------------------------------------------------
// Dual mma.sync GEMM: mu = A@W1+b1, ls = A@W2+b2, out = mu + eps*exp(ls)/10
// ---------------------------------------------------------------------------
__global__ __launch_bounds__(256, 2) void k_mgemm_dual(
    const __half* __restrict__ Ahi, const __half* __restrict__ Alo, int kpad,
    const __half* __restrict__ W1h, const __half* __restrict__ W1l,
    const __half* __restrict__ W2h, const __half* __restrict__ W2l,
    const float* __restrict__ b1, const float* __restrict__ b2,
    const float* __restrict__ eps, int lde,
    float* __restrict__ out, int ldc, int M, int nk, int rows)
{
    extern __shared__ char sm[];
    uint32_t base = s2u(sm);
    const int STRIDE = 2 * ASZ + 4 * BSZ;
    int tid = threadIdx.x;
    int wid = tid >> 5, lane = tid & 31;
    int g = lane >> 2, t = lane & 3;
    int wm = wid & 3, wn = wid >> 2;
    int r0 = blockIdx.y * 128;
    int c0 = blockIdx.x * 64;

    auto loadT = [&](int b, int k0) {
        uint32_t ba = base + b * STRIDE;
        #pragma unroll
        for (int i = 0; i < 2; i++) {
            int it = tid + i * 256;
            int m = it >> 2, c = it & 3;
            int gr = r0 + m;
            bool ok = (gr < rows);
            size_t so = (size_t)(ok ? gr : 0) * kpad + k0 + c * 8;
            uint32_t dd = ba + m * RS + c * 16;
            cpa16(dd, Ahi + so, ok);
            cpa16(dd + ASZ, Alo + so, ok);
        }
        {
            int n = tid >> 2, c = tid & 3;
            size_t so = (size_t)(c0 + n) * 192 + k0 + c * 8;
            uint32_t dd = ba + 2 * ASZ + n * RS + c * 16;
            cpa16(dd, W1h + so, true);
            cpa16(dd + BSZ, W1l + so, true);
            cpa16(dd + 2 * BSZ, W2h + so, true);
            cpa16(dd + 3 * BSZ, W2l + so, true);
        }
        CP_COMMIT();
    };

    loadT(0, 0);

    float ac1[2][4][4], ac2[2][4][4];
    #pragma unroll
    for (int i = 0; i < 2; i++)
        #pragma unroll
        for (int j = 0; j < 4; j++)
            #pragma unroll
            for (int q = 0; q < 4; q++) { ac1[i][j][q] = 0.0f; ac2[i][j][q] = 0.0f; }

    for (int it = 0; it < nk; it++) {
        int b = it & 1;
        if (it + 1 < nk) { loadT(b ^ 1, (it + 1) * 32); cp_wait<1>(); }
        else cp_wait<0>();
        __syncthreads();
        uint32_t ba = base + b * STRIDE;
        uint32_t aB = ba + (wm * 32 + g) * RS + t * 4;
        uint32_t bB = ba + 2 * ASZ + (wn * 32 + g) * RS + t * 4;
        #pragma unroll
        for (int kc = 0; kc < 2; kc++) {
            uint32_t ah[2][4], al[2][4];
            #pragma unroll
            for (int ms = 0; ms < 2; ms++) {
                uint32_t a0 = aB + ms * (16 * RS) + kc * 32;
                ah[ms][0] = lds32(a0);
                ah[ms][1] = lds32(a0 + 8 * RS);
                ah[ms][2] = lds32(a0 + 16);
                ah[ms][3] = lds32(a0 + 8 * RS + 16);
                al[ms][0] = lds32(a0 + ASZ);
                al[ms][1] = lds32(a0 + ASZ + 8 * RS);
                al[ms][2] = lds32(a0 + ASZ + 16);
                al[ms][3] = lds32(a0 + ASZ + 8 * RS + 16);
            }
            #pragma unroll
            for (int ns = 0; ns < 4; ns++) {
                uint32_t b0 = bB + ns * (8 * RS) + kc * 32;
                uint32_t b1h[2], b1l[2], b2h[2], b2l[2];
                b1h[0] = lds32(b0);            b1h[1] = lds32(b0 + 16);
                b1l[0] = lds32(b0 + BSZ);      b1l[1] = lds32(b0 + BSZ + 16);
                b2h[0] = lds32(b0 + 2 * BSZ);  b2h[1] = lds32(b0 + 2 * BSZ + 16);
                b2l[0] = lds32(b0 + 3 * BSZ);  b2l[1] = lds32(b0 + 3 * BSZ + 16);
                #pragma unroll
                for (int ms = 0; ms < 2; ms++) {
                    mma16816(ac1[ms][ns], ah[ms], b1h);
                    mma16816(ac1[ms][ns], ah[ms], b1l);
                    mma16816(ac1[ms][ns], al[ms], b1h);
                    mma16816(ac2[ms][ns], ah[ms], b2h);
                    mma16816(ac2[ms][ns], ah[ms], b2l);
                    mma16816(ac2[ms][ns], al[ms], b2h);
                }
            }
        }
        __syncthreads();
    }

    #pragma unroll
    for (int ms = 0; ms < 2; ms++) {
        #pragma unroll
        for (int h = 0; h < 2; h++) {
            int r = r0 + wm * 32 + ms * 16 + h * 8 + g;
            if (r >= rows) continue;
            #pragma unroll
            for (int ns = 0; ns < 4; ns++) {
                int cc = c0 + wn * 32 + ns * 8 + 2 * t;
                if (cc >= ldc) continue;
                float v0 = 0.0f, v1 = 0.0f;
                if (cc < M) {
                    float mu = ac1[ms][ns][h * 2 + 0] + b1[cc];
                    float ls = ac2[ms][ns][h * 2 + 0] + b2[cc];
                    v0 = mu + eps[(size_t)r * lde + cc] * expf(ls) * 0.1f;
                }
                if (cc + 1 < M) {
                    float mu = ac1[ms][ns][h * 2 + 1] + b1[cc + 1];
                    float ls = ac2[ms][ns][h * 2 + 1] + b2[cc + 1];
                    v1 = mu + eps[(size_t)r * lde + cc + 1] * expf(ls) * 0.1f;
                }
                float2 st; st.x = v0; st.y = v1;
                *(float2*)(&out[(size_t)r * ldc + cc]) = st;
            }
        }
    }
}

// ---------------------------------------------------------------------------
// Host side
// ---------------------------------------------------------------------------
static __half *hAhi, *hAlo, *hWhi, *hWlo;
static float *hbufA, *hbufB;

static void launch_prop(const float* in, int SIN) {
    int blocks = (NNODES + 7) / 8;
    uint2* hi = (uint2*)hAhi;
    uint2* lo = (uint2*)hAlo;
    switch (SIN) {
        case 96:  k_gather<96, 128><<<blocks, 256>>>((const float4*)in, hi, lo); break;
        case 128: k_gather<128, 128><<<blocks, 256>>>((const float4*)in, hi, lo); break;
        case 160: k_gather<160, 192><<<blocks, 256>>>((const float4*)in, hi, lo); break;
        case 192: k_gather<192, 192><<<blocks, 256>>>((const float4*)in, hi, lo); break;
    }
}

static void mm(int kpad, int widx, int K, const float* bias, float* out,
               int ldc, int M, int mode) {
    int nk = (K + 31) / 32;
    dim3 grid((ldc + 63) / 64, (NNODES + 127) / 128);
    size_t smem = 2 * (2 * ASZ + 2 * BSZ);
    k_mgemm<<<grid, 256, smem>>>(hAhi, hAlo, kpad,
                                 hWhi + (size_t)widx * 192 * 192,
                                 hWlo + (size_t)widx * 192 * 192,
                                 bias, out, ldc, M, nk, mode, NNODES);
}

static void mmdual(int kpad, int w1, int w2, int K, const float* b1,
                   const float* b2, const float* eps, int lde, float* out,
                   int ldc, int M) {
    int nk = (K + 31) / 32;
    dim3 grid((ldc + 63) / 64, (NNODES + 127) / 128);
    size_t smem = 2 * (2 * ASZ + 4 * BSZ);
    k_mgemm_dual<<<grid, 256, smem>>>(hAhi, hAlo, kpad,
                                      hWhi + (size_t)w1 * 192 * 192,
                                      hWlo + (size_t)w1 * 192 * 192,
                                      hWhi + (size_t)w2 * 192 * 192,
                                      hWlo + (size_t)w2 * 192 * 192,
                                      b1, b2, eps, lde, out, ldc, M, nk, NNODES);
}

static void wsplit(const float* W, int widx, int K, int M) {
    k_wsplit<<<(192 * 192 + 255) / 256, 256>>>(
        W, hWhi + (size_t)widx * 192 * 192, hWlo + (size_t)widx * 192 * 192, K, M);
}

extern "C" void kernel_launch(void* const* d_in, const int* in_sizes, int n_in,
                              void* d_out, int out_size) {
    const float* x     = (const float*)d_in[0];
    const void*  ei    = d_in[1];
    const float* eps_e = (const float*)d_in[2];
    const float* eps_n = (const float*)d_in[3];
    const float* w1e = (const float*)d_in[4];  const float* b1e = (const float*)d_in[5];
    const float* w2e = (const float*)d_in[6];  const float* b2e = (const float*)d_in[7];
    const float* wme = (const float*)d_in[8];  const float* bme = (const float*)d_in[9];
    const float* wle = (const float*)d_in[10]; const float* ble = (const float*)d_in[11];
    const float* w4e = (const float*)d_in[12]; const float* b4e = (const float*)d_in[13];
    const float* w1n = (const float*)d_in[14]; const float* b1n = (const float*)d_in[15];
    const float* wmn = (const float*)d_in[16]; const float* bmn = (const float*)d_in[17];
    const float* wln = (const float*)d_in[18]; const float* bln = (const float*)d_in[19];
    const float* w5n = (const float*)d_in[20]; const float* b5n = (const float*)d_in[21];

    float* out   = (float*)d_out;
    float* edges = out;                         // [N,192]
    float* nodes = out + (size_t)NNODES * 192;  // [N,96]

    cudaGetSymbolAddress((void**)&hAhi, g_Ahi);
    cudaGetSymbolAddress((void**)&hAlo, g_Alo);
    cudaGetSymbolAddress((void**)&hWhi, g_Whi);
    cudaGetSymbolAddress((void**)&hWlo, g_Wlo);
    cudaGetSymbolAddress((void**)&hbufA, g_bufA);
    cudaGetSymbolAddress((void**)&hbufB, g_bufB);

    cudaFuncSetAttribute(k_mgemm, cudaFuncAttributeMaxDynamicSharedMemorySize,
                         (int)(2 * (2 * ASZ + 2 * BSZ)));
    cudaFuncSetAttribute(k_mgemm_dual,
                         cudaFuncAttributeMaxDynamicSharedMemorySize,
                         (int)(2 * (2 * ASZ + 4 * BSZ)));

    // ---- prep (#4 = full-shape MMA probe for ncu; output overwritten later) --
    k_prep1<<<(NNODES + 255) / 256, 256>>>();                 // #1
    k_detect<<<512, 256>>>((const unsigned*)ei);              // #2
    k_convert<<<(NEDGES + 255) / 256, 256>>>(ei);             // #3
    mm(128, 0, 96, b1e, hbufA, 128, 125, 1);                  // #4 PROBE
    k_dinv<<<(NNODES + 255) / 256, 256>>>();                  // #5
    k_scanA<<<NBLK, 1024>>>();                                // #6
    k_scanB<<<1, 32>>>();                                     // #7
    k_scanC<<<NBLK, 1024>>>();                                // #8
    k_fill<<<(NEDGES + 255) / 256, 256>>>();                  // #9
    wsplit(w1e, 0, 96, 125);
    wsplit(w2e, 1, 125, 144);
    wsplit(wme, 2, 144, 163);
    wsplit(wle, 3, 144, 163);
    wsplit(w4e, 4, 163, 192);
    wsplit(w1n, 5, 96, 96);
    wsplit(wmn, 6, 96, 96);
    wsplit(wln, 7, 96, 96);
    wsplit(w5n, 8, 96, 96);

    // ---- shared first propagation: split(Â x), kpad 128 ----
    launch_prop(x, 96);
    mm(128, 0, 96, b1e, hbufA, 128, 125, 1);                  // e1 relu
    mm(128, 5, 96, b1n, hbufB, 96, 96, 1);                    // n1 relu

    // ---- edge branch ----
    launch_prop(hbufA, 128);                                  // C=125, kpad 128
    mm(128, 1, 125, b2e, hbufA, 160, 144, 1);                 // e2 relu
    launch_prop(hbufA, 160);                                  // C=144, kpad 192
    mmdual(192, 2, 3, 144, bme, ble, eps_e, 163, hbufA, 192, 163);
    launch_prop(hbufA, 192);                                  // C=163, kpad 192
    mm(192, 4, 163, b4e, edges, 192, 192, 2);                 // sigmoid

    // ---- node branch ----
    launch_prop(hbufB, 96);
    mmdual(128, 6, 7, 96, bmn, bln, eps_n, 96, hbufA, 96, 96);
    launch_prop(hbufA, 96);
    mm(128, 8, 96, b5n, nodes, 96, 96, 1);                    // relu
}

// round 11
// speedup vs baseline: 4.0993x; 1.0352x over previous
#include <cuda_runtime.h>
#include <cuda_fp16.h>
#include <math.h>
#include <cstdint>

#define NNODES 50000
#define NEDGES 800000
#define NBLK 13

// ---------------------------------------------------------------------------
// Scratch
// ---------------------------------------------------------------------------
__device__ __align__(16) __half g_Ahi[(size_t)NNODES * 192];
__device__ __align__(16) __half g_Alo[(size_t)NNODES * 192];
__device__ __align__(16) __half g_Whi[9][192 * 192];
__device__ __align__(16) __half g_Wlo[9][192 * 192];
__device__ float g_bufA[(size_t)NNODES * 192];
__device__ float g_bufB[(size_t)NNODES * 128];
__device__ float g_dinv[NNODES];
__device__ int   g_row[NEDGES];
__device__ int   g_col[NEDGES];
__device__ int   g_ideg[NNODES];
__device__ int   g_off[NNODES + 1];
__device__ int   g_cursor[NNODES];
__device__ int2  g_ecsr[NEDGES];
__device__ int   g_bsum[32];
__device__ int   g_bpre[32];
__device__ unsigned g_flag32;

// ---------------------------------------------------------------------------
// PTX helpers (sm_103-safe, no "a" features)
// ---------------------------------------------------------------------------
__device__ __forceinline__ unsigned s2u(const void* p) {
    return (unsigned)__cvta_generic_to_shared(p);
}
__device__ __forceinline__ void cpa16(unsigned dst, const void* src, bool p) {
    asm volatile("cp.async.cg.shared.global [%0], [%1], 16, %2;"
                 :: "r"(dst), "l"(src), "r"(p ? 16 : 0));
}
#define CP_COMMIT() asm volatile("cp.async.commit_group;")
template <int N>
__device__ __forceinline__ void cp_wait() {
    asm volatile("cp.async.wait_group %0;" :: "n"(N) : "memory");
}
__device__ __forceinline__ uint32_t lds32(uint32_t a) {
    uint32_t v;
    asm volatile("ld.shared.b32 %0,[%1];" : "=r"(v) : "r"(a));
    return v;
}
__device__ __forceinline__ void mma16816(float* c, const uint32_t* a,
                                         const uint32_t* b) {
    asm volatile(
        "mma.sync.aligned.m16n8k16.row.col.f32.f16.f16.f32 "
        "{%0,%1,%2,%3}, {%4,%5,%6,%7}, {%8,%9}, {%0,%1,%2,%3};"
        : "+f"(c[0]), "+f"(c[1]), "+f"(c[2]), "+f"(c[3])
        : "r"(a[0]), "r"(a[1]), "r"(a[2]), "r"(a[3]), "r"(b[0]), "r"(b[1]));
}

// ---------------------------------------------------------------------------
// Prep kernels
// ---------------------------------------------------------------------------
__global__ void k_prep1() {
    int i = blockIdx.x * blockDim.x + threadIdx.x;
    if (i < NNODES) g_ideg[i] = 0;
    if (i == 0) g_flag32 = 0u;
}

__global__ void k_detect(const unsigned* __restrict__ w) {
    unsigned v = 0;
    for (int i = blockIdx.x * blockDim.x + threadIdx.x; i < NEDGES;
         i += gridDim.x * blockDim.x)
        v |= w[2 * i + 1];
    #pragma unroll
    for (int o = 16; o; o >>= 1) v |= __shfl_xor_sync(0xFFFFFFFFu, v, o);
    if ((threadIdx.x & 31) == 0 && v) atomicOr(&g_flag32, 1u);
}

__global__ void k_convert(const void* __restrict__ ei) {
    int e = blockIdx.x * blockDim.x + threadIdx.x;
    if (e >= NEDGES) return;
    int r, c;
    if (g_flag32 == 0u) {
        const long long* ll = (const long long*)ei;
        r = (int)ll[e];
        c = (int)ll[NEDGES + e];
    } else {
        const int* q = (const int*)ei;
        r = q[e];
        c = q[NEDGES + e];
    }
    g_row[e] = r;
    g_col[e] = c;
    atomicAdd(&g_ideg[c], 1);
}

__global__ void k_dinv() {
    int i = blockIdx.x * blockDim.x + threadIdx.x;
    if (i < NNODES) g_dinv[i] = rsqrtf((float)g_ideg[i] + 1.0f);
}

__global__ __launch_bounds__(1024) void k_scanA() {
    __shared__ int sh[32];
    int b = blockIdx.x, t = threadIdx.x;
    int base = b * 4096 + t * 4;
    int s = 0;
    #pragma unroll
    for (int j = 0; j < 4; j++) {
        int i = base + j;
        if (i < NNODES) s += g_ideg[i];
    }
    #pragma unroll
    for (int o = 16; o; o >>= 1) s += __shfl_xor_sync(0xFFFFFFFFu, s, o);
    if ((t & 31) == 0) sh[t >> 5] = s;
    __syncthreads();
    if (t < 32) {
        int x = sh[t];
        #pragma unroll
        for (int o = 16; o; o >>= 1) x += __shfl_xor_sync(0xFFFFFFFFu, x, o);
        if (t == 0) g_bsum[b] = x;
    }
}

__global__ void k_scanB() {
    int t = threadIdx.x;
    int v = (t < NBLK) ? g_bsum[t] : 0;
    int own = v;
    #pragma unroll
    for (int o = 1; o < 32; o <<= 1) {
        int u = __shfl_up_sync(0xFFFFFFFFu, v, o);
        if (t >= o) v += u;
    }
    if (t < NBLK) g_bpre[t] = v - own;
}

__global__ __launch_bounds__(1024) void k_scanC() {
    __shared__ int sh[1024];
    int b = blockIdx.x, t = threadIdx.x;
    int base = b * 4096 + t * 4;
    int v[4];
    int s = 0;
    #pragma unroll
    for (int j = 0; j < 4; j++) {
        int i = base + j;
        v[j] = (i < NNODES) ? g_ideg[i] : 0;
        s += v[j];
    }
    sh[t] = s;
    __syncthreads();
    #pragma unroll
    for (int o = 1; o < 1024; o <<= 1) {
        int tmp = (t >= o) ? sh[t - o] : 0;
        __syncthreads();
        sh[t] += tmp;
        __syncthreads();
    }
    int excl = sh[t] - s + g_bpre[b];
    #pragma unroll
    for (int j = 0; j < 4; j++) {
        int i = base + j;
        if (i < NNODES) { g_off[i] = excl; g_cursor[i] = excl; }
        excl += v[j];
    }
    if (b == 0 && t == 0) g_off[NNODES] = NEDGES;
}

__global__ void k_fill() {
    int e = blockIdx.x * blockDim.x + threadIdx.x;
    if (e >= NEDGES) return;
    int r = g_row[e], c = g_col[e];
    float cf = g_dinv[r] * g_dinv[c];
    int pos = atomicAdd(&g_cursor[c], 1);
    g_ecsr[pos] = make_int2(r, __float_as_int(cf));
}

// All 9 weight transposes + fp16 splits in ONE launch (blockIdx.y = slab).
struct WSet { const float* w[9]; int K[9]; int M[9]; };
__global__ void k_wsplit_all(WSet ws, __half* __restrict__ hiB,
                             __half* __restrict__ loB) {
    int slab = blockIdx.y;
    int idx = blockIdx.x * blockDim.x + threadIdx.x;
    if (idx >= 192 * 192) return;
    int n = idx / 192, k = idx % 192;
    int K = ws.K[slab], M = ws.M[slab];
    float v = (k < K && n < M) ? ws.w[slab][(size_t)k * M + n] : 0.0f;
    __half h = __float2half_rn(v);
    size_t o = (size_t)slab * 192 * 192 + idx;
    hiB[o] = h;
    loB[o] = __float2half_rn(v - __half2float(h));
}

// Pad x [N,96] -> bufA [N,128] (zero cols 96..127)
__global__ void k_padx(const float* __restrict__ x, float* __restrict__ o) {
    int i = blockIdx.x * blockDim.x + threadIdx.x;
    if (i >= NNODES * 128) return;
    int n = i >> 7, c = i & 127;
    o[i] = (c < 96) ? x[n * 96 + c] : 0.0f;
}

// ---------------------------------------------------------------------------
// Gather + fp16 split: SIN == KPAD always (padded inputs), full-warp lanes.
// ---------------------------------------------------------------------------
__device__ __forceinline__ uint32_t hfp(float a, float b) {
    __half2 t;
    t.x = __float2half_rn(a);
    t.y = __float2half_rn(b);
    return *reinterpret_cast<uint32_t*>(&t);
}

template <int SIN, int KPAD>
__global__ __launch_bounds__(256) void k_gather(const float4* __restrict__ in4,
                                                uint2* __restrict__ hi,
                                                uint2* __restrict__ lo) {
    constexpr int NV4 = SIN / 4;
    constexpr int OV4 = KPAD / 4;
    constexpr int NIT = (OV4 + 31) / 32;
    int node = blockIdx.x * 8 + (threadIdx.x >> 5);
    if (node >= NNODES) return;
    int lane = threadIdx.x & 31;

    float d = g_dinv[node];
    float dd = d * d;

    float4 acc[NIT];
    #pragma unroll
    for (int v = 0; v < NIT; v++) {
        int id = lane + 32 * v;
        if (id < NV4) {
            float4 t = in4[(size_t)node * NV4 + id];
            acc[v] = make_float4(t.x * dd, t.y * dd, t.z * dd, t.w * dd);
        } else acc[v] = make_float4(0.f, 0.f, 0.f, 0.f);
    }

    int s = g_off[node];
    int e = g_off[node + 1];
    int i = s;
    for (; i + 3 < e; i += 4) {
        int2 p0 = g_ecsr[i];
        int2 p1 = g_ecsr[i + 1];
        int2 p2 = g_ecsr[i + 2];
        int2 p3 = g_ecsr[i + 3];
        float c0 = __int_as_float(p0.y), c1 = __int_as_float(p1.y);
        float c2 = __int_as_float(p2.y), c3 = __int_as_float(p3.y);
        #pragma unroll
        for (int v = 0; v < NIT; v++) {
            int id = lane + 32 * v;
            if (id < NV4) {
                float4 a0 = in4[(size_t)p0.x * NV4 + id];
                float4 a1 = in4[(size_t)p1.x * NV4 + id];
                float4 a2 = in4[(size_t)p2.x * NV4 + id];
                float4 a3 = in4[(size_t)p3.x * NV4 + id];
                acc[v].x += a0.x * c0; acc[v].y += a0.y * c0;
                acc[v].z += a0.z * c0; acc[v].w += a0.w * c0;
                acc[v].x += a1.x * c1; acc[v].y += a1.y * c1;
                acc[v].z += a1.z * c1; acc[v].w += a1.w * c1;
                acc[v].x += a2.x * c2; acc[v].y += a2.y * c2;
                acc[v].z += a2.z * c2; acc[v].w += a2.w * c2;
                acc[v].x += a3.x * c3; acc[v].y += a3.y * c3;
                acc[v].z += a3.z * c3; acc[v].w += a3.w * c3;
            }
        }
    }
    for (; i < e; i++) {
        int2 p = g_ecsr[i];
        float c0 = __int_as_float(p.y);
        #pragma unroll
        for (int v = 0; v < NIT; v++) {
            int id = lane + 32 * v;
            if (id < NV4) {
                float4 a = in4[(size_t)p.x * NV4 + id];
                acc[v].x += a.x * c0; acc[v].y += a.y * c0;
                acc[v].z += a.z * c0; acc[v].w += a.w * c0;
            }
        }
    }
    #pragma unroll
    for (int v = 0; v < NIT; v++) {
        int id = lane + 32 * v;
        if (id < OV4) {
            float4 a = acc[v];
            float hx = __half2float(__float2half_rn(a.x));
            float hy = __half2float(__float2half_rn(a.y));
            float hz = __half2float(__float2half_rn(a.z));
            float hw = __half2float(__float2half_rn(a.w));
            uint2 ph, pl;
            ph.x = hfp(a.x, a.y);
            ph.y = hfp(a.z, a.w);
            pl.x = hfp(a.x - hx, a.y - hy);
            pl.y = hfp(a.z - hz, a.w - hw);
            hi[(size_t)node * OV4 + id] = ph;
            lo[(size_t)node * OV4 + id] = pl;
        }
    }
}

// ---------------------------------------------------------------------------
// mma.sync GEMM (as R10): block 256 thr, tile 128x64, warp 32x32, BK=32 2-buf
// ---------------------------------------------------------------------------
#define RS 80
#define ASZ (128 * RS)
#define BSZ (64 * RS)

__global__ __launch_bounds__(256, 3) void k_mgemm(
    const __half* __restrict__ Ahi, const __half* __restrict__ Alo, int kpad,
    const __half* __restrict__ Wh, const __half* __restrict__ Wl,
    const float* __restrict__ bias, float* __restrict__ out, int ldc,
    int M, int nk, int mode, int rows)
{
    extern __shared__ char sm[];
    uint32_t base = s2u(sm);
    const int STRIDE = 2 * ASZ + 2 * BSZ;
    int tid = threadIdx.x;
    int wid = tid >> 5, lane = tid & 31;
    int g = lane >> 2, t = lane & 3;
    int wm = wid & 3, wn = wid >> 2;
    int r0 = blockIdx.y * 128;
    int c0 = blockIdx.x * 64;

    auto loadT = [&](int b, int k0) {
        uint32_t ba = base + b * STRIDE;
        #pragma unroll
        for (int i = 0; i < 2; i++) {
            int it = tid + i * 256;
            int m = it >> 2, c = it & 3;
            int gr = r0 + m;
            bool ok = (gr < rows);
            size_t so = (size_t)(ok ? gr : 0) * kpad + k0 + c * 8;
            uint32_t dd = ba + m * RS + c * 16;
            cpa16(dd, Ahi + so, ok);
            cpa16(dd + ASZ, Alo + so, ok);
        }
        {
            int n = tid >> 2, c = tid & 3;
            size_t so = (size_t)(c0 + n) * 192 + k0 + c * 8;
            uint32_t dd = ba + 2 * ASZ + n * RS + c * 16;
            cpa16(dd, Wh + so, true);
            cpa16(dd + BSZ, Wl + so, true);
        }
        CP_COMMIT();
    };

    loadT(0, 0);

    float acc[2][4][4];
    #pragma unroll
    for (int i = 0; i < 2; i++)
        #pragma unroll
        for (int j = 0; j < 4; j++)
            #pragma unroll
            for (int q = 0; q < 4; q++) acc[i][j][q] = 0.0f;

    for (int it = 0; it < nk; it++) {
        int b = it & 1;
        if (it + 1 < nk) { loadT(b ^ 1, (it + 1) * 32); cp_wait<1>(); }
        else cp_wait<0>();
        __syncthreads();
        uint32_t ba = base + b * STRIDE;
        uint32_t aB = ba + (wm * 32 + g) * RS + t * 4;
        uint32_t bB = ba + 2 * ASZ + (wn * 32 + g) * RS + t * 4;
        #pragma unroll
        for (int kc = 0; kc < 2; kc++) {
            uint32_t ah[2][4], al[2][4];
            #pragma unroll
            for (int ms = 0; ms < 2; ms++) {
                uint32_t a0 = aB + ms * (16 * RS) + kc * 32;
                ah[ms][0] = lds32(a0);
                ah[ms][1] = lds32(a0 + 8 * RS);
                ah[ms][2] = lds32(a0 + 16);
                ah[ms][3] = lds32(a0 + 8 * RS + 16);
                al[ms][0] = lds32(a0 + ASZ);
                al[ms][1] = lds32(a0 + ASZ + 8 * RS);
                al[ms][2] = lds32(a0 + ASZ + 16);
                al[ms][3] = lds32(a0 + ASZ + 8 * RS + 16);
            }
            #pragma unroll
            for (int ns = 0; ns < 4; ns++) {
                uint32_t b0 = bB + ns * (8 * RS) + kc * 32;
                uint32_t bh[2], bl[2];
                bh[0] = lds32(b0);
                bh[1] = lds32(b0 + 16);
                bl[0] = lds32(b0 + BSZ);
                bl[1] = lds32(b0 + BSZ + 16);
                #pragma unroll
                for (int ms = 0; ms < 2; ms++) {
                    mma16816(acc[ms][ns], ah[ms], bh);
                    mma16816(acc[ms][ns], ah[ms], bl);
                    mma16816(acc[ms][ns], al[ms], bh);
                }
            }
        }
        __syncthreads();
    }

    #pragma unroll
    for (int ms = 0; ms < 2; ms++) {
        #pragma unroll
        for (int h = 0; h < 2; h++) {
            int r = r0 + wm * 32 + ms * 16 + h * 8 + g;
            if (r >= rows) continue;
            #pragma unroll
            for (int ns = 0; ns < 4; ns++) {
                int cc = c0 + wn * 32 + ns * 8 + 2 * t;
                if (cc >= ldc) continue;
                float v0 = acc[ms][ns][h * 2 + 0];
                float v1 = acc[ms][ns][h * 2 + 1];
                if (cc < M) {
                    v0 += bias[cc];
                    if (mode == 1) v0 = fmaxf(v0, 0.0f);
                    else if (mode == 2) v0 = 1.0f / (1.0f + expf(-v0));
                } else v0 = 0.0f;
                if (cc + 1 < M) {
                    v1 += bias[cc + 1];
                    if (mode == 1) v1 = fmaxf(v1, 0.0f);
                    else if (mode == 2) v1 = 1.0f / (1.0f + expf(-v1));
                } else v1 = 0.0f;
                float2 st; st.x = v0; st.y = v1;
                *(float2*)(&out[(size_t)r * ldc + cc]) = st;
            }
        }
    }
}

// ---------------------------------------------------------------------------
// Dual mma.sync GEMM: out = mu + eps*exp(ls)/10
// ---------------------------------------------------------------------------
__global__ __launch_bounds__(256, 2) void k_mgemm_dual(
    const __half* __restrict__ Ahi, const __half* __restrict__ Alo, int kpad,
    const __half* __restrict__ W1h, const __half* __restrict__ W1l,
    const __half* __restrict__ W2h, const __half* __restrict__ W2l,
    const float* __restrict__ b1, const float* __restrict__ b2,
    const float* __restrict__ eps, int lde,
    float* __restrict__ out, int ldc, int M, int nk, int rows)
{
    extern __shared__ char sm[];
    uint32_t base = s2u(sm);
    const int STRIDE = 2 * ASZ + 4 * BSZ;
    int tid = threadIdx.x;
    int wid = tid >> 5, lane = tid & 31;
    int g = lane >> 2, t = lane & 3;
    int wm = wid & 3, wn = wid >> 2;
    int r0 = blockIdx.y * 128;
    int c0 = blockIdx.x * 64;

    auto loadT = [&](int b, int k0) {
        uint32_t ba = base + b * STRIDE;
        #pragma unroll
        for (int i = 0; i < 2; i++) {
            int it = tid + i * 256;
            int m = it >> 2, c = it & 3;
            int gr = r0 + m;
            bool ok = (gr < rows);
            size_t so = (size_t)(ok ? gr : 0) * kpad + k0 + c * 8;
            uint32_t dd = ba + m * RS + c * 16;
            cpa16(dd, Ahi + so, ok);
            cpa16(dd + ASZ, Alo + so, ok);
        }
        {
            int n = tid >> 2, c = tid & 3;
            size_t so = (size_t)(c0 + n) * 192 + k0 + c * 8;
            uint32_t dd = ba + 2 * ASZ + n * RS + c * 16;
            cpa16(dd, W1h + so, true);
            cpa16(dd + BSZ, W1l + so, true);
            cpa16(dd + 2 * BSZ, W2h + so, true);
            cpa16(dd + 3 * BSZ, W2l + so, true);
        }
        CP_COMMIT();
    };

    loadT(0, 0);

    float ac1[2][4][4], ac2[2][4][4];
    #pragma unroll
    for (int i = 0; i < 2; i++)
        #pragma unroll
        for (int j = 0; j < 4; j++)
            #pragma unroll
            for (int q = 0; q < 4; q++) { ac1[i][j][q] = 0.0f; ac2[i][j][q] = 0.0f; }

    for (int it = 0; it < nk; it++) {
        int b = it & 1;
        if (it + 1 < nk) { loadT(b ^ 1, (it + 1) * 32); cp_wait<1>(); }
        else cp_wait<0>();
        __syncthreads();
        uint32_t ba = base + b * STRIDE;
        uint32_t aB = ba + (wm * 32 + g) * RS + t * 4;
        uint32_t bB = ba + 2 * ASZ + (wn * 32 + g) * RS + t * 4;
        #pragma unroll
        for (int kc = 0; kc < 2; kc++) {
            uint32_t ah[2][4], al[2][4];
            #pragma unroll
            for (int ms = 0; ms < 2; ms++) {
                uint32_t a0 = aB + ms * (16 * RS) + kc * 32;
                ah[ms][0] = lds32(a0);
                ah[ms][1] = lds32(a0 + 8 * RS);
                ah[ms][2] = lds32(a0 + 16);
                ah[ms][3] = lds32(a0 + 8 * RS + 16);
                al[ms][0] = lds32(a0 + ASZ);
                al[ms][1] = lds32(a0 + ASZ + 8 * RS);
                al[ms][2] = lds32(a0 + ASZ + 16);
                al[ms][3] = lds32(a0 + ASZ + 8 * RS + 16);
            }
            #pragma unroll
            for (int ns = 0; ns < 4; ns++) {
                uint32_t b0 = bB + ns * (8 * RS) + kc * 32;
                uint32_t b1h[2], b1l[2], b2h[2], b2l[2];
                b1h[0] = lds32(b0);            b1h[1] = lds32(b0 + 16);
                b1l[0] = lds32(b0 + BSZ);      b1l[1] = lds32(b0 + BSZ + 16);
                b2h[0] = lds32(b0 + 2 * BSZ);  b2h[1] = lds32(b0 + 2 * BSZ + 16);
                b2l[0] = lds32(b0 + 3 * BSZ);  b2l[1] = lds32(b0 + 3 * BSZ + 16);
                #pragma unroll
                for (int ms = 0; ms < 2; ms++) {
                    mma16816(ac1[ms][ns], ah[ms], b1h);
                    mma16816(ac1[ms][ns], ah[ms], b1l);
                    mma16816(ac1[ms][ns], al[ms], b1h);
                    mma16816(ac2[ms][ns], ah[ms], b2h);
                    mma16816(ac2[ms][ns], ah[ms], b2l);
                    mma16816(ac2[ms][ns], al[ms], b2h);
                }
            }
        }
        __syncthreads();
    }

    #pragma unroll
    for (int ms = 0; ms < 2; ms++) {
        #pragma unroll
        for (int h = 0; h < 2; h++) {
            int r = r0 + wm * 32 + ms * 16 + h * 8 + g;
            if (r >= rows) continue;
            #pragma unroll
            for (int ns = 0; ns < 4; ns++) {
                int cc = c0 + wn * 32 + ns * 8 + 2 * t;
                if (cc >= ldc) continue;
                float v0 = 0.0f, v1 = 0.0f;
                if (cc < M) {
                    float mu = ac1[ms][ns][h * 2 + 0] + b1[cc];
                    float ls = ac2[ms][ns][h * 2 + 0] + b2[cc];
                    v0 = mu + eps[(size_t)r * lde + cc] * expf(ls) * 0.1f;
                }
                if (cc + 1 < M) {
                    float mu = ac1[ms][ns][h * 2 + 1] + b1[cc + 1];
                    float ls = ac2[ms][ns][h * 2 + 1] + b2[cc + 1];
                    v1 = mu + eps[(size_t)r * lde + cc + 1] * expf(ls) * 0.1f;
                }
                float2 st; st.x = v0; st.y = v1;
                *(float2*)(&out[(size_t)r * ldc + cc]) = st;
            }
        }
    }
}

// ---------------------------------------------------------------------------
// Host side
// ---------------------------------------------------------------------------
static __half *hAhi, *hAlo, *hWhi, *hWlo;
static float *hbufA, *hbufB;

static void launch_prop(const float* in, int SIN) {
    int blocks = (NNODES + 7) / 8;
    uint2* hi = (uint2*)hAhi;
    uint2* lo = (uint2*)hAlo;
    switch (SIN) {
        case 128: k_gather<128, 128><<<blocks, 256>>>((const float4*)in, hi, lo); break;
        case 160: k_gather<160, 192><<<blocks, 256>>>((const float4*)in, hi, lo); break;
        case 192: k_gather<192, 192><<<blocks, 256>>>((const float4*)in, hi, lo); break;
    }
}

static void mm(int kpad, int widx, int K, const float* bias, float* out,
               int ldc, int M, int mode) {
    int nk = (K + 31) / 32;
    dim3 grid((ldc + 63) / 64, (NNODES + 127) / 128);
    size_t smem = 2 * (2 * ASZ + 2 * BSZ);
    k_mgemm<<<grid, 256, smem>>>(hAhi, hAlo, kpad,
                                 hWhi + (size_t)widx * 192 * 192,
                                 hWlo + (size_t)widx * 192 * 192,
                                 bias, out, ldc, M, nk, mode, NNODES);
}

static void mmdual(int kpad, int w1, int w2, int K, const float* b1,
                   const float* b2, const float* eps, int lde, float* out,
                   int ldc, int M) {
    int nk = (K + 31) / 32;
    dim3 grid((ldc + 63) / 64, (NNODES + 127) / 128);
    size_t smem = 2 * (2 * ASZ + 4 * BSZ);
    k_mgemm_dual<<<grid, 256, smem>>>(hAhi, hAlo, kpad,
                                      hWhi + (size_t)w1 * 192 * 192,
                                      hWlo + (size_t)w1 * 192 * 192,
                                      hWhi + (size_t)w2 * 192 * 192,
                                      hWlo + (size_t)w2 * 192 * 192,
                                      b1, b2, eps, lde, out, ldc, M, nk, NNODES);
}

extern "C" void kernel_launch(void* const* d_in, const int* in_sizes, int n_in,
                              void* d_out, int out_size) {
    const float* x     = (const float*)d_in[0];
    const void*  ei    = d_in[1];
    const float* eps_e = (const float*)d_in[2];
    const float* eps_n = (const float*)d_in[3];
    const float* w1e = (const float*)d_in[4];  const float* b1e = (const float*)d_in[5];
    const float* w2e = (const float*)d_in[6];  const float* b2e = (const float*)d_in[7];
    const float* wme = (const float*)d_in[8];  const float* bme = (const float*)d_in[9];
    const float* wle = (const float*)d_in[10]; const float* ble = (const float*)d_in[11];
    const float* w4e = (const float*)d_in[12]; const float* b4e = (const float*)d_in[13];
    const float* w1n = (const float*)d_in[14]; const float* b1n = (const float*)d_in[15];
    const float* wmn = (const float*)d_in[16]; const float* bmn = (const float*)d_in[17];
    const float* wln = (const float*)d_in[18]; const float* bln = (const float*)d_in[19];
    const float* w5n = (const float*)d_in[20]; const float* b5n = (const float*)d_in[21];

    float* out   = (float*)d_out;
    float* edges = out;                         // [N,192]
    float* nodes = out + (size_t)NNODES * 192;  // [N,96]

    cudaGetSymbolAddress((void**)&hAhi, g_Ahi);
    cudaGetSymbolAddress((void**)&hAlo, g_Alo);
    cudaGetSymbolAddress((void**)&hWhi, g_Whi);
    cudaGetSymbolAddress((void**)&hWlo, g_Wlo);
    cudaGetSymbolAddress((void**)&hbufA, g_bufA);
    cudaGetSymbolAddress((void**)&hbufB, g_bufB);

    cudaFuncSetAttribute(k_mgemm, cudaFuncAttributeMaxDynamicSharedMemorySize,
                         (int)(2 * (2 * ASZ + 2 * BSZ)));
    cudaFuncSetAttribute(k_mgemm_dual,
                         cudaFuncAttributeMaxDynamicSharedMemorySize,
                         (int)(2 * (2 * ASZ + 4 * BSZ)));

    // ---- prep ----
    k_prep1<<<(NNODES + 255) / 256, 256>>>();
    k_detect<<<512, 256>>>((const unsigned*)ei);
    k_convert<<<(NEDGES + 255) / 256, 256>>>(ei);
    k_dinv<<<(NNODES + 255) / 256, 256>>>();
    k_scanA<<<NBLK, 1024>>>();
    k_scanB<<<1, 32>>>();
    k_scanC<<<NBLK, 1024>>>();
    k_fill<<<(NEDGES + 255) / 256, 256>>>();
    {
        WSet ws;
        ws.w[0] = w1e; ws.K[0] = 96;  ws.M[0] = 125;
        ws.w[1] = w2e; ws.K[1] = 125; ws.M[1] = 144;
        ws.w[2] = wme; ws.K[2] = 144; ws.M[2] = 163;
        ws.w[3] = wle; ws.K[3] = 144; ws.M[3] = 163;
        ws.w[4] = w4e; ws.K[4] = 163; ws.M[4] = 192;
        ws.w[5] = w1n; ws.K[5] = 96;  ws.M[5] = 96;
        ws.w[6] = wmn; ws.K[6] = 96;  ws.M[6] = 96;
        ws.w[7] = wln; ws.K[7] = 96;  ws.M[7] = 96;
        ws.w[8] = w5n; ws.K[8] = 96;  ws.M[8] = 96;
        dim3 g((192 * 192 + 255) / 256, 9);
        k_wsplit_all<<<g, 256>>>(ws, hWhi, hWlo);
    }
    k_padx<<<(NNODES * 128 + 255) / 256, 256>>>(x, hbufB);

    // ---- shared first propagation: split(Â x), kpad 128 ----
    launch_prop(hbufB, 128);
    mm(128, 0, 96, b1e, hbufA, 128, 125, 1);                  // e1 relu (ldc128)
    mm(128, 5, 96, b1n, hbufB, 128, 96, 1);                   // n1 relu (ldc128)

    // ---- edge branch ----
    launch_prop(hbufA, 128);                                  // C=125, kpad 128
    mm(128, 1, 125, b2e, hbufA, 160, 144, 1);                 // e2 relu
    launch_prop(hbufA, 160);                                  // C=144, kpad 192
    mmdual(192, 2, 3, 144, bme, ble, eps_e, 163, hbufA, 192, 163);
    launch_prop(hbufA, 192);                                  // C=163, kpad 192
    mm(192, 4, 163, b4e, edges, 192, 192, 2);                 // sigmoid

    // ---- node branch ----
    launch_prop(hbufB, 128);                                  // n1, kpad 128
    mmdual(128, 6, 7, 96, bmn, bln, eps_n, 96, hbufA, 128, 96);
    launch_prop(hbufA, 128);                                  // kpad 128
    mm(128, 8, 96, b5n, nodes, 96, 96, 1);                    // relu
}

// round 12
// speedup vs baseline: 4.1391x; 1.0097x over previous
#include <cuda_runtime.h>
#include <cuda_fp16.h>
#include <math.h>
#include <cstdint>

#define NNODES 50000
#define NEDGES 800000
#define NBLK 13

// ---------------------------------------------------------------------------
// Scratch
// ---------------------------------------------------------------------------
__device__ __align__(16) __half g_Ahi[(size_t)NNODES * 192];   // edge-branch split
__device__ __align__(16) __half g_Alo[(size_t)NNODES * 192];
__device__ __align__(16) __half g_Bhi[(size_t)NNODES * 128];   // node-branch split
__device__ __align__(16) __half g_Blo[(size_t)NNODES * 128];
__device__ __align__(16) __half g_Whi[9][192 * 192];
__device__ __align__(16) __half g_Wlo[9][192 * 192];
__device__ float g_bufA[(size_t)NNODES * 192];   // edge fp32 activations
__device__ float g_bufB[(size_t)NNODES * 128];   // x padded / n1
__device__ float g_bufC[(size_t)NNODES * 128];   // node reparam out
__device__ float g_dinv[NNODES];
__device__ int   g_row[NEDGES];
__device__ int   g_col[NEDGES];
__device__ int   g_ideg[NNODES];
__device__ int   g_off[NNODES + 1];
__device__ int   g_cursor[NNODES];
__device__ int2  g_ecsr[NEDGES];
__device__ int   g_bsum[32];
__device__ int   g_bpre[32];
__device__ unsigned g_flag32;

// ---------------------------------------------------------------------------
// PTX helpers (sm_103-safe)
// ---------------------------------------------------------------------------
__device__ __forceinline__ unsigned s2u(const void* p) {
    return (unsigned)__cvta_generic_to_shared(p);
}
__device__ __forceinline__ void cpa16(unsigned dst, const void* src, bool p) {
    asm volatile("cp.async.cg.shared.global [%0], [%1], 16, %2;"
                 :: "r"(dst), "l"(src), "r"(p ? 16 : 0));
}
#define CP_COMMIT() asm volatile("cp.async.commit_group;")
template <int N>
__device__ __forceinline__ void cp_wait() {
    asm volatile("cp.async.wait_group %0;" :: "n"(N) : "memory");
}
__device__ __forceinline__ uint32_t lds32(uint32_t a) {
    uint32_t v;
    asm volatile("ld.shared.b32 %0,[%1];" : "=r"(v) : "r"(a));
    return v;
}
__device__ __forceinline__ void mma16816(float* c, const uint32_t* a,
                                         const uint32_t* b) {
    asm volatile(
        "mma.sync.aligned.m16n8k16.row.col.f32.f16.f16.f32 "
        "{%0,%1,%2,%3}, {%4,%5,%6,%7}, {%8,%9}, {%0,%1,%2,%3};"
        : "+f"(c[0]), "+f"(c[1]), "+f"(c[2]), "+f"(c[3])
        : "r"(a[0]), "r"(a[1]), "r"(a[2]), "r"(a[3]), "r"(b[0]), "r"(b[1]));
}

// ---------------------------------------------------------------------------
// Prep kernels
// ---------------------------------------------------------------------------
__global__ void k_prep1() {
    int i = blockIdx.x * blockDim.x + threadIdx.x;
    if (i < NNODES) g_ideg[i] = 0;
    if (i == 0) g_flag32 = 0u;
}

__global__ void k_detect(const unsigned* __restrict__ w) {
    unsigned v = 0;
    for (int i = blockIdx.x * blockDim.x + threadIdx.x; i < NEDGES;
         i += gridDim.x * blockDim.x)
        v |= w[2 * i + 1];
    #pragma unroll
    for (int o = 16; o; o >>= 1) v |= __shfl_xor_sync(0xFFFFFFFFu, v, o);
    if ((threadIdx.x & 31) == 0 && v) atomicOr(&g_flag32, 1u);
}

__global__ void k_convert(const void* __restrict__ ei) {
    int e = blockIdx.x * blockDim.x + threadIdx.x;
    if (e >= NEDGES) return;
    int r, c;
    if (g_flag32 == 0u) {
        const long long* ll = (const long long*)ei;
        r = (int)ll[e];
        c = (int)ll[NEDGES + e];
    } else {
        const int* q = (const int*)ei;
        r = q[e];
        c = q[NEDGES + e];
    }
    g_row[e] = r;
    g_col[e] = c;
    atomicAdd(&g_ideg[c], 1);
}

// scanA also computes dinv (reads ideg anyway)
__global__ __launch_bounds__(1024) void k_scanA() {
    __shared__ int sh[32];
    int b = blockIdx.x, t = threadIdx.x;
    int base = b * 4096 + t * 4;
    int s = 0;
    #pragma unroll
    for (int j = 0; j < 4; j++) {
        int i = base + j;
        if (i < NNODES) {
            int dv = g_ideg[i];
            s += dv;
            g_dinv[i] = rsqrtf((float)dv + 1.0f);
        }
    }
    #pragma unroll
    for (int o = 16; o; o >>= 1) s += __shfl_xor_sync(0xFFFFFFFFu, s, o);
    if ((t & 31) == 0) sh[t >> 5] = s;
    __syncthreads();
    if (t < 32) {
        int x = sh[t];
        #pragma unroll
        for (int o = 16; o; o >>= 1) x += __shfl_xor_sync(0xFFFFFFFFu, x, o);
        if (t == 0) g_bsum[b] = x;
    }
}

__global__ void k_scanB() {
    int t = threadIdx.x;
    int v = (t < NBLK) ? g_bsum[t] : 0;
    int own = v;
    #pragma unroll
    for (int o = 1; o < 32; o <<= 1) {
        int u = __shfl_up_sync(0xFFFFFFFFu, v, o);
        if (t >= o) v += u;
    }
    if (t < NBLK) g_bpre[t] = v - own;
}

__global__ __launch_bounds__(1024) void k_scanC() {
    __shared__ int sh[1024];
    int b = blockIdx.x, t = threadIdx.x;
    int base = b * 4096 + t * 4;
    int v[4];
    int s = 0;
    #pragma unroll
    for (int j = 0; j < 4; j++) {
        int i = base + j;
        v[j] = (i < NNODES) ? g_ideg[i] : 0;
        s += v[j];
    }
    sh[t] = s;
    __syncthreads();
    #pragma unroll
    for (int o = 1; o < 1024; o <<= 1) {
        int tmp = (t >= o) ? sh[t - o] : 0;
        __syncthreads();
        sh[t] += tmp;
        __syncthreads();
    }
    int excl = sh[t] - s + g_bpre[b];
    #pragma unroll
    for (int j = 0; j < 4; j++) {
        int i = base + j;
        if (i < NNODES) { g_off[i] = excl; g_cursor[i] = excl; }
        excl += v[j];
    }
    if (b == 0 && t == 0) g_off[NNODES] = NEDGES;
}

__global__ void k_fill() {
    int e = blockIdx.x * blockDim.x + threadIdx.x;
    if (e >= NEDGES) return;
    int r = g_row[e], c = g_col[e];
    float cf = g_dinv[r] * g_dinv[c];
    int pos = atomicAdd(&g_cursor[c], 1);
    g_ecsr[pos] = make_int2(r, __float_as_int(cf));
}

// All 9 weight transposes + fp16 splits in one launch (blockIdx.y = slab).
struct WSet { const float* w[9]; int K[9]; int M[9]; };
__global__ void k_wsplit_all(WSet ws, __half* __restrict__ hiB,
                             __half* __restrict__ loB) {
    int slab = blockIdx.y;
    int idx = blockIdx.x * blockDim.x + threadIdx.x;
    if (idx >= 192 * 192) return;
    int n = idx / 192, k = idx % 192;
    int K = ws.K[slab], M = ws.M[slab];
    float v = (k < K && n < M) ? ws.w[slab][(size_t)k * M + n] : 0.0f;
    __half h = __float2half_rn(v);
    size_t o = (size_t)slab * 192 * 192 + idx;
    hiB[o] = h;
    loB[o] = __float2half_rn(v - __half2float(h));
}

// Pad x [N,96] -> [N,128]
__global__ void k_padx(const float* __restrict__ x, float* __restrict__ o) {
    int i = blockIdx.x * blockDim.x + threadIdx.x;
    if (i >= NNODES * 128) return;
    int n = i >> 7, c = i & 127;
    o[i] = (c < 96) ? x[n * 96 + c] : 0.0f;
}

// ---------------------------------------------------------------------------
// Gather + fp16 split
// ---------------------------------------------------------------------------
__device__ __forceinline__ uint32_t hfp(float a, float b) {
    __half2 t;
    t.x = __float2half_rn(a);
    t.y = __float2half_rn(b);
    return *reinterpret_cast<uint32_t*>(&t);
}

template <int SIN, int KPAD>
__global__ __launch_bounds__(256) void k_gather(const float4* __restrict__ in4,
                                                uint2* __restrict__ hi,
                                                uint2* __restrict__ lo) {
    constexpr int NV4 = SIN / 4;
    constexpr int OV4 = KPAD / 4;
    constexpr int NIT = (OV4 + 31) / 32;
    int node = blockIdx.x * 8 + (threadIdx.x >> 5);
    if (node >= NNODES) return;
    int lane = threadIdx.x & 31;

    float d = g_dinv[node];
    float dd = d * d;

    float4 acc[NIT];
    #pragma unroll
    for (int v = 0; v < NIT; v++) {
        int id = lane + 32 * v;
        if (id < NV4) {
            float4 t = in4[(size_t)node * NV4 + id];
            acc[v] = make_float4(t.x * dd, t.y * dd, t.z * dd, t.w * dd);
        } else acc[v] = make_float4(0.f, 0.f, 0.f, 0.f);
    }

    int s = g_off[node];
    int e = g_off[node + 1];
    int i = s;
    for (; i + 3 < e; i += 4) {
        int2 p0 = g_ecsr[i];
        int2 p1 = g_ecsr[i + 1];
        int2 p2 = g_ecsr[i + 2];
        int2 p3 = g_ecsr[i + 3];
        float c0 = __int_as_float(p0.y), c1 = __int_as_float(p1.y);
        float c2 = __int_as_float(p2.y), c3 = __int_as_float(p3.y);
        #pragma unroll
        for (int v = 0; v < NIT; v++) {
            int id = lane + 32 * v;
            if (id < NV4) {
                float4 a0 = in4[(size_t)p0.x * NV4 + id];
                float4 a1 = in4[(size_t)p1.x * NV4 + id];
                float4 a2 = in4[(size_t)p2.x * NV4 + id];
                float4 a3 = in4[(size_t)p3.x * NV4 + id];
                acc[v].x += a0.x * c0; acc[v].y += a0.y * c0;
                acc[v].z += a0.z * c0; acc[v].w += a0.w * c0;
                acc[v].x += a1.x * c1; acc[v].y += a1.y * c1;
                acc[v].z += a1.z * c1; acc[v].w += a1.w * c1;
                acc[v].x += a2.x * c2; acc[v].y += a2.y * c2;
                acc[v].z += a2.z * c2; acc[v].w += a2.w * c2;
                acc[v].x += a3.x * c3; acc[v].y += a3.y * c3;
                acc[v].z += a3.z * c3; acc[v].w += a3.w * c3;
            }
        }
    }
    for (; i < e; i++) {
        int2 p = g_ecsr[i];
        float c0 = __int_as_float(p.y);
        #pragma unroll
        for (int v = 0; v < NIT; v++) {
            int id = lane + 32 * v;
            if (id < NV4) {
                float4 a = in4[(size_t)p.x * NV4 + id];
                acc[v].x += a.x * c0; acc[v].y += a.y * c0;
                acc[v].z += a.z * c0; acc[v].w += a.w * c0;
            }
        }
    }
    #pragma unroll
    for (int v = 0; v < NIT; v++) {
        int id = lane + 32 * v;
        if (id < OV4) {
            float4 a = acc[v];
            float hx = __half2float(__float2half_rn(a.x));
            float hy = __half2float(__float2half_rn(a.y));
            float hz = __half2float(__float2half_rn(a.z));
            float hw = __half2float(__float2half_rn(a.w));
            uint2 ph, pl;
            ph.x = hfp(a.x, a.y);
            ph.y = hfp(a.z, a.w);
            pl.x = hfp(a.x - hx, a.y - hy);
            pl.y = hfp(a.z - hz, a.w - hw);
            hi[(size_t)node * OV4 + id] = ph;
            lo[(size_t)node * OV4 + id] = pl;
        }
    }
}

// ---------------------------------------------------------------------------
// mma.sync GEMM: block 256 thr, tile 128x64, warp 32x32, BK=32 double-buffer
// ---------------------------------------------------------------------------
#define RS 80
#define ASZ (128 * RS)
#define BSZ (64 * RS)

__global__ __launch_bounds__(256, 3) void k_mgemm(
    const __half* __restrict__ Ahi, const __half* __restrict__ Alo, int kpad,
    const __half* __restrict__ Wh, const __half* __restrict__ Wl,
    const float* __restrict__ bias, float* __restrict__ out, int ldc,
    int M, int nk, int mode, int rows)
{
    extern __shared__ char sm[];
    uint32_t base = s2u(sm);
    const int STRIDE = 2 * ASZ + 2 * BSZ;
    int tid = threadIdx.x;
    int wid = tid >> 5, lane = tid & 31;
    int g = lane >> 2, t = lane & 3;
    int wm = wid & 3, wn = wid >> 2;
    int r0 = blockIdx.y * 128;
    int c0 = blockIdx.x * 64;

    auto loadT = [&](int b, int k0) {
        uint32_t ba = base + b * STRIDE;
        #pragma unroll
        for (int i = 0; i < 2; i++) {
            int it = tid + i * 256;
            int m = it >> 2, c = it & 3;
            int gr = r0 + m;
            bool ok = (gr < rows);
            size_t so = (size_t)(ok ? gr : 0) * kpad + k0 + c * 8;
            uint32_t dd = ba + m * RS + c * 16;
            cpa16(dd, Ahi + so, ok);
            cpa16(dd + ASZ, Alo + so, ok);
        }
        {
            int n = tid >> 2, c = tid & 3;
            size_t so = (size_t)(c0 + n) * 192 + k0 + c * 8;
            uint32_t dd = ba + 2 * ASZ + n * RS + c * 16;
            cpa16(dd, Wh + so, true);
            cpa16(dd + BSZ, Wl + so, true);
        }
        CP_COMMIT();
    };

    loadT(0, 0);

    float acc[2][4][4];
    #pragma unroll
    for (int i = 0; i < 2; i++)
        #pragma unroll
        for (int j = 0; j < 4; j++)
            #pragma unroll
            for (int q = 0; q < 4; q++) acc[i][j][q] = 0.0f;

    for (int it = 0; it < nk; it++) {
        int b = it & 1;
        if (it + 1 < nk) { loadT(b ^ 1, (it + 1) * 32); cp_wait<1>(); }
        else cp_wait<0>();
        __syncthreads();
        uint32_t ba = base + b * STRIDE;
        uint32_t aB = ba + (wm * 32 + g) * RS + t * 4;
        uint32_t bB = ba + 2 * ASZ + (wn * 32 + g) * RS + t * 4;
        #pragma unroll
        for (int kc = 0; kc < 2; kc++) {
            uint32_t ah[2][4], al[2][4];
            #pragma unroll
            for (int ms = 0; ms < 2; ms++) {
                uint32_t a0 = aB + ms * (16 * RS) + kc * 32;
                ah[ms][0] = lds32(a0);
                ah[ms][1] = lds32(a0 + 8 * RS);
                ah[ms][2] = lds32(a0 + 16);
                ah[ms][3] = lds32(a0 + 8 * RS + 16);
                al[ms][0] = lds32(a0 + ASZ);
                al[ms][1] = lds32(a0 + ASZ + 8 * RS);
                al[ms][2] = lds32(a0 + ASZ + 16);
                al[ms][3] = lds32(a0 + ASZ + 8 * RS + 16);
            }
            #pragma unroll
            for (int ns = 0; ns < 4; ns++) {
                uint32_t b0 = bB + ns * (8 * RS) + kc * 32;
                uint32_t bh[2], bl[2];
                bh[0] = lds32(b0);
                bh[1] = lds32(b0 + 16);
                bl[0] = lds32(b0 + BSZ);
                bl[1] = lds32(b0 + BSZ + 16);
                #pragma unroll
                for (int ms = 0; ms < 2; ms++) {
                    mma16816(acc[ms][ns], ah[ms], bh);
                    mma16816(acc[ms][ns], ah[ms], bl);
                    mma16816(acc[ms][ns], al[ms], bh);
                }
            }
        }
        __syncthreads();
    }

    #pragma unroll
    for (int ms = 0; ms < 2; ms++) {
        #pragma unroll
        for (int h = 0; h < 2; h++) {
            int r = r0 + wm * 32 + ms * 16 + h * 8 + g;
            if (r >= rows) continue;
            #pragma unroll
            for (int ns = 0; ns < 4; ns++) {
                int cc = c0 + wn * 32 + ns * 8 + 2 * t;
                if (cc >= ldc) continue;
                float v0 = acc[ms][ns][h * 2 + 0];
                float v1 = acc[ms][ns][h * 2 + 1];
                if (cc < M) {
                    v0 += bias[cc];
                    if (mode == 1) v0 = fmaxf(v0, 0.0f);
                    else if (mode == 2) v0 = 1.0f / (1.0f + expf(-v0));
                } else v0 = 0.0f;
                if (cc + 1 < M) {
                    v1 += bias[cc + 1];
                    if (mode == 1) v1 = fmaxf(v1, 0.0f);
                    else if (mode == 2) v1 = 1.0f / (1.0f + expf(-v1));
                } else v1 = 0.0f;
                float2 st; st.x = v0; st.y = v1;
                *(float2*)(&out[(size_t)r * ldc + cc]) = st;
            }
        }
    }
}

// ---------------------------------------------------------------------------
// Dual mma.sync GEMM: out = mu + eps*exp(ls)/10
// ---------------------------------------------------------------------------
__global__ __launch_bounds__(256, 2) void k_mgemm_dual(
    const __half* __restrict__ Ahi, const __half* __restrict__ Alo, int kpad,
    const __half* __restrict__ W1h, const __half* __restrict__ W1l,
    const __half* __restrict__ W2h, const __half* __restrict__ W2l,
    const float* __restrict__ b1, const float* __restrict__ b2,
    const float* __restrict__ eps, int lde,
    float* __restrict__ out, int ldc, int M, int nk, int rows)
{
    extern __shared__ char sm[];
    uint32_t base = s2u(sm);
    const int STRIDE = 2 * ASZ + 4 * BSZ;
    int tid = threadIdx.x;
    int wid = tid >> 5, lane = tid & 31;
    int g = lane >> 2, t = lane & 3;
    int wm = wid & 3, wn = wid >> 2;
    int r0 = blockIdx.y * 128;
    int c0 = blockIdx.x * 64;

    auto loadT = [&](int b, int k0) {
        uint32_t ba = base + b * STRIDE;
        #pragma unroll
        for (int i = 0; i < 2; i++) {
            int it = tid + i * 256;
            int m = it >> 2, c = it & 3;
            int gr = r0 + m;
            bool ok = (gr < rows);
            size_t so = (size_t)(ok ? gr : 0) * kpad + k0 + c * 8;
            uint32_t dd = ba + m * RS + c * 16;
            cpa16(dd, Ahi + so, ok);
            cpa16(dd + ASZ, Alo + so, ok);
        }
        {
            int n = tid >> 2, c = tid & 3;
            size_t so = (size_t)(c0 + n) * 192 + k0 + c * 8;
            uint32_t dd = ba + 2 * ASZ + n * RS + c * 16;
            cpa16(dd, W1h + so, true);
            cpa16(dd + BSZ, W1l + so, true);
            cpa16(dd + 2 * BSZ, W2h + so, true);
            cpa16(dd + 3 * BSZ, W2l + so, true);
        }
        CP_COMMIT();
    };

    loadT(0, 0);

    float ac1[2][4][4], ac2[2][4][4];
    #pragma unroll
    for (int i = 0; i < 2; i++)
        #pragma unroll
        for (int j = 0; j < 4; j++)
            #pragma unroll
            for (int q = 0; q < 4; q++) { ac1[i][j][q] = 0.0f; ac2[i][j][q] = 0.0f; }

    for (int it = 0; it < nk; it++) {
        int b = it & 1;
        if (it + 1 < nk) { loadT(b ^ 1, (it + 1) * 32); cp_wait<1>(); }
        else cp_wait<0>();
        __syncthreads();
        uint32_t ba = base + b * STRIDE;
        uint32_t aB = ba + (wm * 32 + g) * RS + t * 4;
        uint32_t bB = ba + 2 * ASZ + (wn * 32 + g) * RS + t * 4;
        #pragma unroll
        for (int kc = 0; kc < 2; kc++) {
            uint32_t ah[2][4], al[2][4];
            #pragma unroll
            for (int ms = 0; ms < 2; ms++) {
                uint32_t a0 = aB + ms * (16 * RS) + kc * 32;
                ah[ms][0] = lds32(a0);
                ah[ms][1] = lds32(a0 + 8 * RS);
                ah[ms][2] = lds32(a0 + 16);
                ah[ms][3] = lds32(a0 + 8 * RS + 16);
                al[ms][0] = lds32(a0 + ASZ);
                al[ms][1] = lds32(a0 + ASZ + 8 * RS);
                al[ms][2] = lds32(a0 + ASZ + 16);
                al[ms][3] = lds32(a0 + ASZ + 8 * RS + 16);
            }
            #pragma unroll
            for (int ns = 0; ns < 4; ns++) {
                uint32_t b0 = bB + ns * (8 * RS) + kc * 32;
                uint32_t b1h[2], b1l[2], b2h[2], b2l[2];
                b1h[0] = lds32(b0);            b1h[1] = lds32(b0 + 16);
                b1l[0] = lds32(b0 + BSZ);      b1l[1] = lds32(b0 + BSZ + 16);
                b2h[0] = lds32(b0 + 2 * BSZ);  b2h[1] = lds32(b0 + 2 * BSZ + 16);
                b2l[0] = lds32(b0 + 3 * BSZ);  b2l[1] = lds32(b0 + 3 * BSZ + 16);
                #pragma unroll
                for (int ms = 0; ms < 2; ms++) {
                    mma16816(ac1[ms][ns], ah[ms], b1h);
                    mma16816(ac1[ms][ns], ah[ms], b1l);
                    mma16816(ac1[ms][ns], al[ms], b1h);
                    mma16816(ac2[ms][ns], ah[ms], b2h);
                    mma16816(ac2[ms][ns], ah[ms], b2l);
                    mma16816(ac2[ms][ns], al[ms], b2h);
                }
            }
        }
        __syncthreads();
    }

    #pragma unroll
    for (int ms = 0; ms < 2; ms++) {
        #pragma unroll
        for (int h = 0; h < 2; h++) {
            int r = r0 + wm * 32 + ms * 16 + h * 8 + g;
            if (r >= rows) continue;
            #pragma unroll
            for (int ns = 0; ns < 4; ns++) {
                int cc = c0 + wn * 32 + ns * 8 + 2 * t;
                if (cc >= ldc) continue;
                float v0 = 0.0f, v1 = 0.0f;
                if (cc < M) {
                    float mu = ac1[ms][ns][h * 2 + 0] + b1[cc];
                    float ls = ac2[ms][ns][h * 2 + 0] + b2[cc];
                    v0 = mu + eps[(size_t)r * lde + cc] * expf(ls) * 0.1f;
                }
                if (cc + 1 < M) {
                    float mu = ac1[ms][ns][h * 2 + 1] + b1[cc + 1];
                    float ls = ac2[ms][ns][h * 2 + 1] + b2[cc + 1];
                    v1 = mu + eps[(size_t)r * lde + cc + 1] * expf(ls) * 0.1f;
                }
                float2 st; st.x = v0; st.y = v1;
                *(float2*)(&out[(size_t)r * ldc + cc]) = st;
            }
        }
    }
}

// ---------------------------------------------------------------------------
// Host side
// ---------------------------------------------------------------------------
static __half *hAhi, *hAlo, *hBhi, *hBlo, *hWhi, *hWlo;
static float *hbufA, *hbufB, *hbufC;

static void prop(const float* in, int SIN, __half* hi, __half* lo,
                 cudaStream_t st) {
    int blocks = (NNODES + 7) / 8;
    uint2* h2 = (uint2*)hi;
    uint2* l2 = (uint2*)lo;
    switch (SIN) {
        case 128: k_gather<128, 128><<<blocks, 256, 0, st>>>((const float4*)in, h2, l2); break;
        case 160: k_gather<160, 192><<<blocks, 256, 0, st>>>((const float4*)in, h2, l2); break;
        case 192: k_gather<192, 192><<<blocks, 256, 0, st>>>((const float4*)in, h2, l2); break;
    }
}

static void mm(const __half* ah, const __half* al, int kpad, int widx, int K,
               const float* bias, float* out, int ldc, int M, int mode,
               cudaStream_t st) {
    int nk = (K + 31) / 32;
    dim3 grid((ldc + 63) / 64, (NNODES + 127) / 128);
    size_t smem = 2 * (2 * ASZ + 2 * BSZ);
    k_mgemm<<<grid, 256, smem, st>>>(ah, al, kpad,
                                     hWhi + (size_t)widx * 192 * 192,
                                     hWlo + (size_t)widx * 192 * 192,
                                     bias, out, ldc, M, nk, mode, NNODES);
}

static void mmdual(const __half* ah, const __half* al, int kpad, int w1,
                   int w2, int K, const float* b1, const float* b2,
                   const float* eps, int lde, float* out, int ldc, int M,
                   cudaStream_t st) {
    int nk = (K + 31) / 32;
    dim3 grid((ldc + 63) / 64, (NNODES + 127) / 128);
    size_t smem = 2 * (2 * ASZ + 4 * BSZ);
    k_mgemm_dual<<<grid, 256, smem, st>>>(ah, al, kpad,
                                          hWhi + (size_t)w1 * 192 * 192,
                                          hWlo + (size_t)w1 * 192 * 192,
                                          hWhi + (size_t)w2 * 192 * 192,
                                          hWlo + (size_t)w2 * 192 * 192,
                                          b1, b2, eps, lde, out, ldc, M, nk,
                                          NNODES);
}

extern "C" void kernel_launch(void* const* d_in, const int* in_sizes, int n_in,
                              void* d_out, int out_size) {
    const float* x     = (const float*)d_in[0];
    const void*  ei    = d_in[1];
    const float* eps_e = (const float*)d_in[2];
    const float* eps_n = (const float*)d_in[3];
    const float* w1e = (const float*)d_in[4];  const float* b1e = (const float*)d_in[5];
    const float* w2e = (const float*)d_in[6];  const float* b2e = (const float*)d_in[7];
    const float* wme = (const float*)d_in[8];  const float* bme = (const float*)d_in[9];
    const float* wle = (const float*)d_in[10]; const float* ble = (const float*)d_in[11];
    const float* w4e = (const float*)d_in[12]; const float* b4e = (const float*)d_in[13];
    const float* w1n = (const float*)d_in[14]; const float* b1n = (const float*)d_in[15];
    const float* wmn = (const float*)d_in[16]; const float* bmn = (const float*)d_in[17];
    const float* wln = (const float*)d_in[18]; const float* bln = (const float*)d_in[19];
    const float* w5n = (const float*)d_in[20]; const float* b5n = (const float*)d_in[21];

    float* out   = (float*)d_out;
    float* edges = out;                         // [N,192]
    float* nodes = out + (size_t)NNODES * 192;  // [N,96]

    cudaGetSymbolAddress((void**)&hAhi, g_Ahi);
    cudaGetSymbolAddress((void**)&hAlo, g_Alo);
    cudaGetSymbolAddress((void**)&hBhi, g_Bhi);
    cudaGetSymbolAddress((void**)&hBlo, g_Blo);
    cudaGetSymbolAddress((void**)&hWhi, g_Whi);
    cudaGetSymbolAddress((void**)&hWlo, g_Wlo);
    cudaGetSymbolAddress((void**)&hbufA, g_bufA);
    cudaGetSymbolAddress((void**)&hbufB, g_bufB);
    cudaGetSymbolAddress((void**)&hbufC, g_bufC);

    cudaFuncSetAttribute(k_mgemm, cudaFuncAttributeMaxDynamicSharedMemorySize,
                         (int)(2 * (2 * ASZ + 2 * BSZ)));
    cudaFuncSetAttribute(k_mgemm_dual,
                         cudaFuncAttributeMaxDynamicSharedMemorySize,
                         (int)(2 * (2 * ASZ + 4 * BSZ)));

    cudaStream_t s0 = 0;                    // capture (default) stream
    cudaStream_t s1 = cudaStreamPerThread;  // parallel branch (no creation)
    cudaEvent_t evFork0, evPadx, evG1, evN1, evJoin;
    cudaEventCreateWithFlags(&evFork0, cudaEventDisableTiming);
    cudaEventCreateWithFlags(&evPadx, cudaEventDisableTiming);
    cudaEventCreateWithFlags(&evG1, cudaEventDisableTiming);
    cudaEventCreateWithFlags(&evN1, cudaEventDisableTiming);
    cudaEventCreateWithFlags(&evJoin, cudaEventDisableTiming);

    // ---- fork: weight split + x pad on s1, CSR prep on s0 ----
    cudaEventRecord(evFork0, s0);
    cudaStreamWaitEvent(s1, evFork0, 0);
    {
        WSet ws;
        ws.w[0] = w1e; ws.K[0] = 96;  ws.M[0] = 125;
        ws.w[1] = w2e; ws.K[1] = 125; ws.M[1] = 144;
        ws.w[2] = wme; ws.K[2] = 144; ws.M[2] = 163;
        ws.w[3] = wle; ws.K[3] = 144; ws.M[3] = 163;
        ws.w[4] = w4e; ws.K[4] = 163; ws.M[4] = 192;
        ws.w[5] = w1n; ws.K[5] = 96;  ws.M[5] = 96;
        ws.w[6] = wmn; ws.K[6] = 96;  ws.M[6] = 96;
        ws.w[7] = wln; ws.K[7] = 96;  ws.M[7] = 96;
        ws.w[8] = w5n; ws.K[8] = 96;  ws.M[8] = 96;
        dim3 g((192 * 192 + 255) / 256, 9);
        k_wsplit_all<<<g, 256, 0, s1>>>(ws, hWhi, hWlo);
    }
    k_padx<<<(NNODES * 128 + 255) / 256, 256, 0, s1>>>(x, hbufB);
    cudaEventRecord(evPadx, s1);

    k_prep1<<<(NNODES + 255) / 256, 256, 0, s0>>>();
    k_detect<<<512, 256, 0, s0>>>((const unsigned*)ei);
    k_convert<<<(NEDGES + 255) / 256, 256, 0, s0>>>(ei);
    k_scanA<<<NBLK, 1024, 0, s0>>>();
    k_scanB<<<1, 32, 0, s0>>>();
    k_scanC<<<NBLK, 1024, 0, s0>>>();
    k_fill<<<(NEDGES + 255) / 256, 256, 0, s0>>>();

    // ---- shared first propagation (needs padx + fill) ----
    cudaStreamWaitEvent(s0, evPadx, 0);
    prop(hbufB, 128, hAhi, hAlo, s0);              // g1: split(Â x)
    cudaEventRecord(evG1, s0);

    // ---- node branch on s1 (n1 reads g1's Ahi/Alo) ----
    cudaStreamWaitEvent(s1, evG1, 0);
    mm(hAhi, hAlo, 128, 5, 96, b1n, hbufB, 128, 96, 1, s1);     // n1 relu
    cudaEventRecord(evN1, s1);
    prop(hbufB, 128, hBhi, hBlo, s1);                           // g5
    mmdual(hBhi, hBlo, 128, 6, 7, 96, bmn, bln, eps_n, 96,
           hbufC, 128, 96, s1);                                 // nn
    prop(hbufC, 128, hBhi, hBlo, s1);                           // g6
    mm(hBhi, hBlo, 128, 8, 96, b5n, nodes, 96, 96, 1, s1);      // relu -> out

    // ---- edge branch on s0 ----
    mm(hAhi, hAlo, 128, 0, 96, b1e, hbufA, 128, 125, 1, s0);    // e1 relu
    cudaStreamWaitEvent(s0, evN1, 0);   // g2 overwrites Ahi/Alo; n1 must be done
    prop(hbufA, 128, hAhi, hAlo, s0);                           // g2
    mm(hAhi, hAlo, 128, 1, 125, b2e, hbufA, 160, 144, 1, s0);   // e2 relu
    prop(hbufA, 160, hAhi, hAlo, s0);                           // g3 (kpad 192)
    mmdual(hAhi, hAlo, 192, 2, 3, 144, bme, ble, eps_e, 163,
           hbufA, 192, 163, s0);                                // e reparam
    prop(hbufA, 192, hAhi, hAlo, s0);                           // g4
    mm(hAhi, hAlo, 192, 4, 163, b4e, edges, 192, 192, 2, s0);   // sigmoid -> out

    // ---- join node branch back into capture stream ----
    cudaEventRecord(evJoin, s1);
    cudaStreamWaitEvent(s0, evJoin, 0);
}

// round 15
// speedup vs baseline: 4.5747x; 1.1053x over previous
#include <cuda_runtime.h>
#include <cuda_fp16.h>
#include <math.h>
#include <cstdint>

#define NNODES 50000
#define NEDGES 800000
#define NBLK 13

// ---------------------------------------------------------------------------
// Scratch
// ---------------------------------------------------------------------------
__device__ __align__(16) __half g_Ahi[(size_t)NNODES * 192];   // edge split
__device__ __align__(16) __half g_Alo[(size_t)NNODES * 192];
__device__ __align__(16) __half g_Bhi[(size_t)NNODES * 128];   // node split
__device__ __align__(16) __half g_Blo[(size_t)NNODES * 128];
__device__ __align__(16) __half g_Whi[9][192 * 192];
__device__ __align__(16) __half g_Wlo[9][192 * 192];
__device__ __align__(16) __half g_actA[(size_t)NNODES * 192];  // edge activations (fp16)
__device__ __align__(16) __half g_actB[(size_t)NNODES * 128];  // x pad / n1 (fp16)
__device__ __align__(16) __half g_actC[(size_t)NNODES * 128];  // node reparam (fp16)
__device__ float g_dinv[NNODES];
__device__ int   g_row[NEDGES];
__device__ int   g_col[NEDGES];
__device__ int   g_ideg[NNODES];
__device__ int   g_off[NNODES + 1];
__device__ int   g_cursor[NNODES];
__device__ int2  g_ecsr[NEDGES];
__device__ int   g_bsum[32];
__device__ int   g_bpre[32];
__device__ unsigned g_flag32;

// ---------------------------------------------------------------------------
// PTX helpers (sm_103-safe)
// ---------------------------------------------------------------------------
__device__ __forceinline__ unsigned s2u(const void* p) {
    return (unsigned)__cvta_generic_to_shared(p);
}
__device__ __forceinline__ void cpa16(unsigned dst, const void* src, bool p) {
    asm volatile("cp.async.cg.shared.global [%0], [%1], 16, %2;"
                 :: "r"(dst), "l"(src), "r"(p ? 16 : 0));
}
#define CP_COMMIT() asm volatile("cp.async.commit_group;")
template <int N>
__device__ __forceinline__ void cp_wait() {
    asm volatile("cp.async.wait_group %0;" :: "n"(N) : "memory");
}
__device__ __forceinline__ uint32_t lds32(uint32_t a) {
    uint32_t v;
    asm volatile("ld.shared.b32 %0,[%1];" : "=r"(v) : "r"(a));
    return v;
}
__device__ __forceinline__ void mma16816(float* c, const uint32_t* a,
                                         const uint32_t* b) {
    asm volatile(
        "mma.sync.aligned.m16n8k16.row.col.f32.f16.f16.f32 "
        "{%0,%1,%2,%3}, {%4,%5,%6,%7}, {%8,%9}, {%0,%1,%2,%3};"
        : "+f"(c[0]), "+f"(c[1]), "+f"(c[2]), "+f"(c[3])
        : "r"(a[0]), "r"(a[1]), "r"(a[2]), "r"(a[3]), "r"(b[0]), "r"(b[1]));
}
__device__ __forceinline__ uint32_t hfp(float a, float b) {
    __half2 t;
    t.x = __float2half_rn(a);
    t.y = __float2half_rn(b);
    return *reinterpret_cast<uint32_t*>(&t);
}

// ---------------------------------------------------------------------------
// Prep kernels
// ---------------------------------------------------------------------------
__global__ void k_prep1() {
    int i = blockIdx.x * blockDim.x + threadIdx.x;
    if (i < NNODES) g_ideg[i] = 0;
    if (i == 0) g_flag32 = 0u;
}

__global__ void k_detect(const unsigned* __restrict__ w) {
    unsigned v = 0;
    for (int i = blockIdx.x * blockDim.x + threadIdx.x; i < NEDGES;
         i += gridDim.x * blockDim.x)
        v |= w[2 * i + 1];
    #pragma unroll
    for (int o = 16; o; o >>= 1) v |= __shfl_xor_sync(0xFFFFFFFFu, v, o);
    if ((threadIdx.x & 31) == 0 && v) atomicOr(&g_flag32, 1u);
}

__global__ void k_convert(const void* __restrict__ ei) {
    int e = blockIdx.x * blockDim.x + threadIdx.x;
    if (e >= NEDGES) return;
    int r, c;
    if (g_flag32 == 0u) {
        const long long* ll = (const long long*)ei;
        r = (int)ll[e];
        c = (int)ll[NEDGES + e];
    } else {
        const int* q = (const int*)ei;
        r = q[e];
        c = q[NEDGES + e];
    }
    g_row[e] = r;
    g_col[e] = c;
    atomicAdd(&g_ideg[c], 1);
}

// scanA also computes dinv
__global__ __launch_bounds__(1024) void k_scanA() {
    __shared__ int sh[32];
    int b = blockIdx.x, t = threadIdx.x;
    int base = b * 4096 + t * 4;
    int s = 0;
    #pragma unroll
    for (int j = 0; j < 4; j++) {
        int i = base + j;
        if (i < NNODES) {
            int dv = g_ideg[i];
            s += dv;
            g_dinv[i] = rsqrtf((float)dv + 1.0f);
        }
    }
    #pragma unroll
    for (int o = 16; o; o >>= 1) s += __shfl_xor_sync(0xFFFFFFFFu, s, o);
    if ((t & 31) == 0) sh[t >> 5] = s;
    __syncthreads();
    if (t < 32) {
        int x = sh[t];
        #pragma unroll
        for (int o = 16; o; o >>= 1) x += __shfl_xor_sync(0xFFFFFFFFu, x, o);
        if (t == 0) g_bsum[b] = x;
    }
}

__global__ void k_scanB() {
    int t = threadIdx.x;
    int v = (t < NBLK) ? g_bsum[t] : 0;
    int own = v;
    #pragma unroll
    for (int o = 1; o < 32; o <<= 1) {
        int u = __shfl_up_sync(0xFFFFFFFFu, v, o);
        if (t >= o) v += u;
    }
    if (t < NBLK) g_bpre[t] = v - own;
}

__global__ __launch_bounds__(1024) void k_scanC() {
    __shared__ int sh[1024];
    int b = blockIdx.x, t = threadIdx.x;
    int base = b * 4096 + t * 4;
    int v[4];
    int s = 0;
    #pragma unroll
    for (int j = 0; j < 4; j++) {
        int i = base + j;
        v[j] = (i < NNODES) ? g_ideg[i] : 0;
        s += v[j];
    }
    sh[t] = s;
    __syncthreads();
    #pragma unroll
    for (int o = 1; o < 1024; o <<= 1) {
        int tmp = (t >= o) ? sh[t - o] : 0;
        __syncthreads();
        sh[t] += tmp;
        __syncthreads();
    }
    int excl = sh[t] - s + g_bpre[b];
    #pragma unroll
    for (int j = 0; j < 4; j++) {
        int i = base + j;
        if (i < NNODES) { g_off[i] = excl; g_cursor[i] = excl; }
        excl += v[j];
    }
    if (b == 0 && t == 0) g_off[NNODES] = NEDGES;
}

__global__ void k_fill() {
    int e = blockIdx.x * blockDim.x + threadIdx.x;
    if (e >= NEDGES) return;
    int r = g_row[e], c = g_col[e];
    float cf = g_dinv[r] * g_dinv[c];
    int pos = atomicAdd(&g_cursor[c], 1);
    g_ecsr[pos] = make_int2(r, __float_as_int(cf));
}

// All 9 weight transposes + fp16 splits in one launch.
struct WSet { const float* w[9]; int K[9]; int M[9]; };
__global__ void k_wsplit_all(WSet ws, __half* __restrict__ hiB,
                             __half* __restrict__ loB) {
    int slab = blockIdx.y;
    int idx = blockIdx.x * blockDim.x + threadIdx.x;
    if (idx >= 192 * 192) return;
    int n = idx / 192, k = idx % 192;
    int K = ws.K[slab], M = ws.M[slab];
    float v = (k < K && n < M) ? ws.w[slab][(size_t)k * M + n] : 0.0f;
    __half h = __float2half_rn(v);
    size_t o = (size_t)slab * 192 * 192 + idx;
    hiB[o] = h;
    loB[o] = __float2half_rn(v - __half2float(h));
}

// Pad x [N,96] fp32 -> [N,128] fp16
__global__ void k_padx(const float* __restrict__ x, __half* __restrict__ o) {
    int i = blockIdx.x * blockDim.x + threadIdx.x;
    if (i >= NNODES * 128) return;
    int n = i >> 7, c = i & 127;
    o[i] = (c < 96) ? __float2half_rn(x[n * 96 + c]) : __half(0.0f);
}

// ---------------------------------------------------------------------------
// Gather (fp16 in, fp32 accum) + fp16 hi/lo split out. One warp per node.
// Input rows: KPAD halves (zero-padded). Output: hi/lo as half2 words.
// ---------------------------------------------------------------------------
template <int KPAD>
__global__ __launch_bounds__(256) void k_gather(const __half2* __restrict__ in2,
                                                uint32_t* __restrict__ hi,
                                                uint32_t* __restrict__ lo) {
    constexpr int NV2 = KPAD / 2;          // half2 per row (64 or 96)
    constexpr int NIT = (NV2 + 31) / 32;   // 2 or 3
    int node = blockIdx.x * 8 + (threadIdx.x >> 5);
    if (node >= NNODES) return;
    int lane = threadIdx.x & 31;

    float d = g_dinv[node];
    float dd = d * d;

    float2 acc[NIT];
    #pragma unroll
    for (int v = 0; v < NIT; v++) {
        int id = lane + 32 * v;
        if (id < NV2) {
            float2 t = __half22float2(in2[(size_t)node * NV2 + id]);
            acc[v] = make_float2(t.x * dd, t.y * dd);
        } else acc[v] = make_float2(0.f, 0.f);
    }

    int s = g_off[node];
    int e = g_off[node + 1];
    int i = s;
    for (; i + 3 < e; i += 4) {
        int2 p0 = g_ecsr[i];
        int2 p1 = g_ecsr[i + 1];
        int2 p2 = g_ecsr[i + 2];
        int2 p3 = g_ecsr[i + 3];
        float c0 = __int_as_float(p0.y), c1 = __int_as_float(p1.y);
        float c2 = __int_as_float(p2.y), c3 = __int_as_float(p3.y);
        #pragma unroll
        for (int v = 0; v < NIT; v++) {
            int id = lane + 32 * v;
            if (id < NV2) {
                float2 a0 = __half22float2(in2[(size_t)p0.x * NV2 + id]);
                float2 a1 = __half22float2(in2[(size_t)p1.x * NV2 + id]);
                float2 a2 = __half22float2(in2[(size_t)p2.x * NV2 + id]);
                float2 a3 = __half22float2(in2[(size_t)p3.x * NV2 + id]);
                acc[v].x += a0.x * c0; acc[v].y += a0.y * c0;
                acc[v].x += a1.x * c1; acc[v].y += a1.y * c1;
                acc[v].x += a2.x * c2; acc[v].y += a2.y * c2;
                acc[v].x += a3.x * c3; acc[v].y += a3.y * c3;
            }
        }
    }
    for (; i < e; i++) {
        int2 p = g_ecsr[i];
        float c0 = __int_as_float(p.y);
        #pragma unroll
        for (int v = 0; v < NIT; v++) {
            int id = lane + 32 * v;
            if (id < NV2) {
                float2 a = __half22float2(in2[(size_t)p.x * NV2 + id]);
                acc[v].x += a.x * c0; acc[v].y += a.y * c0;
            }
        }
    }
    #pragma unroll
    for (int v = 0; v < NIT; v++) {
        int id = lane + 32 * v;
        if (id < NV2) {
            float2 a = acc[v];
            __half hx = __float2half_rn(a.x);
            __half hy = __float2half_rn(a.y);
            float lx = a.x - __half2float(hx);
            float ly = a.y - __half2float(hy);
            __half2 ph; ph.x = hx; ph.y = hy;
            hi[(size_t)node * NV2 + id] = *reinterpret_cast<uint32_t*>(&ph);
            lo[(size_t)node * NV2 + id] = hfp(lx, ly);
        }
    }
}

// ---------------------------------------------------------------------------
// mma.sync GEMM: block 256 thr, tile 128x64, warp 32x32, BK=32 double-buffer.
// half_out: write packed half2 (zero-padded to ldc); else fp32.
// ---------------------------------------------------------------------------
#define RS 80
#define ASZ (128 * RS)
#define BSZ (64 * RS)

__global__ __launch_bounds__(256, 3) void k_mgemm(
    const __half* __restrict__ Ahi, const __half* __restrict__ Alo, int kpad,
    const __half* __restrict__ Wh, const __half* __restrict__ Wl,
    const float* __restrict__ bias, void* __restrict__ out, int ldc,
    int M, int nk, int mode, int half_out, int rows)
{
    extern __shared__ char sm[];
    uint32_t base = s2u(sm);
    const int STRIDE = 2 * ASZ + 2 * BSZ;
    int tid = threadIdx.x;
    int wid = tid >> 5, lane = tid & 31;
    int g = lane >> 2, t = lane & 3;
    int wm = wid & 3, wn = wid >> 2;
    int r0 = blockIdx.y * 128;
    int c0 = blockIdx.x * 64;

    auto loadT = [&](int b, int k0) {
        uint32_t ba = base + b * STRIDE;
        #pragma unroll
        for (int i = 0; i < 2; i++) {
            int it = tid + i * 256;
            int m = it >> 2, c = it & 3;
            int gr = r0 + m;
            bool ok = (gr < rows);
            size_t so = (size_t)(ok ? gr : 0) * kpad + k0 + c * 8;
            uint32_t dd = ba + m * RS + c * 16;
            cpa16(dd, Ahi + so, ok);
            cpa16(dd + ASZ, Alo + so, ok);
        }
        {
            int n = tid >> 2, c = tid & 3;
            size_t so = (size_t)(c0 + n) * 192 + k0 + c * 8;
            uint32_t dd = ba + 2 * ASZ + n * RS + c * 16;
            cpa16(dd, Wh + so, true);
            cpa16(dd + BSZ, Wl + so, true);
        }
        CP_COMMIT();
    };

    loadT(0, 0);

    float acc[2][4][4];
    #pragma unroll
    for (int i = 0; i < 2; i++)
        #pragma unroll
        for (int j = 0; j < 4; j++)
            #pragma unroll
            for (int q = 0; q < 4; q++) acc[i][j][q] = 0.0f;

    for (int it = 0; it < nk; it++) {
        int b = it & 1;
        if (it + 1 < nk) { loadT(b ^ 1, (it + 1) * 32); cp_wait<1>(); }
        else cp_wait<0>();
        __syncthreads();
        uint32_t ba = base + b * STRIDE;
        uint32_t aB = ba + (wm * 32 + g) * RS + t * 4;
        uint32_t bB = ba + 2 * ASZ + (wn * 32 + g) * RS + t * 4;
        #pragma unroll
        for (int kc = 0; kc < 2; kc++) {
            uint32_t ah[2][4], al[2][4];
            #pragma unroll
            for (int ms = 0; ms < 2; ms++) {
                uint32_t a0 = aB + ms * (16 * RS) + kc * 32;
                ah[ms][0] = lds32(a0);
                ah[ms][1] = lds32(a0 + 8 * RS);
                ah[ms][2] = lds32(a0 + 16);
                ah[ms][3] = lds32(a0 + 8 * RS + 16);
                al[ms][0] = lds32(a0 + ASZ);
                al[ms][1] = lds32(a0 + ASZ + 8 * RS);
                al[ms][2] = lds32(a0 + ASZ + 16);
                al[ms][3] = lds32(a0 + ASZ + 8 * RS + 16);
            }
            #pragma unroll
            for (int ns = 0; ns < 4; ns++) {
                uint32_t b0 = bB + ns * (8 * RS) + kc * 32;
                uint32_t bh[2], bl[2];
                bh[0] = lds32(b0);
                bh[1] = lds32(b0 + 16);
                bl[0] = lds32(b0 + BSZ);
                bl[1] = lds32(b0 + BSZ + 16);
                #pragma unroll
                for (int ms = 0; ms < 2; ms++) {
                    mma16816(acc[ms][ns], ah[ms], bh);
                    mma16816(acc[ms][ns], ah[ms], bl);
                    mma16816(acc[ms][ns], al[ms], bh);
                }
            }
        }
        __syncthreads();
    }

    #pragma unroll
    for (int ms = 0; ms < 2; ms++) {
        #pragma unroll
        for (int h = 0; h < 2; h++) {
            int r = r0 + wm * 32 + ms * 16 + h * 8 + g;
            if (r >= rows) continue;
            #pragma unroll
            for (int ns = 0; ns < 4; ns++) {
                int cc = c0 + wn * 32 + ns * 8 + 2 * t;
                if (cc >= ldc) continue;
                float v0 = acc[ms][ns][h * 2 + 0];
                float v1 = acc[ms][ns][h * 2 + 1];
                if (cc < M) {
                    v0 += bias[cc];
                    if (mode == 1) v0 = fmaxf(v0, 0.0f);
                    else if (mode == 2) v0 = 1.0f / (1.0f + expf(-v0));
                } else v0 = 0.0f;
                if (cc + 1 < M) {
                    v1 += bias[cc + 1];
                    if (mode == 1) v1 = fmaxf(v1, 0.0f);
                    else if (mode == 2) v1 = 1.0f / (1.0f + expf(-v1));
                } else v1 = 0.0f;
                if (half_out) {
                    *(uint32_t*)((__half*)out + (size_t)r * ldc + cc) = hfp(v0, v1);
                } else {
                    float2 st; st.x = v0; st.y = v1;
                    *(float2*)((float*)out + (size_t)r * ldc + cc) = st;
                }
            }
        }
    }
}

// ---------------------------------------------------------------------------
// Dual mma.sync GEMM: out = mu + eps*exp(ls)/10 (fp16 out always)
// ---------------------------------------------------------------------------
__global__ __launch_bounds__(256, 2) void k_mgemm_dual(
    const __half* __restrict__ Ahi, const __half* __restrict__ Alo, int kpad,
    const __half* __restrict__ W1h, const __half* __restrict__ W1l,
    const __half* __restrict__ W2h, const __half* __restrict__ W2l,
    const float* __restrict__ b1, const float* __restrict__ b2,
    const float* __restrict__ eps, int lde,
    __half* __restrict__ out, int ldc, int M, int nk, int rows)
{
    extern __shared__ char sm[];
    uint32_t base = s2u(sm);
    const int STRIDE = 2 * ASZ + 4 * BSZ;
    int tid = threadIdx.x;
    int wid = tid >> 5, lane = tid & 31;
    int g = lane >> 2, t = lane & 3;
    int wm = wid & 3, wn = wid >> 2;
    int r0 = blockIdx.y * 128;
    int c0 = blockIdx.x * 64;

    auto loadT = [&](int b, int k0) {
        uint32_t ba = base + b * STRIDE;
        #pragma unroll
        for (int i = 0; i < 2; i++) {
            int it = tid + i * 256;
            int m = it >> 2, c = it & 3;
            int gr = r0 + m;
            bool ok = (gr < rows);
            size_t so = (size_t)(ok ? gr : 0) * kpad + k0 + c * 8;
            uint32_t dd = ba + m * RS + c * 16;
            cpa16(dd, Ahi + so, ok);
            cpa16(dd + ASZ, Alo + so, ok);
        }
        {
            int n = tid >> 2, c = tid & 3;
            size_t so = (size_t)(c0 + n) * 192 + k0 + c * 8;
            uint32_t dd = ba + 2 * ASZ + n * RS + c * 16;
            cpa16(dd, W1h + so, true);
            cpa16(dd + BSZ, W1l + so, true);
            cpa16(dd + 2 * BSZ, W2h + so, true);
            cpa16(dd + 3 * BSZ, W2l + so, true);
        }
        CP_COMMIT();
    };

    loadT(0, 0);

    float ac1[2][4][4], ac2[2][4][4];
    #pragma unroll
    for (int i = 0; i < 2; i++)
        #pragma unroll
        for (int j = 0; j < 4; j++)
            #pragma unroll
            for (int q = 0; q < 4; q++) { ac1[i][j][q] = 0.0f; ac2[i][j][q] = 0.0f; }

    for (int it = 0; it < nk; it++) {
        int b = it & 1;
        if (it + 1 < nk) { loadT(b ^ 1, (it + 1) * 32); cp_wait<1>(); }
        else cp_wait<0>();
        __syncthreads();
        uint32_t ba = base + b * STRIDE;
        uint32_t aB = ba + (wm * 32 + g) * RS + t * 4;
        uint32_t bB = ba + 2 * ASZ + (wn * 32 + g) * RS + t * 4;
        #pragma unroll
        for (int kc = 0; kc < 2; kc++) {
            uint32_t ah[2][4], al[2][4];
            #pragma unroll
            for (int ms = 0; ms < 2; ms++) {
                uint32_t a0 = aB + ms * (16 * RS) + kc * 32;
                ah[ms][0] = lds32(a0);
                ah[ms][1] = lds32(a0 + 8 * RS);
                ah[ms][2] = lds32(a0 + 16);
                ah[ms][3] = lds32(a0 + 8 * RS + 16);
                al[ms][0] = lds32(a0 + ASZ);
                al[ms][1] = lds32(a0 + ASZ + 8 * RS);
                al[ms][2] = lds32(a0 + ASZ + 16);
                al[ms][3] = lds32(a0 + ASZ + 8 * RS + 16);
            }
            #pragma unroll
            for (int ns = 0; ns < 4; ns++) {
                uint32_t b0 = bB + ns * (8 * RS) + kc * 32;
                uint32_t b1h[2], b1l[2], b2h[2], b2l[2];
                b1h[0] = lds32(b0);            b1h[1] = lds32(b0 + 16);
                b1l[0] = lds32(b0 + BSZ);      b1l[1] = lds32(b0 + BSZ + 16);
                b2h[0] = lds32(b0 + 2 * BSZ);  b2h[1] = lds32(b0 + 2 * BSZ + 16);
                b2l[0] = lds32(b0 + 3 * BSZ);  b2l[1] = lds32(b0 + 3 * BSZ + 16);
                #pragma unroll
                for (int ms = 0; ms < 2; ms++) {
                    mma16816(ac1[ms][ns], ah[ms], b1h);
                    mma16816(ac1[ms][ns], ah[ms], b1l);
                    mma16816(ac1[ms][ns], al[ms], b1h);
                    mma16816(ac2[ms][ns], ah[ms], b2h);
                    mma16816(ac2[ms][ns], ah[ms], b2l);
                    mma16816(ac2[ms][ns], al[ms], b2h);
                }
            }
        }
        __syncthreads();
    }

    #pragma unroll
    for (int ms = 0; ms < 2; ms++) {
        #pragma unroll
        for (int h = 0; h < 2; h++) {
            int r = r0 + wm * 32 + ms * 16 + h * 8 + g;
            if (r >= rows) continue;
            #pragma unroll
            for (int ns = 0; ns < 4; ns++) {
                int cc = c0 + wn * 32 + ns * 8 + 2 * t;
                if (cc >= ldc) continue;
                float v0 = 0.0f, v1 = 0.0f;
                if (cc < M) {
                    float mu = ac1[ms][ns][h * 2 + 0] + b1[cc];
                    float ls = ac2[ms][ns][h * 2 + 0] + b2[cc];
                    v0 = mu + eps[(size_t)r * lde + cc] * expf(ls) * 0.1f;
                }
                if (cc + 1 < M) {
                    float mu = ac1[ms][ns][h * 2 + 1] + b1[cc + 1];
                    float ls = ac2[ms][ns][h * 2 + 1] + b2[cc + 1];
                    v1 = mu + eps[(size_t)r * lde + cc + 1] * expf(ls) * 0.1f;
                }
                *(uint32_t*)(out + (size_t)r * ldc + cc) = hfp(v0, v1);
            }
        }
    }
}

// ---------------------------------------------------------------------------
// Host side
// ---------------------------------------------------------------------------
static __half *hAhi, *hAlo, *hBhi, *hBlo, *hWhi, *hWlo;
static __half *hactA, *hactB, *hactC;

static void prop(const __half* in, int KPAD, __half* hi, __half* lo,
                 cudaStream_t st) {
    int blocks = (NNODES + 7) / 8;
    uint32_t* h2 = (uint32_t*)hi;
    uint32_t* l2 = (uint32_t*)lo;
    if (KPAD == 128)
        k_gather<128><<<blocks, 256, 0, st>>>((const __half2*)in, h2, l2);
    else
        k_gather<192><<<blocks, 256, 0, st>>>((const __half2*)in, h2, l2);
}

static void mm(const __half* ah, const __half* al, int kpad, int widx, int K,
               const float* bias, void* out, int ldc, int M, int mode,
               int half_out, cudaStream_t st) {
    int nk = (K + 31) / 32;
    dim3 grid((ldc + 63) / 64, (NNODES + 127) / 128);
    size_t smem = 2 * (2 * ASZ + 2 * BSZ);
    k_mgemm<<<grid, 256, smem, st>>>(ah, al, kpad,
                                     hWhi + (size_t)widx * 192 * 192,
                                     hWlo + (size_t)widx * 192 * 192,
                                     bias, out, ldc, M, nk, mode, half_out,
                                     NNODES);
}

static void mmdual(const __half* ah, const __half* al, int kpad, int w1,
                   int w2, int K, const float* b1, const float* b2,
                   const float* eps, int lde, __half* out, int ldc, int M,
                   cudaStream_t st) {
    int nk = (K + 31) / 32;
    dim3 grid((ldc + 63) / 64, (NNODES + 127) / 128);
    size_t smem = 2 * (2 * ASZ + 4 * BSZ);
    k_mgemm_dual<<<grid, 256, smem, st>>>(ah, al, kpad,
                                          hWhi + (size_t)w1 * 192 * 192,
                                          hWlo + (size_t)w1 * 192 * 192,
                                          hWhi + (size_t)w2 * 192 * 192,
                                          hWlo + (size_t)w2 * 192 * 192,
                                          b1, b2, eps, lde, out, ldc, M, nk,
                                          NNODES);
}

extern "C" void kernel_launch(void* const* d_in, const int* in_sizes, int n_in,
                              void* d_out, int out_size) {
    const float* x     = (const float*)d_in[0];
    const void*  ei    = d_in[1];
    const float* eps_e = (const float*)d_in[2];
    const float* eps_n = (const float*)d_in[3];
    const float* w1e = (const float*)d_in[4];  const float* b1e = (const float*)d_in[5];
    const float* w2e = (const float*)d_in[6];  const float* b2e = (const float*)d_in[7];
    const float* wme = (const float*)d_in[8];  const float* bme = (const float*)d_in[9];
    const float* wle = (const float*)d_in[10]; const float* ble = (const float*)d_in[11];
    const float* w4e = (const float*)d_in[12]; const float* b4e = (const float*)d_in[13];
    const float* w1n = (const float*)d_in[14]; const float* b1n = (const float*)d_in[15];
    const float* wmn = (const float*)d_in[16]; const float* bmn = (const float*)d_in[17];
    const float* wln = (const float*)d_in[18]; const float* bln = (const float*)d_in[19];
    const float* w5n = (const float*)d_in[20]; const float* b5n = (const float*)d_in[21];

    float* out   = (float*)d_out;
    float* edges = out;                         // [N,192]
    float* nodes = out + (size_t)NNODES * 192;  // [N,96]

    cudaGetSymbolAddress((void**)&hAhi, g_Ahi);
    cudaGetSymbolAddress((void**)&hAlo, g_Alo);
    cudaGetSymbolAddress((void**)&hBhi, g_Bhi);
    cudaGetSymbolAddress((void**)&hBlo, g_Blo);
    cudaGetSymbolAddress((void**)&hWhi, g_Whi);
    cudaGetSymbolAddress((void**)&hWlo, g_Wlo);
    cudaGetSymbolAddress((void**)&hactA, g_actA);
    cudaGetSymbolAddress((void**)&hactB, g_actB);
    cudaGetSymbolAddress((void**)&hactC, g_actC);

    cudaFuncSetAttribute(k_mgemm, cudaFuncAttributeMaxDynamicSharedMemorySize,
                         (int)(2 * (2 * ASZ + 2 * BSZ)));
    cudaFuncSetAttribute(k_mgemm_dual,
                         cudaFuncAttributeMaxDynamicSharedMemorySize,
                         (int)(2 * (2 * ASZ + 4 * BSZ)));

    cudaStream_t s0 = 0;
    cudaStream_t s1 = cudaStreamPerThread;
    cudaEvent_t evFork0, evPadx, evG1, evN1, evJoin;
    cudaEventCreateWithFlags(&evFork0, cudaEventDisableTiming);
    cudaEventCreateWithFlags(&evPadx, cudaEventDisableTiming);
    cudaEventCreateWithFlags(&evG1, cudaEventDisableTiming);
    cudaEventCreateWithFlags(&evN1, cudaEventDisableTiming);
    cudaEventCreateWithFlags(&evJoin, cudaEventDisableTiming);

    // ---- fork: weight split + x pad on s1, CSR prep on s0 ----
    cudaEventRecord(evFork0, s0);
    cudaStreamWaitEvent(s1, evFork0, 0);
    {
        WSet ws;
        ws.w[0] = w1e; ws.K[0] = 96;  ws.M[0] = 125;
        ws.w[1] = w2e; ws.K[1] = 125; ws.M[1] = 144;
        ws.w[2] = wme; ws.K[2] = 144; ws.M[2] = 163;
        ws.w[3] = wle; ws.K[3] = 144; ws.M[3] = 163;
        ws.w[4] = w4e; ws.K[4] = 163; ws.M[4] = 192;
        ws.w[5] = w1n; ws.K[5] = 96;  ws.M[5] = 96;
        ws.w[6] = wmn; ws.K[6] = 96;  ws.M[6] = 96;
        ws.w[7] = wln; ws.K[7] = 96;  ws.M[7] = 96;
        ws.w[8] = w5n; ws.K[8] = 96;  ws.M[8] = 96;
        dim3 g((192 * 192 + 255) / 256, 9);
        k_wsplit_all<<<g, 256, 0, s1>>>(ws, hWhi, hWlo);
    }
    k_padx<<<(NNODES * 128 + 255) / 256, 256, 0, s1>>>(x, hactB);
    cudaEventRecord(evPadx, s1);

    k_prep1<<<(NNODES + 255) / 256, 256, 0, s0>>>();
    k_detect<<<512, 256, 0, s0>>>((const unsigned*)ei);
    k_convert<<<(NEDGES + 255) / 256, 256, 0, s0>>>(ei);
    k_scanA<<<NBLK, 1024, 0, s0>>>();
    k_scanB<<<1, 32, 0, s0>>>();
    k_scanC<<<NBLK, 1024, 0, s0>>>();
    k_fill<<<(NEDGES + 255) / 256, 256, 0, s0>>>();

    // ---- shared first propagation: g1 = split(Â x) ----
    cudaStreamWaitEvent(s0, evPadx, 0);
    prop(hactB, 128, hAhi, hAlo, s0);
    cudaEventRecord(evG1, s0);

    // ---- node branch on s1 (n1 reads g1's Ahi/Alo) ----
    cudaStreamWaitEvent(s1, evG1, 0);
    mm(hAhi, hAlo, 128, 5, 96, b1n, hactB, 128, 96, 1, 1, s1);  // n1 relu -> fp16
    cudaEventRecord(evN1, s1);
    prop(hactB, 128, hBhi, hBlo, s1);                           // g5
    mmdual(hBhi, hBlo, 128, 6, 7, 96, bmn, bln, eps_n, 96,
           hactC, 128, 96, s1);                                 // nn -> fp16
    prop(hactC, 128, hBhi, hBlo, s1);                           // g6
    mm(hBhi, hBlo, 128, 8, 96, b5n, nodes, 96, 96, 1, 0, s1);   // relu -> fp32 out

    // ---- edge branch on s0 ----
    mm(hAhi, hAlo, 128, 0, 96, b1e, hactA, 128, 125, 1, 1, s0); // e1 relu -> fp16
    cudaStreamWaitEvent(s0, evN1, 0);   // g2 overwrites Ahi/Alo; n1 must be done
    prop(hactA, 128, hAhi, hAlo, s0);                           // g2
    mm(hAhi, hAlo, 128, 1, 125, b2e, hactA, 192, 144, 1, 1, s0);// e2 relu -> fp16 (ldc192)
    prop(hactA, 192, hAhi, hAlo, s0);                           // g3
    mmdual(hAhi, hAlo, 192, 2, 3, 144, bme, ble, eps_e, 163,
           hactA, 192, 163, s0);                                // e reparam -> fp16
    prop(hactA, 192, hAhi, hAlo, s0);                           // g4
    mm(hAhi, hAlo, 192, 4, 163, b4e, edges, 192, 192, 2, 0, s0);// sigmoid -> fp32 out

    // ---- join ----
    cudaEventRecord(evJoin, s1);
    cudaStreamWaitEvent(s0, evJoin, 0);
}

// round 16
// speedup vs baseline: 5.2397x; 1.1454x over previous
#include <cuda_runtime.h>
#include <cuda_fp16.h>
#include <math.h>
#include <cstdint>

#define NNODES 50000
#define NEDGES 800000
#define NBLK 13

// ---------------------------------------------------------------------------
// Scratch
// ---------------------------------------------------------------------------
__device__ __align__(16) __half g_A[(size_t)NNODES * 192];     // edge gather out (fp16)
__device__ __align__(16) __half g_B[(size_t)NNODES * 128];     // node gather out (fp16)
__device__ __align__(16) __half g_Whi[9][192 * 192];
__device__ __align__(16) __half g_Wlo[9][192 * 192];
__device__ __align__(16) __half g_actA[(size_t)NNODES * 192];  // edge activations (fp16)
__device__ __align__(16) __half g_actB[(size_t)NNODES * 128];  // x pad / n1 (fp16)
__device__ __align__(16) __half g_actC[(size_t)NNODES * 128];  // node reparam (fp16)
__device__ float g_dinv[NNODES];
__device__ int   g_row[NEDGES];
__device__ int   g_col[NEDGES];
__device__ int   g_ideg[NNODES];
__device__ int   g_off[NNODES + 1];
__device__ int   g_cursor[NNODES];
__device__ int2  g_ecsr[NEDGES];
__device__ int   g_bsum[32];
__device__ int   g_bpre[32];
__device__ unsigned g_flag32;

// ---------------------------------------------------------------------------
// PTX helpers (sm_103-safe)
// ---------------------------------------------------------------------------
__device__ __forceinline__ unsigned s2u(const void* p) {
    return (unsigned)__cvta_generic_to_shared(p);
}
__device__ __forceinline__ void cpa16(unsigned dst, const void* src, bool p) {
    asm volatile("cp.async.cg.shared.global [%0], [%1], 16, %2;"
                 :: "r"(dst), "l"(src), "r"(p ? 16 : 0));
}
#define CP_COMMIT() asm volatile("cp.async.commit_group;")
template <int N>
__device__ __forceinline__ void cp_wait() {
    asm volatile("cp.async.wait_group %0;" :: "n"(N) : "memory");
}
__device__ __forceinline__ uint32_t lds32(uint32_t a) {
    uint32_t v;
    asm volatile("ld.shared.b32 %0,[%1];" : "=r"(v) : "r"(a));
    return v;
}
__device__ __forceinline__ void mma16816(float* c, const uint32_t* a,
                                         const uint32_t* b) {
    asm volatile(
        "mma.sync.aligned.m16n8k16.row.col.f32.f16.f16.f32 "
        "{%0,%1,%2,%3}, {%4,%5,%6,%7}, {%8,%9}, {%0,%1,%2,%3};"
        : "+f"(c[0]), "+f"(c[1]), "+f"(c[2]), "+f"(c[3])
        : "r"(a[0]), "r"(a[1]), "r"(a[2]), "r"(a[3]), "r"(b[0]), "r"(b[1]));
}
__device__ __forceinline__ uint32_t hfp(float a, float b) {
    __half2 t;
    t.x = __float2half_rn(a);
    t.y = __float2half_rn(b);
    return *reinterpret_cast<uint32_t*>(&t);
}

// ---------------------------------------------------------------------------
// Prep kernels
// ---------------------------------------------------------------------------
__global__ void k_prep1() {
    int i = blockIdx.x * blockDim.x + threadIdx.x;
    if (i < NNODES) g_ideg[i] = 0;
    if (i == 0) g_flag32 = 0u;
}

__global__ void k_detect(const unsigned* __restrict__ w) {
    unsigned v = 0;
    for (int i = blockIdx.x * blockDim.x + threadIdx.x; i < NEDGES;
         i += gridDim.x * blockDim.x)
        v |= w[2 * i + 1];
    #pragma unroll
    for (int o = 16; o; o >>= 1) v |= __shfl_xor_sync(0xFFFFFFFFu, v, o);
    if ((threadIdx.x & 31) == 0 && v) atomicOr(&g_flag32, 1u);
}

__global__ void k_convert(const void* __restrict__ ei) {
    int e = blockIdx.x * blockDim.x + threadIdx.x;
    if (e >= NEDGES) return;
    int r, c;
    if (g_flag32 == 0u) {
        const long long* ll = (const long long*)ei;
        r = (int)ll[e];
        c = (int)ll[NEDGES + e];
    } else {
        const int* q = (const int*)ei;
        r = q[e];
        c = q[NEDGES + e];
    }
    g_row[e] = r;
    g_col[e] = c;
    atomicAdd(&g_ideg[c], 1);
}

__global__ __launch_bounds__(1024) void k_scanA() {
    __shared__ int sh[32];
    int b = blockIdx.x, t = threadIdx.x;
    int base = b * 4096 + t * 4;
    int s = 0;
    #pragma unroll
    for (int j = 0; j < 4; j++) {
        int i = base + j;
        if (i < NNODES) {
            int dv = g_ideg[i];
            s += dv;
            g_dinv[i] = rsqrtf((float)dv + 1.0f);
        }
    }
    #pragma unroll
    for (int o = 16; o; o >>= 1) s += __shfl_xor_sync(0xFFFFFFFFu, s, o);
    if ((t & 31) == 0) sh[t >> 5] = s;
    __syncthreads();
    if (t < 32) {
        int x = sh[t];
        #pragma unroll
        for (int o = 16; o; o >>= 1) x += __shfl_xor_sync(0xFFFFFFFFu, x, o);
        if (t == 0) g_bsum[b] = x;
    }
}

__global__ void k_scanB() {
    int t = threadIdx.x;
    int v = (t < NBLK) ? g_bsum[t] : 0;
    int own = v;
    #pragma unroll
    for (int o = 1; o < 32; o <<= 1) {
        int u = __shfl_up_sync(0xFFFFFFFFu, v, o);
        if (t >= o) v += u;
    }
    if (t < NBLK) g_bpre[t] = v - own;
}

__global__ __launch_bounds__(1024) void k_scanC() {
    __shared__ int sh[1024];
    int b = blockIdx.x, t = threadIdx.x;
    int base = b * 4096 + t * 4;
    int v[4];
    int s = 0;
    #pragma unroll
    for (int j = 0; j < 4; j++) {
        int i = base + j;
        v[j] = (i < NNODES) ? g_ideg[i] : 0;
        s += v[j];
    }
    sh[t] = s;
    __syncthreads();
    #pragma unroll
    for (int o = 1; o < 1024; o <<= 1) {
        int tmp = (t >= o) ? sh[t - o] : 0;
        __syncthreads();
        sh[t] += tmp;
        __syncthreads();
    }
    int excl = sh[t] - s + g_bpre[b];
    #pragma unroll
    for (int j = 0; j < 4; j++) {
        int i = base + j;
        if (i < NNODES) { g_off[i] = excl; g_cursor[i] = excl; }
        excl += v[j];
    }
    if (b == 0 && t == 0) g_off[NNODES] = NEDGES;
}

__global__ void k_fill() {
    int e = blockIdx.x * blockDim.x + threadIdx.x;
    if (e >= NEDGES) return;
    int r = g_row[e], c = g_col[e];
    float cf = g_dinv[r] * g_dinv[c];
    int pos = atomicAdd(&g_cursor[c], 1);
    g_ecsr[pos] = make_int2(r, __float_as_int(cf));
}

// All 9 weight transposes + fp16 splits in one launch.
struct WSet { const float* w[9]; int K[9]; int M[9]; };
__global__ void k_wsplit_all(WSet ws, __half* __restrict__ hiB,
                             __half* __restrict__ loB) {
    int slab = blockIdx.y;
    int idx = blockIdx.x * blockDim.x + threadIdx.x;
    if (idx >= 192 * 192) return;
    int n = idx / 192, k = idx % 192;
    int K = ws.K[slab], M = ws.M[slab];
    float v = (k < K && n < M) ? ws.w[slab][(size_t)k * M + n] : 0.0f;
    __half h = __float2half_rn(v);
    size_t o = (size_t)slab * 192 * 192 + idx;
    hiB[o] = h;
    loB[o] = __float2half_rn(v - __half2float(h));
}

// Pad x [N,96] fp32 -> [N,128] fp16
__global__ void k_padx(const float* __restrict__ x, __half* __restrict__ o) {
    int i = blockIdx.x * blockDim.x + threadIdx.x;
    if (i >= NNODES * 128) return;
    int n = i >> 7, c = i & 127;
    o[i] = (c < 96) ? __float2half_rn(x[n * 96 + c]) : __half(0.0f);
}

// ---------------------------------------------------------------------------
// Gather (fp16 in, fp32 accum, fp16 out). One warp per node.
// ---------------------------------------------------------------------------
template <int KPAD>
__global__ __launch_bounds__(256) void k_gather(const __half2* __restrict__ in2,
                                                uint32_t* __restrict__ outw) {
    constexpr int NV2 = KPAD / 2;          // half2 per row (64 or 96)
    constexpr int NIT = (NV2 + 31) / 32;   // 2 or 3
    int node = blockIdx.x * 8 + (threadIdx.x >> 5);
    if (node >= NNODES) return;
    int lane = threadIdx.x & 31;

    float d = g_dinv[node];
    float dd = d * d;

    float2 acc[NIT];
    #pragma unroll
    for (int v = 0; v < NIT; v++) {
        int id = lane + 32 * v;
        if (id < NV2) {
            float2 t = __half22float2(in2[(size_t)node * NV2 + id]);
            acc[v] = make_float2(t.x * dd, t.y * dd);
        } else acc[v] = make_float2(0.f, 0.f);
    }

    int s = g_off[node];
    int e = g_off[node + 1];
    int i = s;
    for (; i + 3 < e; i += 4) {
        int2 p0 = g_ecsr[i];
        int2 p1 = g_ecsr[i + 1];
        int2 p2 = g_ecsr[i + 2];
        int2 p3 = g_ecsr[i + 3];
        float c0 = __int_as_float(p0.y), c1 = __int_as_float(p1.y);
        float c2 = __int_as_float(p2.y), c3 = __int_as_float(p3.y);
        #pragma unroll
        for (int v = 0; v < NIT; v++) {
            int id = lane + 32 * v;
            if (id < NV2) {
                float2 a0 = __half22float2(in2[(size_t)p0.x * NV2 + id]);
                float2 a1 = __half22float2(in2[(size_t)p1.x * NV2 + id]);
                float2 a2 = __half22float2(in2[(size_t)p2.x * NV2 + id]);
                float2 a3 = __half22float2(in2[(size_t)p3.x * NV2 + id]);
                acc[v].x += a0.x * c0; acc[v].y += a0.y * c0;
                acc[v].x += a1.x * c1; acc[v].y += a1.y * c1;
                acc[v].x += a2.x * c2; acc[v].y += a2.y * c2;
                acc[v].x += a3.x * c3; acc[v].y += a3.y * c3;
            }
        }
    }
    for (; i < e; i++) {
        int2 p = g_ecsr[i];
        float c0 = __int_as_float(p.y);
        #pragma unroll
        for (int v = 0; v < NIT; v++) {
            int id = lane + 32 * v;
            if (id < NV2) {
                float2 a = __half22float2(in2[(size_t)p.x * NV2 + id]);
                acc[v].x += a.x * c0; acc[v].y += a.y * c0;
            }
        }
    }
    #pragma unroll
    for (int v = 0; v < NIT; v++) {
        int id = lane + 32 * v;
        if (id < NV2)
            outw[(size_t)node * NV2 + id] = hfp(acc[v].x, acc[v].y);
    }
}

// ---------------------------------------------------------------------------
// mma.sync GEMM: A plain fp16, W split hi/lo. 2 MMAs per fragment.
// Block 256 thr, tile 128x64, warp 32x32, BK=32 double-buffered.
// ---------------------------------------------------------------------------
#define RS 80
#define ASZ (128 * RS)
#define BSZ (64 * RS)

__global__ __launch_bounds__(256, 3) void k_mgemm(
    const __half* __restrict__ A, int kpad,
    const __half* __restrict__ Wh, const __half* __restrict__ Wl,
    const float* __restrict__ bias, void* __restrict__ out, int ldc,
    int M, int nk, int mode, int half_out, int rows)
{
    extern __shared__ char sm[];
    uint32_t base = s2u(sm);
    const int STRIDE = ASZ + 2 * BSZ;
    int tid = threadIdx.x;
    int wid = tid >> 5, lane = tid & 31;
    int g = lane >> 2, t = lane & 3;
    int wm = wid & 3, wn = wid >> 2;
    int r0 = blockIdx.y * 128;
    int c0 = blockIdx.x * 64;

    auto loadT = [&](int b, int k0) {
        uint32_t ba = base + b * STRIDE;
        #pragma unroll
        for (int i = 0; i < 2; i++) {
            int it = tid + i * 256;
            int m = it >> 2, c = it & 3;
            int gr = r0 + m;
            bool ok = (gr < rows);
            size_t so = (size_t)(ok ? gr : 0) * kpad + k0 + c * 8;
            cpa16(ba + m * RS + c * 16, A + so, ok);
        }
        {
            int n = tid >> 2, c = tid & 3;
            size_t so = (size_t)(c0 + n) * 192 + k0 + c * 8;
            uint32_t dd = ba + ASZ + n * RS + c * 16;
            cpa16(dd, Wh + so, true);
            cpa16(dd + BSZ, Wl + so, true);
        }
        CP_COMMIT();
    };

    loadT(0, 0);

    float acc[2][4][4];
    #pragma unroll
    for (int i = 0; i < 2; i++)
        #pragma unroll
        for (int j = 0; j < 4; j++)
            #pragma unroll
            for (int q = 0; q < 4; q++) acc[i][j][q] = 0.0f;

    for (int it = 0; it < nk; it++) {
        int b = it & 1;
        if (it + 1 < nk) { loadT(b ^ 1, (it + 1) * 32); cp_wait<1>(); }
        else cp_wait<0>();
        __syncthreads();
        uint32_t ba = base + b * STRIDE;
        uint32_t aB = ba + (wm * 32 + g) * RS + t * 4;
        uint32_t bB = ba + ASZ + (wn * 32 + g) * RS + t * 4;
        #pragma unroll
        for (int kc = 0; kc < 2; kc++) {
            uint32_t ah[2][4];
            #pragma unroll
            for (int ms = 0; ms < 2; ms++) {
                uint32_t a0 = aB + ms * (16 * RS) + kc * 32;
                ah[ms][0] = lds32(a0);
                ah[ms][1] = lds32(a0 + 8 * RS);
                ah[ms][2] = lds32(a0 + 16);
                ah[ms][3] = lds32(a0 + 8 * RS + 16);
            }
            #pragma unroll
            for (int ns = 0; ns < 4; ns++) {
                uint32_t b0 = bB + ns * (8 * RS) + kc * 32;
                uint32_t bh[2], bl[2];
                bh[0] = lds32(b0);
                bh[1] = lds32(b0 + 16);
                bl[0] = lds32(b0 + BSZ);
                bl[1] = lds32(b0 + BSZ + 16);
                #pragma unroll
                for (int ms = 0; ms < 2; ms++) {
                    mma16816(acc[ms][ns], ah[ms], bh);
                    mma16816(acc[ms][ns], ah[ms], bl);
                }
            }
        }
        __syncthreads();
    }

    #pragma unroll
    for (int ms = 0; ms < 2; ms++) {
        #pragma unroll
        for (int h = 0; h < 2; h++) {
            int r = r0 + wm * 32 + ms * 16 + h * 8 + g;
            if (r >= rows) continue;
            #pragma unroll
            for (int ns = 0; ns < 4; ns++) {
                int cc = c0 + wn * 32 + ns * 8 + 2 * t;
                if (cc >= ldc) continue;
                float v0 = acc[ms][ns][h * 2 + 0];
                float v1 = acc[ms][ns][h * 2 + 1];
                if (cc < M) {
                    v0 += bias[cc];
                    if (mode == 1) v0 = fmaxf(v0, 0.0f);
                    else if (mode == 2) v0 = 1.0f / (1.0f + expf(-v0));
                } else v0 = 0.0f;
                if (cc + 1 < M) {
                    v1 += bias[cc + 1];
                    if (mode == 1) v1 = fmaxf(v1, 0.0f);
                    else if (mode == 2) v1 = 1.0f / (1.0f + expf(-v1));
                } else v1 = 0.0f;
                if (half_out) {
                    *(uint32_t*)((__half*)out + (size_t)r * ldc + cc) = hfp(v0, v1);
                } else {
                    float2 st; st.x = v0; st.y = v1;
                    *(float2*)((float*)out + (size_t)r * ldc + cc) = st;
                }
            }
        }
    }
}

// ---------------------------------------------------------------------------
// Dual mma.sync GEMM: out = mu + eps*exp(ls)/10 (fp16 out), 4 MMAs/frag.
// ---------------------------------------------------------------------------
__global__ __launch_bounds__(256, 3) void k_mgemm_dual(
    const __half* __restrict__ A, int kpad,
    const __half* __restrict__ W1h, const __half* __restrict__ W1l,
    const __half* __restrict__ W2h, const __half* __restrict__ W2l,
    const float* __restrict__ b1, const float* __restrict__ b2,
    const float* __restrict__ eps, int lde,
    __half* __restrict__ out, int ldc, int M, int nk, int rows)
{
    extern __shared__ char sm[];
    uint32_t base = s2u(sm);
    const int STRIDE = ASZ + 4 * BSZ;
    int tid = threadIdx.x;
    int wid = tid >> 5, lane = tid & 31;
    int g = lane >> 2, t = lane & 3;
    int wm = wid & 3, wn = wid >> 2;
    int r0 = blockIdx.y * 128;
    int c0 = blockIdx.x * 64;

    auto loadT = [&](int b, int k0) {
        uint32_t ba = base + b * STRIDE;
        #pragma unroll
        for (int i = 0; i < 2; i++) {
            int it = tid + i * 256;
            int m = it >> 2, c = it & 3;
            int gr = r0 + m;
            bool ok = (gr < rows);
            size_t so = (size_t)(ok ? gr : 0) * kpad + k0 + c * 8;
            cpa16(ba + m * RS + c * 16, A + so, ok);
        }
        {
            int n = tid >> 2, c = tid & 3;
            size_t so = (size_t)(c0 + n) * 192 + k0 + c * 8;
            uint32_t dd = ba + ASZ + n * RS + c * 16;
            cpa16(dd, W1h + so, true);
            cpa16(dd + BSZ, W1l + so, true);
            cpa16(dd + 2 * BSZ, W2h + so, true);
            cpa16(dd + 3 * BSZ, W2l + so, true);
        }
        CP_COMMIT();
    };

    loadT(0, 0);

    float ac1[2][4][4], ac2[2][4][4];
    #pragma unroll
    for (int i = 0; i < 2; i++)
        #pragma unroll
        for (int j = 0; j < 4; j++)
            #pragma unroll
            for (int q = 0; q < 4; q++) { ac1[i][j][q] = 0.0f; ac2[i][j][q] = 0.0f; }

    for (int it = 0; it < nk; it++) {
        int b = it & 1;
        if (it + 1 < nk) { loadT(b ^ 1, (it + 1) * 32); cp_wait<1>(); }
        else cp_wait<0>();
        __syncthreads();
        uint32_t ba = base + b * STRIDE;
        uint32_t aB = ba + (wm * 32 + g) * RS + t * 4;
        uint32_t bB = ba + ASZ + (wn * 32 + g) * RS + t * 4;
        #pragma unroll
        for (int kc = 0; kc < 2; kc++) {
            uint32_t ah[2][4];
            #pragma unroll
            for (int ms = 0; ms < 2; ms++) {
                uint32_t a0 = aB + ms * (16 * RS) + kc * 32;
                ah[ms][0] = lds32(a0);
                ah[ms][1] = lds32(a0 + 8 * RS);
                ah[ms][2] = lds32(a0 + 16);
                ah[ms][3] = lds32(a0 + 8 * RS + 16);
            }
            #pragma unroll
            for (int ns = 0; ns < 4; ns++) {
                uint32_t b0 = bB + ns * (8 * RS) + kc * 32;
                uint32_t b1h[2], b1l[2], b2h[2], b2l[2];
                b1h[0] = lds32(b0);            b1h[1] = lds32(b0 + 16);
                b1l[0] = lds32(b0 + BSZ);      b1l[1] = lds32(b0 + BSZ + 16);
                b2h[0] = lds32(b0 + 2 * BSZ);  b2h[1] = lds32(b0 + 2 * BSZ + 16);
                b2l[0] = lds32(b0 + 3 * BSZ);  b2l[1] = lds32(b0 + 3 * BSZ + 16);
                #pragma unroll
                for (int ms = 0; ms < 2; ms++) {
                    mma16816(ac1[ms][ns], ah[ms], b1h);
                    mma16816(ac1[ms][ns], ah[ms], b1l);
                    mma16816(ac2[ms][ns], ah[ms], b2h);
                    mma16816(ac2[ms][ns], ah[ms], b2l);
                }
            }
        }
        __syncthreads();
    }

    #pragma unroll
    for (int ms = 0; ms < 2; ms++) {
        #pragma unroll
        for (int h = 0; h < 2; h++) {
            int r = r0 + wm * 32 + ms * 16 + h * 8 + g;
            if (r >= rows) continue;
            #pragma unroll
            for (int ns = 0; ns < 4; ns++) {
                int cc = c0 + wn * 32 + ns * 8 + 2 * t;
                if (cc >= ldc) continue;
                float v0 = 0.0f, v1 = 0.0f;
                if (cc < M) {
                    float mu = ac1[ms][ns][h * 2 + 0] + b1[cc];
                    float ls = ac2[ms][ns][h * 2 + 0] + b2[cc];
                    v0 = mu + eps[(size_t)r * lde + cc] * expf(ls) * 0.1f;
                }
                if (cc + 1 < M) {
                    float mu = ac1[ms][ns][h * 2 + 1] + b1[cc + 1];
                    float ls = ac2[ms][ns][h * 2 + 1] + b2[cc + 1];
                    v1 = mu + eps[(size_t)r * lde + cc + 1] * expf(ls) * 0.1f;
                }
                *(uint32_t*)(out + (size_t)r * ldc + cc) = hfp(v0, v1);
            }
        }
    }
}

// ---------------------------------------------------------------------------
// Host side
// ---------------------------------------------------------------------------
static __half *hA, *hB, *hWhi, *hWlo;
static __half *hactA, *hactB, *hactC;

static void prop(const __half* in, int KPAD, __half* outp, cudaStream_t st) {
    int blocks = (NNODES + 7) / 8;
    uint32_t* o = (uint32_t*)outp;
    if (KPAD == 128)
        k_gather<128><<<blocks, 256, 0, st>>>((const __half2*)in, o);
    else
        k_gather<192><<<blocks, 256, 0, st>>>((const __half2*)in, o);
}

static void mm(const __half* a, int kpad, int widx, int K, const float* bias,
               void* out, int ldc, int M, int mode, int half_out,
               cudaStream_t st) {
    int nk = (K + 31) / 32;
    dim3 grid((ldc + 63) / 64, (NNODES + 127) / 128);
    size_t smem = 2 * (ASZ + 2 * BSZ);
    k_mgemm<<<grid, 256, smem, st>>>(a, kpad,
                                     hWhi + (size_t)widx * 192 * 192,
                                     hWlo + (size_t)widx * 192 * 192,
                                     bias, out, ldc, M, nk, mode, half_out,
                                     NNODES);
}

static void mmdual(const __half* a, int kpad, int w1, int w2, int K,
                   const float* b1, const float* b2, const float* eps, int lde,
                   __half* out, int ldc, int M, cudaStream_t st) {
    int nk = (K + 31) / 32;
    dim3 grid((ldc + 63) / 64, (NNODES + 127) / 128);
    size_t smem = 2 * (ASZ + 4 * BSZ);
    k_mgemm_dual<<<grid, 256, smem, st>>>(a, kpad,
                                          hWhi + (size_t)w1 * 192 * 192,
                                          hWlo + (size_t)w1 * 192 * 192,
                                          hWhi + (size_t)w2 * 192 * 192,
                                          hWlo + (size_t)w2 * 192 * 192,
                                          b1, b2, eps, lde, out, ldc, M, nk,
                                          NNODES);
}

extern "C" void kernel_launch(void* const* d_in, const int* in_sizes, int n_in,
                              void* d_out, int out_size) {
    const float* x     = (const float*)d_in[0];
    const void*  ei    = d_in[1];
    const float* eps_e = (const float*)d_in[2];
    const float* eps_n = (const float*)d_in[3];
    const float* w1e = (const float*)d_in[4];  const float* b1e = (const float*)d_in[5];
    const float* w2e = (const float*)d_in[6];  const float* b2e = (const float*)d_in[7];
    const float* wme = (const float*)d_in[8];  const float* bme = (const float*)d_in[9];
    const float* wle = (const float*)d_in[10]; const float* ble = (const float*)d_in[11];
    const float* w4e = (const float*)d_in[12]; const float* b4e = (const float*)d_in[13];
    const float* w1n = (const float*)d_in[14]; const float* b1n = (const float*)d_in[15];
    const float* wmn = (const float*)d_in[16]; const float* bmn = (const float*)d_in[17];
    const float* wln = (const float*)d_in[18]; const float* bln = (const float*)d_in[19];
    const float* w5n = (const float*)d_in[20]; const float* b5n = (const float*)d_in[21];

    float* out   = (float*)d_out;
    float* edges = out;                         // [N,192]
    float* nodes = out + (size_t)NNODES * 192;  // [N,96]

    cudaGetSymbolAddress((void**)&hA, g_A);
    cudaGetSymbolAddress((void**)&hB, g_B);
    cudaGetSymbolAddress((void**)&hWhi, g_Whi);
    cudaGetSymbolAddress((void**)&hWlo, g_Wlo);
    cudaGetSymbolAddress((void**)&hactA, g_actA);
    cudaGetSymbolAddress((void**)&hactB, g_actB);
    cudaGetSymbolAddress((void**)&hactC, g_actC);

    cudaFuncSetAttribute(k_mgemm, cudaFuncAttributeMaxDynamicSharedMemorySize,
                         (int)(2 * (ASZ + 2 * BSZ)));
    cudaFuncSetAttribute(k_mgemm_dual,
                         cudaFuncAttributeMaxDynamicSharedMemorySize,
                         (int)(2 * (ASZ + 4 * BSZ)));

    cudaStream_t s0 = 0;
    cudaStream_t s1 = cudaStreamPerThread;
    cudaEvent_t evFork0, evPadx, evG1, evN1, evJoin;
    cudaEventCreateWithFlags(&evFork0, cudaEventDisableTiming);
    cudaEventCreateWithFlags(&evPadx, cudaEventDisableTiming);
    cudaEventCreateWithFlags(&evG1, cudaEventDisableTiming);
    cudaEventCreateWithFlags(&evN1, cudaEventDisableTiming);
    cudaEventCreateWithFlags(&evJoin, cudaEventDisableTiming);

    // ---- fork: weight split + x pad on s1, CSR prep on s0 ----
    cudaEventRecord(evFork0, s0);
    cudaStreamWaitEvent(s1, evFork0, 0);
    {
        WSet ws;
        ws.w[0] = w1e; ws.K[0] = 96;  ws.M[0] = 125;
        ws.w[1] = w2e; ws.K[1] = 125; ws.M[1] = 144;
        ws.w[2] = wme; ws.K[2] = 144; ws.M[2] = 163;
        ws.w[3] = wle; ws.K[3] = 144; ws.M[3] = 163;
        ws.w[4] = w4e; ws.K[4] = 163; ws.M[4] = 192;
        ws.w[5] = w1n; ws.K[5] = 96;  ws.M[5] = 96;
        ws.w[6] = wmn; ws.K[6] = 96;  ws.M[6] = 96;
        ws.w[7] = wln; ws.K[7] = 96;  ws.M[7] = 96;
        ws.w[8] = w5n; ws.K[8] = 96;  ws.M[8] = 96;
        dim3 g((192 * 192 + 255) / 256, 9);
        k_wsplit_all<<<g, 256, 0, s1>>>(ws, hWhi, hWlo);
    }
    k_padx<<<(NNODES * 128 + 255) / 256, 256, 0, s1>>>(x, hactB);
    cudaEventRecord(evPadx, s1);

    k_prep1<<<(NNODES + 255) / 256, 256, 0, s0>>>();
    k_detect<<<512, 256, 0, s0>>>((const unsigned*)ei);
    k_convert<<<(NEDGES + 255) / 256, 256, 0, s0>>>(ei);
    k_scanA<<<NBLK, 1024, 0, s0>>>();
    k_scanB<<<1, 32, 0, s0>>>();
    k_scanC<<<NBLK, 1024, 0, s0>>>();
    k_fill<<<(NEDGES + 255) / 256, 256, 0, s0>>>();

    // ---- shared first propagation: g1 = Â x (fp16) ----
    cudaStreamWaitEvent(s0, evPadx, 0);
    prop(hactB, 128, hA, s0);
    cudaEventRecord(evG1, s0);

    // ---- node branch on s1 (n1 reads g1's output hA) ----
    cudaStreamWaitEvent(s1, evG1, 0);
    mm(hA, 128, 5, 96, b1n, hactB, 128, 96, 1, 1, s1);          // n1 relu -> fp16
    cudaEventRecord(evN1, s1);
    prop(hactB, 128, hB, s1);                                   // g5
    mmdual(hB, 128, 6, 7, 96, bmn, bln, eps_n, 96,
           hactC, 128, 96, s1);                                 // nn -> fp16
    prop(hactC, 128, hB, s1);                                   // g6
    mm(hB, 128, 8, 96, b5n, nodes, 96, 96, 1, 0, s1);           // relu -> fp32 out

    // ---- edge branch on s0 ----
    mm(hA, 128, 0, 96, b1e, hactA, 128, 125, 1, 1, s0);         // e1 relu -> fp16
    cudaStreamWaitEvent(s0, evN1, 0);   // g2 overwrites hA; n1 must be done
    prop(hactA, 128, hA, s0);                                   // g2
    mm(hA, 128, 1, 125, b2e, hactA, 192, 144, 1, 1, s0);        // e2 relu -> fp16 (ldc192)
    prop(hactA, 192, hA, s0);                                   // g3
    mmdual(hA, 192, 2, 3, 144, bme, ble, eps_e, 163,
           hactA, 192, 163, s0);                                // e reparam -> fp16
    prop(hactA, 192, hA, s0);                                   // g4
    mm(hA, 192, 4, 163, b4e, edges, 192, 192, 2, 0, s0);        // sigmoid -> fp32 out

    // ---- join ----
    cudaEventRecord(evJoin, s1);
    cudaStreamWaitEvent(s0, evJoin, 0);
}